// round 1
// baseline (speedup 1.0000x reference)
#include <cuda_runtime.h>
#include <math.h>

#define Bb 2
#define Ss 4096
#define Dd 512
#define Hh 8
#define NBb 64

// Scratch (device globals: allocation-free, graph-safe)
__device__ float g_q[Bb*Ss*Dd];
__device__ float g_k[Bb*Ss*Dd];
__device__ float g_v[Bb*Ss*Dd];
__device__ float g_ctx[Bb*Ss*Dd];
__device__ float g_h[Bb*Ss*Dd];

// ---------------------------------------------------------------------------
// SGEMM: Y[8192,512] = alpha * X[8192,512] @ W[512,512]
// 64x64 block tile, BK=16, 256 threads, 4x4 microtile per thread.
// ---------------------------------------------------------------------------
__global__ __launch_bounds__(256) void sgemm64(const float* __restrict__ X,
                                               const float* __restrict__ W,
                                               float* __restrict__ Y, float alpha)
{
    __shared__ float Xs[16][68];   // [k][row], padded
    __shared__ float Ws[16][64];   // [k][col]
    int t  = threadIdx.x;
    int ty = t >> 4, tx = t & 15;
    int rowBase = blockIdx.y * 64;
    int colBase = blockIdx.x * 64;
    int xr = t >> 2, xc = t & 3;   // X loader: 64 rows x 4 float4-chunks
    int wr = t >> 4, wc = t & 15;  // W loader: 16 rows x 16 float4-chunks

    float acc[4][4];
#pragma unroll
    for (int j = 0; j < 4; j++)
#pragma unroll
        for (int i = 0; i < 4; i++) acc[j][i] = 0.f;

    for (int kb = 0; kb < 512; kb += 16) {
        float4 xv = *(const float4*)&X[(size_t)(rowBase + xr) * 512 + kb + xc * 4];
        float4 wv = *(const float4*)&W[(size_t)(kb + wr) * 512 + colBase + wc * 4];
        __syncthreads();
        Xs[xc*4+0][xr] = xv.x; Xs[xc*4+1][xr] = xv.y;
        Xs[xc*4+2][xr] = xv.z; Xs[xc*4+3][xr] = xv.w;
        *(float4*)&Ws[wr][wc*4] = wv;
        __syncthreads();
#pragma unroll
        for (int kk = 0; kk < 16; kk++) {
            float4 a = *(const float4*)&Xs[kk][ty*4];
            float4 b = *(const float4*)&Ws[kk][tx*4];
            acc[0][0] += a.x*b.x; acc[0][1] += a.x*b.y; acc[0][2] += a.x*b.z; acc[0][3] += a.x*b.w;
            acc[1][0] += a.y*b.x; acc[1][1] += a.y*b.y; acc[1][2] += a.y*b.z; acc[1][3] += a.y*b.w;
            acc[2][0] += a.z*b.x; acc[2][1] += a.z*b.y; acc[2][2] += a.z*b.z; acc[2][3] += a.z*b.w;
            acc[3][0] += a.w*b.x; acc[3][1] += a.w*b.y; acc[3][2] += a.w*b.z; acc[3][3] += a.w*b.w;
        }
    }
#pragma unroll
    for (int j = 0; j < 4; j++) {
        float4 o = make_float4(acc[j][0]*alpha, acc[j][1]*alpha,
                               acc[j][2]*alpha, acc[j][3]*alpha);
        *(float4*)&Y[(size_t)(rowBase + ty*4 + j) * 512 + colBase + tx*4] = o;
    }
}

// ---------------------------------------------------------------------------
// Attention: one CTA per (b, h, q-block). Dense q-blocks {0,1,62,63} sweep
// all 64 key blocks; mid blocks visit band(q-1,q,q+1) + global(0,63) + 3 rand.
// Online softmax; 64x64 tiles; K and V share one swizzled smem buffer.
// ---------------------------------------------------------------------------
__device__ __forceinline__ float redmax16(float v) {
#pragma unroll
    for (int m = 8; m >= 1; m >>= 1) v = fmaxf(v, __shfl_xor_sync(0xffffffffu, v, m));
    return v;
}
__device__ __forceinline__ float redsum16(float v) {
#pragma unroll
    for (int m = 8; m >= 1; m >>= 1) v += __shfl_xor_sync(0xffffffffu, v, m);
    return v;
}

__global__ __launch_bounds__(256) void attn_kernel(const float* __restrict__ mask,
                                                   const int* __restrict__ rand_blocks)
{
    __shared__ float qs[64*64];   // q tile, natural [row][d]
    __shared__ float kv[64*64];   // K then V, d-index swizzled by row
    __shared__ float ps[64*64];   // softmax p tile [row][k]

    int t  = threadIdx.x;
    int ty = t >> 4, tx = t & 15;
    int blk = blockIdx.x;
    int qb = blk & 63;
    int h  = (blk >> 6) & 7;
    int b  = blk >> 9;
    size_t headOff = (size_t)h * 64;
    size_t baseRow = (size_t)b * Ss;

    // Load scaled-Q tile (rows qb*64.., head columns)
#pragma unroll
    for (int it = 0; it < 4; it++) {
        int idx = t + it * 256;
        int row = idx >> 4, ch = idx & 15;
        float4 v4 = *(const float4*)&g_q[(baseRow + qb*64 + row) * Dd + headOff + ch*4];
        *(float4*)&qs[row*64 + ch*4] = v4;
    }
    float mqr[4];
#pragma unroll
    for (int j = 0; j < 4; j++) mqr[j] = mask[baseRow + qb*64 + ty*4 + j];

    float acc[4][4], mo[4], ls[4];
#pragma unroll
    for (int j = 0; j < 4; j++) {
        mo[j] = -INFINITY; ls[j] = 0.f;
#pragma unroll
        for (int i = 0; i < 4; i++) acc[j][i] = 0.f;
    }

    bool dense = (qb < 2) || (qb >= 62);
    int nkb = dense ? 64 : 8;

    for (int itk = 0; itk < nkb; itk++) {
        int kb; bool band = false;
        if (dense) kb = itk;
        else if (itk < 3)       { kb = qb - 1 + itk; band = true; }
        else if (itk == 3)        kb = 0;
        else if (itk == 4)        kb = 63;
        else                      kb = rand_blocks[(qb - 2) * 3 + (itk - 5)];

        __syncthreads();                       // prior iter's ps/kv reads done
        // Load K tile swizzled: elem (kc,d) -> kv[kc*64 + (d ^ (((kc>>2)&15)<<2))]
#pragma unroll
        for (int it = 0; it < 4; it++) {
            int idx = t + it * 256;
            int kc = idx >> 4, d = (idx & 15) * 4;
            float4 v4 = *(const float4*)&g_k[(baseRow + kb*64 + kc) * Dd + headOff + d];
            int dsw = d ^ (((kc >> 2) & 15) << 2);
            *(float4*)&kv[kc*64 + dsw] = v4;
        }
        __syncthreads();

        // QK^T scores: 4x4 microtile
        float sc[4][4];
#pragma unroll
        for (int j = 0; j < 4; j++)
#pragma unroll
            for (int i = 0; i < 4; i++) sc[j][i] = 0.f;
        int swz = tx << 2;                      // (kc>>2)==tx for kc=tx*4+i
#pragma unroll
        for (int d0 = 0; d0 < 64; d0 += 4) {
            float4 a[4], bb[4];
#pragma unroll
            for (int j = 0; j < 4; j++) a[j]  = *(const float4*)&qs[(ty*4+j)*64 + d0];
            int dsw = d0 ^ swz;
#pragma unroll
            for (int i = 0; i < 4; i++) bb[i] = *(const float4*)&kv[(tx*4+i)*64 + dsw];
#pragma unroll
            for (int j = 0; j < 4; j++)
#pragma unroll
                for (int i = 0; i < 4; i++)
                    sc[j][i] += a[j].x*bb[i].x + a[j].y*bb[i].y
                              + a[j].z*bb[i].z + a[j].w*bb[i].w;
        }

        // Mask: band uses mask_q*mask_k, others key-mask only (matches reference)
#pragma unroll
        for (int i = 0; i < 4; i++) {
            float mkv = mask[baseRow + kb*64 + tx*4 + i];
#pragma unroll
            for (int j = 0; j < 4; j++) {
                float mm = band ? mkv * mqr[j] : mkv;
                sc[j][i] += (1.0f - mm) * (-1000000000.0f);
            }
        }

        // Online softmax update
#pragma unroll
        for (int j = 0; j < 4; j++) {
            float m = fmaxf(fmaxf(sc[j][0], sc[j][1]), fmaxf(sc[j][2], sc[j][3]));
            m = redmax16(m);
            float mn = fmaxf(mo[j], m);
            float corr = __expf(mo[j] - mn);
            float rs = 0.f;
#pragma unroll
            for (int i = 0; i < 4; i++) { float p = __expf(sc[j][i] - mn); sc[j][i] = p; rs += p; }
            rs = redsum16(rs);
            ls[j] = ls[j] * corr + rs;
#pragma unroll
            for (int i = 0; i < 4; i++) acc[j][i] *= corr;
            mo[j] = mn;
        }

        __syncthreads();                       // all QK reads of kv done
        // Load V into kv (same swizzle); write p tile
#pragma unroll
        for (int it = 0; it < 4; it++) {
            int idx = t + it * 256;
            int kc = idx >> 4, d = (idx & 15) * 4;
            float4 v4 = *(const float4*)&g_v[(baseRow + kb*64 + kc) * Dd + headOff + d];
            int dsw = d ^ (((kc >> 2) & 15) << 2);
            *(float4*)&kv[kc*64 + dsw] = v4;
        }
#pragma unroll
        for (int j = 0; j < 4; j++)
            *(float4*)&ps[(ty*4+j)*64 + tx*4] =
                make_float4(sc[j][0], sc[j][1], sc[j][2], sc[j][3]);
        __syncthreads();

        // PV accumulate
#pragma unroll
        for (int k0 = 0; k0 < 64; k0 += 4) {
            float4 pj[4];
#pragma unroll
            for (int j = 0; j < 4; j++) pj[j] = *(const float4*)&ps[(ty*4+j)*64 + k0];
            int vswz = ((k0 >> 2) & 15) << 2;
#pragma unroll
            for (int kk = 0; kk < 4; kk++) {
                float4 vv = *(const float4*)&kv[(k0+kk)*64 + ((tx*4) ^ vswz)];
#pragma unroll
                for (int j = 0; j < 4; j++) {
                    float p = (kk == 0) ? pj[j].x : (kk == 1) ? pj[j].y
                            : (kk == 2) ? pj[j].z : pj[j].w;
                    acc[j][0] += p * vv.x; acc[j][1] += p * vv.y;
                    acc[j][2] += p * vv.z; acc[j][3] += p * vv.w;
                }
            }
        }
    }

    // Normalize and store context
#pragma unroll
    for (int j = 0; j < 4; j++) {
        float inv = 1.0f / ls[j];
        float4 o = make_float4(acc[j][0]*inv, acc[j][1]*inv, acc[j][2]*inv, acc[j][3]*inv);
        *(float4*)&g_ctx[(baseRow + qb*64 + ty*4 + j) * Dd + headOff + tx*4] = o;
    }
}

// ---------------------------------------------------------------------------
// Residual + bias + LayerNorm: one CTA per row, 256 threads x 2 elements.
// ---------------------------------------------------------------------------
__global__ __launch_bounds__(256) void ln_kernel(const float* __restrict__ x,
                                                 const float* __restrict__ bo,
                                                 const float* __restrict__ gamma,
                                                 const float* __restrict__ beta,
                                                 float* __restrict__ out)
{
    int row = blockIdx.x;
    int t = threadIdx.x;
    size_t base = (size_t)row * 512;
    float h0 = g_h[base + t]       + bo[t]       + x[base + t];
    float h1 = g_h[base + t + 256] + bo[t + 256] + x[base + t + 256];
    float s = h0 + h1;
    float q = h0*h0 + h1*h1;
#pragma unroll
    for (int m = 16; m >= 1; m >>= 1) {
        s += __shfl_xor_sync(0xffffffffu, s, m);
        q += __shfl_xor_sync(0xffffffffu, q, m);
    }
    __shared__ float ss[8], qq[8];
    int w = t >> 5;
    if ((t & 31) == 0) { ss[w] = s; qq[w] = q; }
    __syncthreads();
    float S2 = 0.f, Q2 = 0.f;
#pragma unroll
    for (int i = 0; i < 8; i++) { S2 += ss[i]; Q2 += qq[i]; }
    float mu  = S2 * (1.0f / 512.0f);
    float var = Q2 * (1.0f / 512.0f) - mu * mu;
    float inv = rsqrtf(var + 1e-12f);
    out[base + t]       = (h0 - mu) * inv * gamma[t]       + beta[t];
    out[base + t + 256] = (h1 - mu) * inv * gamma[t + 256] + beta[t + 256];
}

// ---------------------------------------------------------------------------
extern "C" void kernel_launch(void* const* d_in, const int* in_sizes, int n_in,
                              void* d_out, int out_size)
{
    const float* x     = (const float*)d_in[0];
    const float* mask  = (const float*)d_in[1];
    const int*   rb    = (const int*)  d_in[2];
    const float* Wq    = (const float*)d_in[3];
    const float* Wk    = (const float*)d_in[4];
    const float* Wv    = (const float*)d_in[5];
    const float* Wo    = (const float*)d_in[6];
    const float* bo    = (const float*)d_in[7];
    const float* gamma = (const float*)d_in[8];
    const float* beta  = (const float*)d_in[9];
    float* out = (float*)d_out;

    float *qp, *kp, *vp, *cp, *hp;
    cudaGetSymbolAddress((void**)&qp, g_q);
    cudaGetSymbolAddress((void**)&kp, g_k);
    cudaGetSymbolAddress((void**)&vp, g_v);
    cudaGetSymbolAddress((void**)&cp, g_ctx);
    cudaGetSymbolAddress((void**)&hp, g_h);

    dim3 gg(8, 128);                                  // 512/64 x 8192/64
    sgemm64<<<gg, 256>>>(x, Wq, qp, 0.125f);          // q *= HD^-0.5
    sgemm64<<<gg, 256>>>(x, Wk, kp, 1.0f);
    sgemm64<<<gg, 256>>>(x, Wv, vp, 1.0f);
    attn_kernel<<<Bb * Hh * NBb, 256>>>(mask, rb);    // 1024 CTAs
    sgemm64<<<gg, 256>>>(cp, Wo, hp, 1.0f);
    ln_kernel<<<Bb * Ss, 256>>>(x, bo, gamma, beta, out);
}

// round 2
// speedup vs baseline: 1.3021x; 1.3021x over previous
#include <cuda_runtime.h>
#include <math.h>

#define Bb 2
#define Ss 4096
#define Dd 512
#define Hh 8
#define NBb 64

// Scratch (device globals: allocation-free, graph-safe)
__device__ float g_q[Bb*Ss*Dd];
__device__ float g_k[Bb*Ss*Dd];
__device__ float g_v[Bb*Ss*Dd];
__device__ float g_ctx[Bb*Ss*Dd];
__device__ float g_h[Bb*Ss*Dd];
// Dense split-K partials: 512 slots x (64x64 acc + 64 m + 64 l)
#define SLOT_F 4224
__device__ float g_part[512 * SLOT_F];

// ---------------------------------------------------------------------------
// SGEMM: Y[8192,512] = alpha * X[8192,512] @ W[512,512]
// ---------------------------------------------------------------------------
__global__ __launch_bounds__(256) void sgemm64(const float* __restrict__ X,
                                               const float* __restrict__ W,
                                               float* __restrict__ Y, float alpha)
{
    __shared__ float Xs[16][68];
    __shared__ float Ws[16][64];
    int t  = threadIdx.x;
    int ty = t >> 4, tx = t & 15;
    int rowBase = blockIdx.y * 64;
    int colBase = blockIdx.x * 64;
    int xr = t >> 2, xc = t & 3;
    int wr = t >> 4, wc = t & 15;

    float acc[4][4];
#pragma unroll
    for (int j = 0; j < 4; j++)
#pragma unroll
        for (int i = 0; i < 4; i++) acc[j][i] = 0.f;

    for (int kb = 0; kb < 512; kb += 16) {
        float4 xv = *(const float4*)&X[(size_t)(rowBase + xr) * 512 + kb + xc * 4];
        float4 wv = *(const float4*)&W[(size_t)(kb + wr) * 512 + colBase + wc * 4];
        __syncthreads();
        Xs[xc*4+0][xr] = xv.x; Xs[xc*4+1][xr] = xv.y;
        Xs[xc*4+2][xr] = xv.z; Xs[xc*4+3][xr] = xv.w;
        *(float4*)&Ws[wr][wc*4] = wv;
        __syncthreads();
#pragma unroll
        for (int kk = 0; kk < 16; kk++) {
            float4 a = *(const float4*)&Xs[kk][ty*4];
            float4 b = *(const float4*)&Ws[kk][tx*4];
            acc[0][0] += a.x*b.x; acc[0][1] += a.x*b.y; acc[0][2] += a.x*b.z; acc[0][3] += a.x*b.w;
            acc[1][0] += a.y*b.x; acc[1][1] += a.y*b.y; acc[1][2] += a.y*b.z; acc[1][3] += a.y*b.w;
            acc[2][0] += a.z*b.x; acc[2][1] += a.z*b.y; acc[2][2] += a.z*b.z; acc[2][3] += a.z*b.w;
            acc[3][0] += a.w*b.x; acc[3][1] += a.w*b.y; acc[3][2] += a.w*b.z; acc[3][3] += a.w*b.w;
        }
    }
#pragma unroll
    for (int j = 0; j < 4; j++) {
        float4 o = make_float4(acc[j][0]*alpha, acc[j][1]*alpha,
                               acc[j][2]*alpha, acc[j][3]*alpha);
        *(float4*)&Y[(size_t)(rowBase + ty*4 + j) * 512 + colBase + tx*4] = o;
    }
}

// ---------------------------------------------------------------------------
// Balanced attention: 1472 uniform work units of 8 key-blocks each.
//   unit u in [0,92) per (b,h):
//     u < 60         -> mid q-block qb=u+2 (band+glob+rand), writes ctx
//     u >= 60        -> dense split: d=u-60; qb={0,1,62,63}[d>>3], chunk=d&7,
//                       key blocks [chunk*8, chunk*8+8), writes partial slot
// ---------------------------------------------------------------------------
__device__ __forceinline__ float redmax16(float v) {
#pragma unroll
    for (int m = 8; m >= 1; m >>= 1) v = fmaxf(v, __shfl_xor_sync(0xffffffffu, v, m));
    return v;
}
__device__ __forceinline__ float redsum16(float v) {
#pragma unroll
    for (int m = 8; m >= 1; m >>= 1) v += __shfl_xor_sync(0xffffffffu, v, m);
    return v;
}

__global__ __launch_bounds__(256, 2) void attn_kernel(const float* __restrict__ mask,
                                                      const int* __restrict__ rand_blocks)
{
    __shared__ float qs[64*64];
    __shared__ float kv[64*64];
    __shared__ float ps[64*64];

    int t  = threadIdx.x;
    int ty = t >> 4, tx = t & 15;
    int u  = blockIdx.x % 92;
    int bh = blockIdx.x / 92;
    int b  = bh >> 3;
    int h  = bh & 7;
    size_t headOff = (size_t)h * 64;
    size_t baseRow = (size_t)b * Ss;

    bool mid = (u < 60);
    int qb, chunk = 0, di = 0;
    if (mid) { qb = u + 2; }
    else {
        int d = u - 60;
        di = d >> 3; chunk = d & 7;
        qb = (di < 2) ? di : (60 + di);
    }

    // Load scaled-Q tile
#pragma unroll
    for (int it = 0; it < 4; it++) {
        int idx = t + it * 256;
        int row = idx >> 4, ch = idx & 15;
        float4 v4 = *(const float4*)&g_q[(baseRow + qb*64 + row) * Dd + headOff + ch*4];
        *(float4*)&qs[row*64 + ch*4] = v4;
    }
    float mqr[4];
#pragma unroll
    for (int j = 0; j < 4; j++) mqr[j] = mask[baseRow + qb*64 + ty*4 + j];

    float acc[4][4], mo[4], ls[4];
#pragma unroll
    for (int j = 0; j < 4; j++) {
        mo[j] = -INFINITY; ls[j] = 0.f;
#pragma unroll
        for (int i = 0; i < 4; i++) acc[j][i] = 0.f;
    }

    for (int itk = 0; itk < 8; itk++) {
        int kb; bool band = false;
        if (!mid) kb = chunk * 8 + itk;
        else if (itk < 3)       { kb = qb - 1 + itk; band = true; }
        else if (itk == 3)        kb = 0;
        else if (itk == 4)        kb = 63;
        else                      kb = rand_blocks[(qb - 2) * 3 + (itk - 5)];

        __syncthreads();
        // K tile, swizzled: (kc,d) -> kv[kc*64 + (d ^ (((kc>>2)&15)<<2))]
#pragma unroll
        for (int it = 0; it < 4; it++) {
            int idx = t + it * 256;
            int kc = idx >> 4, d = (idx & 15) * 4;
            float4 v4 = *(const float4*)&g_k[(baseRow + kb*64 + kc) * Dd + headOff + d];
            int dsw = d ^ (((kc >> 2) & 15) << 2);
            *(float4*)&kv[kc*64 + dsw] = v4;
        }
        __syncthreads();

        float sc[4][4];
#pragma unroll
        for (int j = 0; j < 4; j++)
#pragma unroll
            for (int i = 0; i < 4; i++) sc[j][i] = 0.f;
        int swz = tx << 2;
#pragma unroll
        for (int d0 = 0; d0 < 64; d0 += 4) {
            float4 a[4], bb[4];
#pragma unroll
            for (int j = 0; j < 4; j++) a[j]  = *(const float4*)&qs[(ty*4+j)*64 + d0];
            int dsw = d0 ^ swz;
#pragma unroll
            for (int i = 0; i < 4; i++) bb[i] = *(const float4*)&kv[(tx*4+i)*64 + dsw];
#pragma unroll
            for (int j = 0; j < 4; j++)
#pragma unroll
                for (int i = 0; i < 4; i++)
                    sc[j][i] += a[j].x*bb[i].x + a[j].y*bb[i].y
                              + a[j].z*bb[i].z + a[j].w*bb[i].w;
        }

#pragma unroll
        for (int i = 0; i < 4; i++) {
            float mkv = mask[baseRow + kb*64 + tx*4 + i];
#pragma unroll
            for (int j = 0; j < 4; j++) {
                float mm = band ? mkv * mqr[j] : mkv;
                sc[j][i] += (1.0f - mm) * (-1000000000.0f);
            }
        }

#pragma unroll
        for (int j = 0; j < 4; j++) {
            float m = fmaxf(fmaxf(sc[j][0], sc[j][1]), fmaxf(sc[j][2], sc[j][3]));
            m = redmax16(m);
            float mn = fmaxf(mo[j], m);
            float corr = __expf(mo[j] - mn);
            float rs = 0.f;
#pragma unroll
            for (int i = 0; i < 4; i++) { float p = __expf(sc[j][i] - mn); sc[j][i] = p; rs += p; }
            rs = redsum16(rs);
            ls[j] = ls[j] * corr + rs;
#pragma unroll
            for (int i = 0; i < 4; i++) acc[j][i] *= corr;
            mo[j] = mn;
        }

        __syncthreads();
#pragma unroll
        for (int it = 0; it < 4; it++) {
            int idx = t + it * 256;
            int kc = idx >> 4, d = (idx & 15) * 4;
            float4 v4 = *(const float4*)&g_v[(baseRow + kb*64 + kc) * Dd + headOff + d];
            int dsw = d ^ (((kc >> 2) & 15) << 2);
            *(float4*)&kv[kc*64 + dsw] = v4;
        }
#pragma unroll
        for (int j = 0; j < 4; j++)
            *(float4*)&ps[(ty*4+j)*64 + tx*4] =
                make_float4(sc[j][0], sc[j][1], sc[j][2], sc[j][3]);
        __syncthreads();

#pragma unroll
        for (int k0 = 0; k0 < 64; k0 += 4) {
            float4 pj[4];
#pragma unroll
            for (int j = 0; j < 4; j++) pj[j] = *(const float4*)&ps[(ty*4+j)*64 + k0];
            int vswz = ((k0 >> 2) & 15) << 2;
#pragma unroll
            for (int kk = 0; kk < 4; kk++) {
                float4 vv = *(const float4*)&kv[(k0+kk)*64 + ((tx*4) ^ vswz)];
#pragma unroll
                for (int j = 0; j < 4; j++) {
                    float p = (kk == 0) ? pj[j].x : (kk == 1) ? pj[j].y
                            : (kk == 2) ? pj[j].z : pj[j].w;
                    acc[j][0] += p * vv.x; acc[j][1] += p * vv.y;
                    acc[j][2] += p * vv.z; acc[j][3] += p * vv.w;
                }
            }
        }
    }

    if (mid) {
#pragma unroll
        for (int j = 0; j < 4; j++) {
            float inv = 1.0f / ls[j];
            float4 o = make_float4(acc[j][0]*inv, acc[j][1]*inv, acc[j][2]*inv, acc[j][3]*inv);
            *(float4*)&g_ctx[(baseRow + qb*64 + ty*4 + j) * Dd + headOff + tx*4] = o;
        }
    } else {
        int slot = (bh * 4 + di) * 8 + chunk;
        float* p = g_part + (size_t)slot * SLOT_F;
#pragma unroll
        for (int j = 0; j < 4; j++) {
            int row = ty * 4 + j;
            *(float4*)&p[row*64 + tx*4] =
                make_float4(acc[j][0], acc[j][1], acc[j][2], acc[j][3]);
            if (tx == 0) { p[4096 + row] = mo[j]; p[4160 + row] = ls[j]; }
        }
    }
}

// ---------------------------------------------------------------------------
// Combine 8 split-K partials per dense (b,h,qb). 64 CTAs x 256 threads.
// thread: row = t & 63, col group = (t>>6)*16
// ---------------------------------------------------------------------------
__global__ __launch_bounds__(256) void combine_kernel()
{
    int g  = blockIdx.x;          // (bh*4 + di)
    int bh = g >> 2, di = g & 3;
    int qb = (di < 2) ? di : (60 + di);
    int b  = bh >> 3, h = bh & 7;
    int t   = threadIdx.x;
    int row = t & 63;
    int c0  = (t >> 6) * 16;

    const float* base = g_part + (size_t)(g * 8) * SLOT_F;
    float m[8];
    float M = -INFINITY;
#pragma unroll
    for (int s = 0; s < 8; s++) { m[s] = base[s*SLOT_F + 4096 + row]; M = fmaxf(M, m[s]); }
    float w[8]; float L = 0.f;
#pragma unroll
    for (int s = 0; s < 8; s++) { w[s] = __expf(m[s] - M); L += base[s*SLOT_F + 4160 + row] * w[s]; }
    float inv = 1.0f / L;

    float o[16];
#pragma unroll
    for (int c = 0; c < 16; c++) o[c] = 0.f;
#pragma unroll
    for (int s = 0; s < 8; s++) {
        const float* pa = base + s*SLOT_F + row*64 + c0;
        float ws = w[s];
#pragma unroll
        for (int c4 = 0; c4 < 4; c4++) {
            float4 v4 = *(const float4*)&pa[c4*4];
            o[c4*4+0] += ws * v4.x; o[c4*4+1] += ws * v4.y;
            o[c4*4+2] += ws * v4.z; o[c4*4+3] += ws * v4.w;
        }
    }
    float* dst = &g_ctx[((size_t)b*Ss + qb*64 + row) * Dd + h*64 + c0];
#pragma unroll
    for (int c4 = 0; c4 < 4; c4++)
        *(float4*)&dst[c4*4] = make_float4(o[c4*4+0]*inv, o[c4*4+1]*inv,
                                           o[c4*4+2]*inv, o[c4*4+3]*inv);
}

// ---------------------------------------------------------------------------
// Residual + bias + LayerNorm
// ---------------------------------------------------------------------------
__global__ __launch_bounds__(256) void ln_kernel(const float* __restrict__ x,
                                                 const float* __restrict__ bo,
                                                 const float* __restrict__ gamma,
                                                 const float* __restrict__ beta,
                                                 float* __restrict__ out)
{
    int row = blockIdx.x;
    int t = threadIdx.x;
    size_t base = (size_t)row * 512;
    float h0 = g_h[base + t]       + bo[t]       + x[base + t];
    float h1 = g_h[base + t + 256] + bo[t + 256] + x[base + t + 256];
    float s = h0 + h1;
    float q = h0*h0 + h1*h1;
#pragma unroll
    for (int m = 16; m >= 1; m >>= 1) {
        s += __shfl_xor_sync(0xffffffffu, s, m);
        q += __shfl_xor_sync(0xffffffffu, q, m);
    }
    __shared__ float ss[8], qq[8];
    int w = t >> 5;
    if ((t & 31) == 0) { ss[w] = s; qq[w] = q; }
    __syncthreads();
    float S2 = 0.f, Q2 = 0.f;
#pragma unroll
    for (int i = 0; i < 8; i++) { S2 += ss[i]; Q2 += qq[i]; }
    float mu  = S2 * (1.0f / 512.0f);
    float var = Q2 * (1.0f / 512.0f) - mu * mu;
    float inv = rsqrtf(var + 1e-12f);
    out[base + t]       = (h0 - mu) * inv * gamma[t]       + beta[t];
    out[base + t + 256] = (h1 - mu) * inv * gamma[t + 256] + beta[t + 256];
}

// ---------------------------------------------------------------------------
extern "C" void kernel_launch(void* const* d_in, const int* in_sizes, int n_in,
                              void* d_out, int out_size)
{
    const float* x     = (const float*)d_in[0];
    const float* mask  = (const float*)d_in[1];
    const int*   rb    = (const int*)  d_in[2];
    const float* Wq    = (const float*)d_in[3];
    const float* Wk    = (const float*)d_in[4];
    const float* Wv    = (const float*)d_in[5];
    const float* Wo    = (const float*)d_in[6];
    const float* bo    = (const float*)d_in[7];
    const float* gamma = (const float*)d_in[8];
    const float* beta  = (const float*)d_in[9];
    float* out = (float*)d_out;

    float *qp, *kp, *vp, *cp, *hp;
    cudaGetSymbolAddress((void**)&qp, g_q);
    cudaGetSymbolAddress((void**)&kp, g_k);
    cudaGetSymbolAddress((void**)&vp, g_v);
    cudaGetSymbolAddress((void**)&cp, g_ctx);
    cudaGetSymbolAddress((void**)&hp, g_h);

    dim3 gg(8, 128);
    sgemm64<<<gg, 256>>>(x, Wq, qp, 0.125f);
    sgemm64<<<gg, 256>>>(x, Wk, kp, 1.0f);
    sgemm64<<<gg, 256>>>(x, Wv, vp, 1.0f);
    attn_kernel<<<16 * 92, 256>>>(mask, rb);       // 1472 uniform units
    combine_kernel<<<64, 256>>>();
    sgemm64<<<gg, 256>>>(cp, Wo, hp, 1.0f);
    ln_kernel<<<Bb * Ss, 256>>>(x, bo, gamma, beta, out);
}

// round 4
// speedup vs baseline: 2.0338x; 1.5620x over previous
#include <cuda_runtime.h>
#include <cuda_bf16.h>
#include <math.h>
#include <stdint.h>

#define Bb 2
#define Ss 4096
#define Dd 512
#define NROWS (Bb*Ss)      // 8192

// ---------------- scratch (device globals: allocation-free) ----------------
__device__ float g_q[NROWS*Dd];
__device__ float g_k[NROWS*Dd];
__device__ float g_v[NROWS*Dd];
__device__ float g_ctx[NROWS*Dd];
__device__ float g_h[NROWS*Dd];
#define SLOT_F 4224
__device__ float g_part[512 * SLOT_F];
__device__ __align__(16) __nv_bfloat16 g_xhi[NROWS*Dd];
__device__ __align__(16) __nv_bfloat16 g_xlo[NROWS*Dd];
__device__ __align__(16) __nv_bfloat16 g_wthi[4*Dd*Dd];   // W^T per matrix
__device__ __align__(16) __nv_bfloat16 g_wtlo[4*Dd*Dd];

// ---------------- PTX helpers (base-target legal: sm_80+) ----------------
__device__ __forceinline__ uint32_t smem_u32(const void* p) {
    return (uint32_t)__cvta_generic_to_shared(p);
}
#define CPASYNC16(dst, src) \
    asm volatile("cp.async.cg.shared.global [%0], [%1], 16;" :: "r"(dst), "l"(src))
#define CPCOMMIT() asm volatile("cp.async.commit_group;" ::: "memory")
#define CPWAIT(n)  asm volatile("cp.async.wait_group %0;" :: "n"(n) : "memory")

#define LDSM_X4(r0, r1, r2, r3, a) \
    asm volatile("ldmatrix.sync.aligned.m8n8.x4.shared.b16 {%0,%1,%2,%3}, [%4];" \
                 : "=r"(r0), "=r"(r1), "=r"(r2), "=r"(r3) : "r"(a))

#define MMA16816(D, A, B0, B1) \
    asm volatile("mma.sync.aligned.m16n8k16.row.col.f32.bf16.bf16.f32 " \
                 "{%0,%1,%2,%3},{%4,%5,%6,%7},{%8,%9},{%0,%1,%2,%3};" \
                 : "+f"((D)[0]), "+f"((D)[1]), "+f"((D)[2]), "+f"((D)[3]) \
                 : "r"((A)[0]), "r"((A)[1]), "r"((A)[2]), "r"((A)[3]), \
                   "r"(B0), "r"(B1))

// ---------------------------------------------------------------------------
// Conversion: fp32 -> bf16 hi/lo split (elementwise). One CTA per row.
// ---------------------------------------------------------------------------
__global__ __launch_bounds__(256) void conv_x(const float* __restrict__ X,
                                              __nv_bfloat16* __restrict__ Hi,
                                              __nv_bfloat16* __restrict__ Lo)
{
    size_t i0 = (size_t)blockIdx.x * 512 + threadIdx.x;
#pragma unroll
    for (int s = 0; s < 2; s++) {
        size_t i = i0 + s * 256;
        float v = X[i];
        __nv_bfloat16 h = __float2bfloat16(v);
        Hi[i] = h;
        Lo[i] = __float2bfloat16(v - __bfloat162float(h));
    }
}

// W[512,512] -> W^T bf16 hi/lo. grid (16,16), block (32,8)
__global__ void conv_wt(const float* __restrict__ W,
                        __nv_bfloat16* __restrict__ Th,
                        __nv_bfloat16* __restrict__ Tl)
{
    __shared__ float tile[32][33];
    int n0 = blockIdx.x * 32, k0 = blockIdx.y * 32;
    int tx = threadIdx.x, ty = threadIdx.y;
#pragma unroll
    for (int j = 0; j < 32; j += 8)
        tile[ty + j][tx] = W[(size_t)(k0 + ty + j) * 512 + n0 + tx];
    __syncthreads();
#pragma unroll
    for (int j = 0; j < 32; j += 8) {
        int row = ty + j;
        float v = tile[tx][row];
        __nv_bfloat16 h = __float2bfloat16(v);
        size_t o = (size_t)(n0 + row) * 512 + k0 + tx;
        Th[o] = h;
        Tl[o] = __float2bfloat16(v - __bfloat162float(h));
    }
}

// ---------------------------------------------------------------------------
// HMMA bf16 GEMM with hi/lo compensation:
//   Y[8192,512] = alpha * (Ahi@Bhi^T + Ahi@Blo^T + Alo@Bhi^T), B given as [n][k]
// CTA tile 128x128, warp tile 32x64, BK=64 double-buffered via cp.async.
// SMEM: A0 | B0 | A1 | B1  (4 x 16 KB = 64 KB dynamic)
// ---------------------------------------------------------------------------
#define GEMM_SMEM 65536

__device__ __forceinline__ void gemm_ld_chunk(const __nv_bfloat16* __restrict__ A,
                                              const __nv_bfloat16* __restrict__ Bt,
                                              int rowBase, int colBase, int k0,
                                              uint32_t Ab, uint32_t Bbuf, int t)
{
#pragma unroll
    for (int it = 0; it < 4; it++) {
        int idx = it * 256 + t;
        int r = idx >> 3, c = idx & 7;
        uint32_t d = Ab + r * 128 + ((c ^ (r & 7)) << 4);
        CPASYNC16(d, &A[(size_t)(rowBase + r) * 512 + k0 + c * 8]);
    }
#pragma unroll
    for (int it = 0; it < 4; it++) {
        int idx = it * 256 + t;
        int r = idx >> 3, c = idx & 7;
        uint32_t d = Bbuf + r * 128 + ((c ^ (r & 7)) << 4);
        CPASYNC16(d, &Bt[(size_t)(colBase + r) * 512 + k0 + c * 8]);
    }
    CPCOMMIT();
}

__global__ __launch_bounds__(256, 2)
void gemm_hmma(const __nv_bfloat16* __restrict__ Ahi,
               const __nv_bfloat16* __restrict__ Alo,
               const __nv_bfloat16* __restrict__ Bhi,
               const __nv_bfloat16* __restrict__ Blo,
               float* __restrict__ Y, float alpha)
{
    extern __shared__ __align__(128) char sm[];
    uint32_t sbase = smem_u32(sm);
    int t = threadIdx.x, w = t >> 5, lane = t & 31;
    int rowBase = blockIdx.y * 128, colBase = blockIdx.x * 128;
    int wm = (w & 3) * 32, wn = (w >> 2) * 64;

    float acc[2][8][4];
#pragma unroll
    for (int mt = 0; mt < 2; mt++)
#pragma unroll
        for (int nt = 0; nt < 8; nt++)
#pragma unroll
            for (int e = 0; e < 4; e++) acc[mt][nt][e] = 0.f;

    // lane address components for ldmatrix
    int laneA_row = (((lane >> 3) & 1) << 3) + (lane & 7);
    int laneA_ch  = (lane >> 4);
    int laneB_row = ((lane >> 4) << 3) + (lane & 7);
    int laneB_ch  = ((lane >> 3) & 1);

    // prologue: chunk 0 (seg 0: Ahi x Bhi)
    gemm_ld_chunk(Ahi, Bhi, rowBase, colBase, 0, sbase, sbase + 16384u, t);

    for (int i = 0; i < 24; i++) {
        int buf = i & 1;
        if (i < 23) {
            int j = i + 1, seg = j >> 3, k0 = (j & 7) * 64;
            const __nv_bfloat16* As = (seg < 2)  ? Ahi : Alo;
            const __nv_bfloat16* Bs = (seg == 1) ? Blo : Bhi;
            uint32_t Ab = sbase + (buf ? 0u : 32768u);
            uint32_t Bbuf = Ab + 16384u;
            gemm_ld_chunk(As, Bs, rowBase, colBase, k0, Ab, Bbuf, t);
            CPWAIT(1);
        } else {
            CPWAIT(0);
        }
        __syncthreads();

        uint32_t Ab = sbase + (buf ? 32768u : 0u);
        uint32_t Bbuf = Ab + 16384u;
#pragma unroll
        for (int ks = 0; ks < 4; ks++) {
            uint32_t afr[2][4];
#pragma unroll
            for (int mt = 0; mt < 2; mt++) {
                int row = wm + mt * 16 + laneA_row;
                int ch  = ks * 2 + laneA_ch;
                uint32_t a = Ab + row * 128 + ((ch ^ (row & 7)) << 4);
                LDSM_X4(afr[mt][0], afr[mt][1], afr[mt][2], afr[mt][3], a);
            }
#pragma unroll
            for (int p = 0; p < 4; p++) {
                int row = wn + p * 16 + laneB_row;
                int ch  = ks * 2 + laneB_ch;
                uint32_t a = Bbuf + row * 128 + ((ch ^ (row & 7)) << 4);
                uint32_t b0, b1, b2, b3;
                LDSM_X4(b0, b1, b2, b3, a);
#pragma unroll
                for (int mt = 0; mt < 2; mt++) {
                    MMA16816(acc[mt][p*2],   afr[mt], b0, b1);
                    MMA16816(acc[mt][p*2+1], afr[mt], b2, b3);
                }
            }
        }
        __syncthreads();
    }

    // epilogue
#pragma unroll
    for (int mt = 0; mt < 2; mt++)
#pragma unroll
        for (int nt = 0; nt < 8; nt++) {
            float* a4 = acc[mt][nt];
            int r0 = rowBase + wm + mt * 16 + (lane >> 2);
            int c0 = colBase + wn + nt * 8 + (lane & 3) * 2;
            *(float2*)&Y[(size_t)r0 * 512 + c0] =
                make_float2(a4[0] * alpha, a4[1] * alpha);
            *(float2*)&Y[(size_t)(r0 + 8) * 512 + c0] =
                make_float2(a4[2] * alpha, a4[3] * alpha);
        }
}

// ---------------------------------------------------------------------------
// Balanced attention (unchanged): 1472 uniform 8-block units.
// ---------------------------------------------------------------------------
__device__ __forceinline__ float redmax16(float v) {
#pragma unroll
    for (int m = 8; m >= 1; m >>= 1) v = fmaxf(v, __shfl_xor_sync(0xffffffffu, v, m));
    return v;
}
__device__ __forceinline__ float redsum16(float v) {
#pragma unroll
    for (int m = 8; m >= 1; m >>= 1) v += __shfl_xor_sync(0xffffffffu, v, m);
    return v;
}

__global__ __launch_bounds__(256, 2) void attn_kernel(const float* __restrict__ mask,
                                                      const int* __restrict__ rand_blocks)
{
    __shared__ float qs[64*64];
    __shared__ float kv[64*64];
    __shared__ float ps[64*64];

    int t  = threadIdx.x;
    int ty = t >> 4, tx = t & 15;
    int u  = blockIdx.x % 92;
    int bh = blockIdx.x / 92;
    int b  = bh >> 3;
    int h  = bh & 7;
    size_t headOff = (size_t)h * 64;
    size_t baseRow = (size_t)b * Ss;

    bool mid = (u < 60);
    int qb, chunk = 0, di = 0;
    if (mid) { qb = u + 2; }
    else {
        int d = u - 60;
        di = d >> 3; chunk = d & 7;
        qb = (di < 2) ? di : (60 + di);
    }

#pragma unroll
    for (int it = 0; it < 4; it++) {
        int idx = t + it * 256;
        int row = idx >> 4, ch = idx & 15;
        float4 v4 = *(const float4*)&g_q[(baseRow + qb*64 + row) * Dd + headOff + ch*4];
        *(float4*)&qs[row*64 + ch*4] = v4;
    }
    float mqr[4];
#pragma unroll
    for (int j = 0; j < 4; j++) mqr[j] = mask[baseRow + qb*64 + ty*4 + j];

    float acc[4][4], mo[4], ls[4];
#pragma unroll
    for (int j = 0; j < 4; j++) {
        mo[j] = -INFINITY; ls[j] = 0.f;
#pragma unroll
        for (int i = 0; i < 4; i++) acc[j][i] = 0.f;
    }

    for (int itk = 0; itk < 8; itk++) {
        int kb; bool band = false;
        if (!mid) kb = chunk * 8 + itk;
        else if (itk < 3)       { kb = qb - 1 + itk; band = true; }
        else if (itk == 3)        kb = 0;
        else if (itk == 4)        kb = 63;
        else                      kb = rand_blocks[(qb - 2) * 3 + (itk - 5)];

        __syncthreads();
#pragma unroll
        for (int it = 0; it < 4; it++) {
            int idx = t + it * 256;
            int kc = idx >> 4, d = (idx & 15) * 4;
            float4 v4 = *(const float4*)&g_k[(baseRow + kb*64 + kc) * Dd + headOff + d];
            int dsw = d ^ (((kc >> 2) & 15) << 2);
            *(float4*)&kv[kc*64 + dsw] = v4;
        }
        __syncthreads();

        float sc[4][4];
#pragma unroll
        for (int j = 0; j < 4; j++)
#pragma unroll
            for (int i = 0; i < 4; i++) sc[j][i] = 0.f;
        int swz = tx << 2;
#pragma unroll
        for (int d0 = 0; d0 < 64; d0 += 4) {
            float4 a[4], bb[4];
#pragma unroll
            for (int j = 0; j < 4; j++) a[j]  = *(const float4*)&qs[(ty*4+j)*64 + d0];
            int dsw = d0 ^ swz;
#pragma unroll
            for (int i = 0; i < 4; i++) bb[i] = *(const float4*)&kv[(tx*4+i)*64 + dsw];
#pragma unroll
            for (int j = 0; j < 4; j++)
#pragma unroll
                for (int i = 0; i < 4; i++)
                    sc[j][i] += a[j].x*bb[i].x + a[j].y*bb[i].y
                              + a[j].z*bb[i].z + a[j].w*bb[i].w;
        }

#pragma unroll
        for (int i = 0; i < 4; i++) {
            float mkv = mask[baseRow + kb*64 + tx*4 + i];
#pragma unroll
            for (int j = 0; j < 4; j++) {
                float mm = band ? mkv * mqr[j] : mkv;
                sc[j][i] += (1.0f - mm) * (-1000000000.0f);
            }
        }

#pragma unroll
        for (int j = 0; j < 4; j++) {
            float m = fmaxf(fmaxf(sc[j][0], sc[j][1]), fmaxf(sc[j][2], sc[j][3]));
            m = redmax16(m);
            float mn = fmaxf(mo[j], m);
            float corr = __expf(mo[j] - mn);
            float rs = 0.f;
#pragma unroll
            for (int i = 0; i < 4; i++) { float p = __expf(sc[j][i] - mn); sc[j][i] = p; rs += p; }
            rs = redsum16(rs);
            ls[j] = ls[j] * corr + rs;
#pragma unroll
            for (int i = 0; i < 4; i++) acc[j][i] *= corr;
            mo[j] = mn;
        }

        __syncthreads();
#pragma unroll
        for (int it = 0; it < 4; it++) {
            int idx = t + it * 256;
            int kc = idx >> 4, d = (idx & 15) * 4;
            float4 v4 = *(const float4*)&g_v[(baseRow + kb*64 + kc) * Dd + headOff + d];
            int dsw = d ^ (((kc >> 2) & 15) << 2);
            *(float4*)&kv[kc*64 + dsw] = v4;
        }
#pragma unroll
        for (int j = 0; j < 4; j++)
            *(float4*)&ps[(ty*4+j)*64 + tx*4] =
                make_float4(sc[j][0], sc[j][1], sc[j][2], sc[j][3]);
        __syncthreads();

#pragma unroll
        for (int k0 = 0; k0 < 64; k0 += 4) {
            float4 pj[4];
#pragma unroll
            for (int j = 0; j < 4; j++) pj[j] = *(const float4*)&ps[(ty*4+j)*64 + k0];
            int vswz = ((k0 >> 2) & 15) << 2;
#pragma unroll
            for (int kk = 0; kk < 4; kk++) {
                float4 vv = *(const float4*)&kv[(k0+kk)*64 + ((tx*4) ^ vswz)];
#pragma unroll
                for (int j = 0; j < 4; j++) {
                    float p = (kk == 0) ? pj[j].x : (kk == 1) ? pj[j].y
                            : (kk == 2) ? pj[j].z : pj[j].w;
                    acc[j][0] += p * vv.x; acc[j][1] += p * vv.y;
                    acc[j][2] += p * vv.z; acc[j][3] += p * vv.w;
                }
            }
        }
    }

    if (mid) {
#pragma unroll
        for (int j = 0; j < 4; j++) {
            float inv = 1.0f / ls[j];
            float4 o = make_float4(acc[j][0]*inv, acc[j][1]*inv, acc[j][2]*inv, acc[j][3]*inv);
            *(float4*)&g_ctx[(baseRow + qb*64 + ty*4 + j) * Dd + headOff + tx*4] = o;
        }
    } else {
        int slot = (bh * 4 + di) * 8 + chunk;
        float* p = g_part + (size_t)slot * SLOT_F;
#pragma unroll
        for (int j = 0; j < 4; j++) {
            int row = ty * 4 + j;
            *(float4*)&p[row*64 + tx*4] =
                make_float4(acc[j][0], acc[j][1], acc[j][2], acc[j][3]);
            if (tx == 0) { p[4096 + row] = mo[j]; p[4160 + row] = ls[j]; }
        }
    }
}

// ---------------------------------------------------------------------------
__global__ __launch_bounds__(256) void combine_kernel()
{
    int g  = blockIdx.x;
    int bh = g >> 2, di = g & 3;
    int qb = (di < 2) ? di : (60 + di);
    int b  = bh >> 3, h = bh & 7;
    int t   = threadIdx.x;
    int row = t & 63;
    int c0  = (t >> 6) * 16;

    const float* base = g_part + (size_t)(g * 8) * SLOT_F;
    float m[8];
    float M = -INFINITY;
#pragma unroll
    for (int s = 0; s < 8; s++) { m[s] = base[s*SLOT_F + 4096 + row]; M = fmaxf(M, m[s]); }
    float w[8]; float L = 0.f;
#pragma unroll
    for (int s = 0; s < 8; s++) { w[s] = __expf(m[s] - M); L += base[s*SLOT_F + 4160 + row] * w[s]; }
    float inv = 1.0f / L;

    float o[16];
#pragma unroll
    for (int c = 0; c < 16; c++) o[c] = 0.f;
#pragma unroll
    for (int s = 0; s < 8; s++) {
        const float* pa = base + s*SLOT_F + row*64 + c0;
        float ws = w[s];
#pragma unroll
        for (int c4 = 0; c4 < 4; c4++) {
            float4 v4 = *(const float4*)&pa[c4*4];
            o[c4*4+0] += ws * v4.x; o[c4*4+1] += ws * v4.y;
            o[c4*4+2] += ws * v4.z; o[c4*4+3] += ws * v4.w;
        }
    }
    float* dst = &g_ctx[((size_t)b*Ss + qb*64 + row) * Dd + h*64 + c0];
#pragma unroll
    for (int c4 = 0; c4 < 4; c4++)
        *(float4*)&dst[c4*4] = make_float4(o[c4*4+0]*inv, o[c4*4+1]*inv,
                                           o[c4*4+2]*inv, o[c4*4+3]*inv);
}

// ---------------------------------------------------------------------------
__global__ __launch_bounds__(256) void ln_kernel(const float* __restrict__ x,
                                                 const float* __restrict__ bo,
                                                 const float* __restrict__ gamma,
                                                 const float* __restrict__ beta,
                                                 float* __restrict__ out)
{
    int row = blockIdx.x;
    int t = threadIdx.x;
    size_t base = (size_t)row * 512;
    float h0 = g_h[base + t]       + bo[t]       + x[base + t];
    float h1 = g_h[base + t + 256] + bo[t + 256] + x[base + t + 256];
    float s = h0 + h1;
    float q = h0*h0 + h1*h1;
#pragma unroll
    for (int m = 16; m >= 1; m >>= 1) {
        s += __shfl_xor_sync(0xffffffffu, s, m);
        q += __shfl_xor_sync(0xffffffffu, q, m);
    }
    __shared__ float ss[8], qq[8];
    int w = t >> 5;
    if ((t & 31) == 0) { ss[w] = s; qq[w] = q; }
    __syncthreads();
    float S2 = 0.f, Q2 = 0.f;
#pragma unroll
    for (int i = 0; i < 8; i++) { S2 += ss[i]; Q2 += qq[i]; }
    float mu  = S2 * (1.0f / 512.0f);
    float var = Q2 * (1.0f / 512.0f) - mu * mu;
    float inv = rsqrtf(var + 1e-12f);
    out[base + t]       = (h0 - mu) * inv * gamma[t]       + beta[t];
    out[base + t + 256] = (h1 - mu) * inv * gamma[t + 256] + beta[t + 256];
}

// ---------------------------------------------------------------------------
extern "C" void kernel_launch(void* const* d_in, const int* in_sizes, int n_in,
                              void* d_out, int out_size)
{
    const float* x     = (const float*)d_in[0];
    const float* mask  = (const float*)d_in[1];
    const int*   rb    = (const int*)  d_in[2];
    const float* Wq    = (const float*)d_in[3];
    const float* Wk    = (const float*)d_in[4];
    const float* Wv    = (const float*)d_in[5];
    const float* Wo    = (const float*)d_in[6];
    const float* bo    = (const float*)d_in[7];
    const float* gamma = (const float*)d_in[8];
    const float* beta  = (const float*)d_in[9];
    float* out = (float*)d_out;

    float *qp, *kp, *vp, *cp, *hp;
    __nv_bfloat16 *xh, *xl, *wth, *wtl;
    cudaGetSymbolAddress((void**)&qp, g_q);
    cudaGetSymbolAddress((void**)&kp, g_k);
    cudaGetSymbolAddress((void**)&vp, g_v);
    cudaGetSymbolAddress((void**)&cp, g_ctx);
    cudaGetSymbolAddress((void**)&hp, g_h);
    cudaGetSymbolAddress((void**)&xh, g_xhi);
    cudaGetSymbolAddress((void**)&xl, g_xlo);
    cudaGetSymbolAddress((void**)&wth, g_wthi);
    cudaGetSymbolAddress((void**)&wtl, g_wtlo);

    cudaFuncSetAttribute(gemm_hmma, cudaFuncAttributeMaxDynamicSharedMemorySize, GEMM_SMEM);

    dim3 wtg(16, 16), wtb(32, 8);
    conv_x<<<NROWS, 256>>>(x, xh, xl);
    conv_wt<<<wtg, wtb>>>(Wq, wth + 0*262144, wtl + 0*262144);
    conv_wt<<<wtg, wtb>>>(Wk, wth + 1*262144, wtl + 1*262144);
    conv_wt<<<wtg, wtb>>>(Wv, wth + 2*262144, wtl + 2*262144);
    conv_wt<<<wtg, wtb>>>(Wo, wth + 3*262144, wtl + 3*262144);

    dim3 gg(4, 64);                       // 512/128 x 8192/128
    gemm_hmma<<<gg, 256, GEMM_SMEM>>>(xh, xl, wth + 0*262144, wtl + 0*262144, qp, 0.125f);
    gemm_hmma<<<gg, 256, GEMM_SMEM>>>(xh, xl, wth + 1*262144, wtl + 1*262144, kp, 1.0f);
    gemm_hmma<<<gg, 256, GEMM_SMEM>>>(xh, xl, wth + 2*262144, wtl + 2*262144, vp, 1.0f);

    attn_kernel<<<16 * 92, 256>>>(mask, rb);
    combine_kernel<<<64, 256>>>();

    conv_x<<<NROWS, 256>>>(cp, xh, xl);   // reuse hi/lo buffers for ctx
    gemm_hmma<<<gg, 256, GEMM_SMEM>>>(xh, xl, wth + 3*262144, wtl + 3*262144, hp, 1.0f);

    ln_kernel<<<Bb * Ss, 256>>>(x, bo, gamma, beta, out);
}

// round 5
// speedup vs baseline: 3.1969x; 1.5718x over previous
#include <cuda_runtime.h>
#include <cuda_bf16.h>
#include <math.h>
#include <stdint.h>

#define Bb 2
#define Ss 4096
#define Dd 512
#define NROWS (Bb*Ss)      // 8192
#define NEGF -1000000000.0f

// ---------------- scratch (device globals: allocation-free) ----------------
__device__ float g_h[NROWS*Dd];
#define SLOT_F 4224
__device__ float g_part[512 * SLOT_F];
__device__ __align__(16) __nv_bfloat16 g_xhi[NROWS*Dd];
__device__ __align__(16) __nv_bfloat16 g_xlo[NROWS*Dd];
__device__ __align__(16) __nv_bfloat16 g_wthi[4*Dd*Dd];   // W^T x4 (qkv rows 0..1535, Wo 1536..)
__device__ __align__(16) __nv_bfloat16 g_wtlo[4*Dd*Dd];
// per-head q/k/v: [bh][s][128] bf16, cols 0..63 = hi, 64..127 = lo
__device__ __align__(16) __nv_bfloat16 g_qc[16ULL*4096*128];
__device__ __align__(16) __nv_bfloat16 g_kc[16ULL*4096*128];
__device__ __align__(16) __nv_bfloat16 g_vc[16ULL*4096*128];

// ---------------- PTX helpers (base-target legal) ----------------
__device__ __forceinline__ uint32_t smem_u32(const void* p) {
    return (uint32_t)__cvta_generic_to_shared(p);
}
#define CPASYNC16(dst, src) \
    asm volatile("cp.async.cg.shared.global [%0], [%1], 16;" :: "r"(dst), "l"(src))
#define CPCOMMIT() asm volatile("cp.async.commit_group;" ::: "memory")
#define CPWAIT(n)  asm volatile("cp.async.wait_group %0;" :: "n"(n) : "memory")

#define LDSM_X4(r0, r1, r2, r3, a) \
    asm volatile("ldmatrix.sync.aligned.m8n8.x4.shared.b16 {%0,%1,%2,%3}, [%4];" \
                 : "=r"(r0), "=r"(r1), "=r"(r2), "=r"(r3) : "r"(a))
#define LDSM_X4T(r0, r1, r2, r3, a) \
    asm volatile("ldmatrix.sync.aligned.m8n8.x4.trans.shared.b16 {%0,%1,%2,%3}, [%4];" \
                 : "=r"(r0), "=r"(r1), "=r"(r2), "=r"(r3) : "r"(a))

#define MMA16816(D, A, B0, B1) \
    asm volatile("mma.sync.aligned.m16n8k16.row.col.f32.bf16.bf16.f32 " \
                 "{%0,%1,%2,%3},{%4,%5,%6,%7},{%8,%9},{%0,%1,%2,%3};" \
                 : "+f"((D)[0]), "+f"((D)[1]), "+f"((D)[2]), "+f"((D)[3]) \
                 : "r"((A)[0]), "r"((A)[1]), "r"((A)[2]), "r"((A)[3]), \
                   "r"(B0), "r"(B1))

__device__ __forceinline__ uint32_t pack_hi(float a, float b) {
    __nv_bfloat162 h = __floats2bfloat162_rn(a, b);
    return *(uint32_t*)&h;
}
__device__ __forceinline__ void split2(float a, float b, uint32_t& hi, uint32_t& lo) {
    __nv_bfloat16 ha = __float2bfloat16(a), hb = __float2bfloat16(b);
    float ra = a - __bfloat162float(ha), rb = b - __bfloat162float(hb);
    __nv_bfloat162 H; H.x = ha; H.y = hb;
    __nv_bfloat162 L = __floats2bfloat162_rn(ra, rb);
    hi = *(uint32_t*)&H; lo = *(uint32_t*)&L;
}

// ---------------------------------------------------------------------------
// Conversions
// ---------------------------------------------------------------------------
__global__ __launch_bounds__(256) void conv_x(const float* __restrict__ X,
                                              __nv_bfloat16* __restrict__ Hi,
                                              __nv_bfloat16* __restrict__ Lo)
{
    size_t i0 = (size_t)blockIdx.x * 512 + threadIdx.x;
#pragma unroll
    for (int s = 0; s < 2; s++) {
        size_t i = i0 + s * 256;
        float v = X[i];
        __nv_bfloat16 h = __float2bfloat16(v);
        Hi[i] = h;
        Lo[i] = __float2bfloat16(v - __bfloat162float(h));
    }
}

__global__ void conv_wt(const float* __restrict__ W,
                        __nv_bfloat16* __restrict__ Th,
                        __nv_bfloat16* __restrict__ Tl)
{
    __shared__ float tile[32][33];
    int n0 = blockIdx.x * 32, k0 = blockIdx.y * 32;
    int tx = threadIdx.x, ty = threadIdx.y;
#pragma unroll
    for (int j = 0; j < 32; j += 8)
        tile[ty + j][tx] = W[(size_t)(k0 + ty + j) * 512 + n0 + tx];
    __syncthreads();
#pragma unroll
    for (int j = 0; j < 32; j += 8) {
        int row = ty + j;
        float v = tile[tx][row];
        __nv_bfloat16 h = __float2bfloat16(v);
        size_t o = (size_t)(n0 + row) * 512 + k0 + tx;
        Th[o] = h;
        Tl[o] = __float2bfloat16(v - __bfloat162float(h));
    }
}

// ---------------------------------------------------------------------------
// Shared GEMM mainloop pieces (CTA 128x128, BK=64, cp.async double buffer)
// ---------------------------------------------------------------------------
#define GEMM_SMEM 65536

__device__ __forceinline__ void gemm_ld_chunk(const __nv_bfloat16* __restrict__ A,
                                              const __nv_bfloat16* __restrict__ Bt,
                                              int rowBase, int colBase, int k0,
                                              uint32_t Ab, uint32_t Bbuf, int t)
{
#pragma unroll
    for (int it = 0; it < 4; it++) {
        int idx = it * 256 + t;
        int r = idx >> 3, c = idx & 7;
        uint32_t d = Ab + r * 128 + ((c ^ (r & 7)) << 4);
        CPASYNC16(d, &A[(size_t)(rowBase + r) * 512 + k0 + c * 8]);
    }
#pragma unroll
    for (int it = 0; it < 4; it++) {
        int idx = it * 256 + t;
        int r = idx >> 3, c = idx & 7;
        uint32_t d = Bbuf + r * 128 + ((c ^ (r & 7)) << 4);
        CPASYNC16(d, &Bt[(size_t)(colBase + r) * 512 + k0 + c * 8]);
    }
    CPCOMMIT();
}

__device__ __forceinline__ void gemm_mainloop(const __nv_bfloat16* Ahi, const __nv_bfloat16* Alo,
                                              const __nv_bfloat16* Bhi, const __nv_bfloat16* Blo,
                                              int rowBase, int colBase, uint32_t sbase, int t,
                                              float acc[2][8][4])
{
    int w = t >> 5, lane = t & 31;
    int wm = (w & 3) * 32, wn = (w >> 2) * 64;
    int laneA_row = (((lane >> 3) & 1) << 3) + (lane & 7);
    int laneA_ch  = (lane >> 4);
    int laneB_row = ((lane >> 4) << 3) + (lane & 7);
    int laneB_ch  = ((lane >> 3) & 1);

    gemm_ld_chunk(Ahi, Bhi, rowBase, colBase, 0, sbase, sbase + 16384u, t);

    for (int i = 0; i < 24; i++) {
        int buf = i & 1;
        if (i < 23) {
            int j = i + 1, seg = j >> 3, k0 = (j & 7) * 64;
            const __nv_bfloat16* As = (seg < 2)  ? Ahi : Alo;
            const __nv_bfloat16* Bs = (seg == 1) ? Blo : Bhi;
            uint32_t Ab = sbase + (buf ? 0u : 32768u);
            gemm_ld_chunk(As, Bs, rowBase, colBase, k0, Ab, Ab + 16384u, t);
            CPWAIT(1);
        } else {
            CPWAIT(0);
        }
        __syncthreads();

        uint32_t Ab = sbase + (buf ? 32768u : 0u);
        uint32_t Bbuf = Ab + 16384u;
#pragma unroll
        for (int ks = 0; ks < 4; ks++) {
            uint32_t afr[2][4];
#pragma unroll
            for (int mt = 0; mt < 2; mt++) {
                int row = wm + mt * 16 + laneA_row;
                int ch  = ks * 2 + laneA_ch;
                uint32_t a = Ab + row * 128 + ((ch ^ (row & 7)) << 4);
                LDSM_X4(afr[mt][0], afr[mt][1], afr[mt][2], afr[mt][3], a);
            }
#pragma unroll
            for (int p = 0; p < 4; p++) {
                int row = wn + p * 16 + laneB_row;
                int ch  = ks * 2 + laneB_ch;
                uint32_t a = Bbuf + row * 128 + ((ch ^ (row & 7)) << 4);
                uint32_t b0, b1, b2, b3;
                LDSM_X4(b0, b1, b2, b3, a);
#pragma unroll
                for (int mt = 0; mt < 2; mt++) {
                    MMA16816(acc[mt][p*2],   afr[mt], b0, b1);
                    MMA16816(acc[mt][p*2+1], afr[mt], b2, b3);
                }
            }
        }
        __syncthreads();
    }
}

// Generic GEMM: Y fp32, stride 512
__global__ __launch_bounds__(256, 2)
void gemm_hmma(const __nv_bfloat16* __restrict__ Ahi,
               const __nv_bfloat16* __restrict__ Alo,
               const __nv_bfloat16* __restrict__ Bhi,
               const __nv_bfloat16* __restrict__ Blo,
               float* __restrict__ Y, float alpha)
{
    extern __shared__ __align__(128) char sm[];
    uint32_t sbase = smem_u32(sm);
    int t = threadIdx.x, w = t >> 5, lane = t & 31;
    int rowBase = blockIdx.y * 128, colBase = blockIdx.x * 128;
    int wm = (w & 3) * 32, wn = (w >> 2) * 64;

    float acc[2][8][4];
#pragma unroll
    for (int mt = 0; mt < 2; mt++)
#pragma unroll
        for (int nt = 0; nt < 8; nt++)
#pragma unroll
            for (int e = 0; e < 4; e++) acc[mt][nt][e] = 0.f;

    gemm_mainloop(Ahi, Alo, Bhi, Blo, rowBase, colBase, sbase, t, acc);

#pragma unroll
    for (int mt = 0; mt < 2; mt++)
#pragma unroll
        for (int nt = 0; nt < 8; nt++) {
            float* a4 = acc[mt][nt];
            int r0 = rowBase + wm + mt * 16 + (lane >> 2);
            int c0 = colBase + wn + nt * 8 + (lane & 3) * 2;
            *(float2*)&Y[(size_t)r0 * 512 + c0] = make_float2(a4[0]*alpha, a4[1]*alpha);
            *(float2*)&Y[(size_t)(r0+8) * 512 + c0] = make_float2(a4[2]*alpha, a4[3]*alpha);
        }
}

// QKV GEMM: B rows span 1536 (Wq|Wk|Wv transposed). Epilogue writes per-head
// hi/lo bf16 to g_qc / g_kc / g_vc (q scaled by 0.125).
__global__ __launch_bounds__(256, 2)
void gemm_qkv(const __nv_bfloat16* __restrict__ Ahi,
              const __nv_bfloat16* __restrict__ Alo,
              const __nv_bfloat16* __restrict__ Bhi,
              const __nv_bfloat16* __restrict__ Blo)
{
    extern __shared__ __align__(128) char sm[];
    uint32_t sbase = smem_u32(sm);
    int t = threadIdx.x, w = t >> 5, lane = t & 31;
    int rowBase = blockIdx.y * 128, colBase = blockIdx.x * 128;
    int wm = (w & 3) * 32, wn = (w >> 2) * 64;

    float acc[2][8][4];
#pragma unroll
    for (int mt = 0; mt < 2; mt++)
#pragma unroll
        for (int nt = 0; nt < 8; nt++)
#pragma unroll
            for (int e = 0; e < 4; e++) acc[mt][nt][e] = 0.f;

    gemm_mainloop(Ahi, Alo, Bhi, Blo, rowBase, colBase, sbase, t, acc);

    int tensor = colBase >> 9;
    float alpha = (tensor == 0) ? 0.125f : 1.0f;
    __nv_bfloat16* dst = (tensor == 0) ? g_qc : (tensor == 1) ? g_kc : g_vc;

#pragma unroll
    for (int mt = 0; mt < 2; mt++)
#pragma unroll
        for (int nt = 0; nt < 8; nt++) {
            float* a4 = acc[mt][nt];
            int r0 = rowBase + wm + mt * 16 + (lane >> 2);
            int cc = (colBase & 511) + wn + nt * 8 + (lane & 3) * 2;
            int hh = cc >> 6, dd = cc & 63;
            int b = r0 >> 12, s = r0 & 4095;
            size_t off = ((size_t)((b << 3) + hh) * 4096 + s) * 128 + dd;
            uint32_t hi, lo;
            split2(a4[0]*alpha, a4[1]*alpha, hi, lo);
            *(uint32_t*)&dst[off] = hi;
            *(uint32_t*)&dst[off + 64] = lo;
            size_t off2 = off + 8ULL * 128;   // row r0+8, same (b,h)
            split2(a4[2]*alpha, a4[3]*alpha, hi, lo);
            *(uint32_t*)&dst[off2] = hi;
            *(uint32_t*)&dst[off2 + 64] = lo;
        }
}

// ---------------------------------------------------------------------------
// HMMA attention: 1472 uniform 8-block units, hi/lo-compensated bf16 MMA.
// smem tiles [64 rows][128 bf16] (hi cols 0..63, lo 64..127), 16B-chunk swizzle.
// ---------------------------------------------------------------------------
#define ATT_SMEM (65536 + 256 + 512 + 512)

__global__ __launch_bounds__(256, 2)
void attn_hmma(const float* __restrict__ mask, const int* __restrict__ rand_blocks)
{
    extern __shared__ __align__(128) char sm[];
    uint32_t sb = smem_u32(sm);
    const uint32_t QS = sb, KS = sb + 16384, VS = sb + 32768, PS = sb + 49152;
    float* kmask_s = (float*)(sm + 65536);
    float* red1 = (float*)(sm + 65792);
    float* red2 = (float*)(sm + 66304);

    int t = threadIdx.x, w = t >> 5, lane = t & 31;
    int wm = (w & 3) * 16, wn = (w >> 2) * 32;
    int wni = w >> 2;

    int u  = blockIdx.x % 92;
    int bh = blockIdx.x / 92;
    int b  = bh >> 3, h = bh & 7;

    bool mid = (u < 60);
    int qb, chunk = 0, di = 0;
    if (mid) { qb = u + 2; }
    else {
        int d = u - 60;
        di = d >> 3; chunk = d & 7;
        qb = (di < 2) ? di : (60 + di);
    }

    // load Q tile [64][128]
    size_t qoff = ((size_t)bh * 4096 + qb * 64) * 128;
#pragma unroll
    for (int it = 0; it < 4; it++) {
        int idx = it * 256 + t;
        int r = idx >> 4, c = idx & 15;
        uint4 v = *(const uint4*)&g_qc[qoff + r * 128 + c * 8];
        *(uint4*)(sm + r * 256 + (((c ^ (r & 7)) & 15) << 4)) = v;
    }

    int r1 = wm + (lane >> 2), r2 = r1 + 8;
    float mq1 = mask[b * 4096 + qb * 64 + r1];
    float mq2 = mask[b * 4096 + qb * 64 + r2];

    float acc[4][4];
#pragma unroll
    for (int nt = 0; nt < 4; nt++)
#pragma unroll
        for (int e = 0; e < 4; e++) acc[nt][e] = 0.f;
    float mo1 = -INFINITY, mo2 = -INFINITY, ls1 = 0.f, ls2 = 0.f;

    int laneA_row = (((lane >> 3) & 1) << 3) + (lane & 7);
    int laneA_ch  = lane >> 4;
    int laneB_row = ((lane >> 4) << 3) + (lane & 7);
    int laneB_ch  = (lane >> 3) & 1;
    int laneV_row = lane & 15;
    int laneV_g   = lane >> 4;

    for (int itk = 0; itk < 8; itk++) {
        int kb; bool band = false;
        if (!mid) kb = chunk * 8 + itk;
        else if (itk < 3)       { kb = qb - 1 + itk; band = true; }
        else if (itk == 3)        kb = 0;
        else if (itk == 4)        kb = 63;
        else                      kb = rand_blocks[(qb - 2) * 3 + (itk - 5)];

        __syncthreads();
        size_t koff = ((size_t)bh * 4096 + kb * 64) * 128;
#pragma unroll
        for (int it = 0; it < 4; it++) {
            int idx = it * 256 + t;
            int r = idx >> 4, c = idx & 15;
            uint4 v = *(const uint4*)&g_kc[koff + r * 128 + c * 8];
            *(uint4*)(sm + 16384 + r * 256 + (((c ^ (r & 7)) & 15) << 4)) = v;
        }
#pragma unroll
        for (int it = 0; it < 4; it++) {
            int idx = it * 256 + t;
            int r = idx >> 4, c = idx & 15;
            uint4 v = *(const uint4*)&g_vc[koff + r * 128 + c * 8];
            *(uint4*)(sm + 32768 + r * 256 + (((c ^ (r & 7)) & 15) << 4)) = v;
        }
        if (t < 64) kmask_s[t] = mask[b * 4096 + kb * 64 + t];
        __syncthreads();

        // ---- QK: s = qh.kh + qh.kl + ql.kh (12 k16 steps) ----
        float sc[4][4];
#pragma unroll
        for (int nt = 0; nt < 4; nt++)
#pragma unroll
            for (int e = 0; e < 4; e++) sc[nt][e] = 0.f;

#pragma unroll
        for (int st = 0; st < 12; st++) {
            int Ah = (st < 8) ? 0 : 8;
            int Bh = ((st >> 2) == 1) ? 8 : 0;
            int kc2 = (st & 3) * 2;
            uint32_t a[4];
            {
                int row = wm + laneA_row;
                int ch = Ah + kc2 + laneA_ch;
                LDSM_X4(a[0], a[1], a[2], a[3], QS + row * 256 + ((ch ^ (row & 7)) << 4));
            }
#pragma unroll
            for (int g = 0; g < 2; g++) {
                int row = wn + g * 16 + laneB_row;
                int ch = Bh + kc2 + laneB_ch;
                uint32_t b0, b1, b2, b3;
                LDSM_X4(b0, b1, b2, b3, KS + row * 256 + ((ch ^ (row & 7)) << 4));
                MMA16816(sc[g*2],   a, b0, b1);
                MMA16816(sc[g*2+1], a, b2, b3);
            }
        }

        // ---- mask ----
#pragma unroll
        for (int nt = 0; nt < 4; nt++) {
            int col = wn + nt * 8 + (lane & 3) * 2;
            float mk0 = kmask_s[col], mk1 = kmask_s[col + 1];
            float m00 = band ? mk0 * mq1 : mk0;
            float m01 = band ? mk1 * mq1 : mk1;
            float m10 = band ? mk0 * mq2 : mk0;
            float m11 = band ? mk1 * mq2 : mk1;
            sc[nt][0] += (1.0f - m00) * NEGF;
            sc[nt][1] += (1.0f - m01) * NEGF;
            sc[nt][2] += (1.0f - m10) * NEGF;
            sc[nt][3] += (1.0f - m11) * NEGF;
        }

        // ---- row max (32 cols in-warp, then cross-warp via smem) ----
        float m1 = -INFINITY, m2 = -INFINITY;
#pragma unroll
        for (int nt = 0; nt < 4; nt++) {
            m1 = fmaxf(m1, fmaxf(sc[nt][0], sc[nt][1]));
            m2 = fmaxf(m2, fmaxf(sc[nt][2], sc[nt][3]));
        }
        m1 = fmaxf(m1, __shfl_xor_sync(0xffffffffu, m1, 1));
        m1 = fmaxf(m1, __shfl_xor_sync(0xffffffffu, m1, 2));
        m2 = fmaxf(m2, __shfl_xor_sync(0xffffffffu, m2, 1));
        m2 = fmaxf(m2, __shfl_xor_sync(0xffffffffu, m2, 2));
        if ((lane & 3) == 0) {
            red1[wni * 64 + r1] = m1;
            red1[wni * 64 + r2] = m2;
        }
        __syncthreads();
        float mn1 = fmaxf(mo1, fmaxf(red1[r1], red1[64 + r1]));
        float mn2 = fmaxf(mo2, fmaxf(red1[r2], red1[64 + r2]));
        float corr1 = __expf(mo1 - mn1);
        float corr2 = __expf(mo2 - mn2);

        // ---- exp, p hi/lo store, partial sums ----
        float sum1 = 0.f, sum2 = 0.f;
#pragma unroll
        for (int nt = 0; nt < 4; nt++) {
            float p00 = __expf(sc[nt][0] - mn1), p01 = __expf(sc[nt][1] - mn1);
            float p10 = __expf(sc[nt][2] - mn2), p11 = __expf(sc[nt][3] - mn2);
            sum1 += p00 + p01; sum2 += p10 + p11;
            uint32_t hi, lo;
            int chb = (wn >> 3) + nt;
            int within = (lane & 3) * 4;
            split2(p00, p01, hi, lo);
            *(uint32_t*)(sm + 49152 + r1 * 256 + ((chb ^ (r1 & 7)) << 4) + within) = hi;
            *(uint32_t*)(sm + 49152 + r1 * 256 + (((chb + 8) ^ (r1 & 7)) << 4) + within) = lo;
            split2(p10, p11, hi, lo);
            *(uint32_t*)(sm + 49152 + r2 * 256 + ((chb ^ (r2 & 7)) << 4) + within) = hi;
            *(uint32_t*)(sm + 49152 + r2 * 256 + (((chb + 8) ^ (r2 & 7)) << 4) + within) = lo;
        }
        sum1 += __shfl_xor_sync(0xffffffffu, sum1, 1);
        sum1 += __shfl_xor_sync(0xffffffffu, sum1, 2);
        sum2 += __shfl_xor_sync(0xffffffffu, sum2, 1);
        sum2 += __shfl_xor_sync(0xffffffffu, sum2, 2);
        if ((lane & 3) == 0) {
            red2[wni * 64 + r1] = sum1;
            red2[wni * 64 + r2] = sum2;
        }
        __syncthreads();
        ls1 = ls1 * corr1 + red2[r1] + red2[64 + r1];
        ls2 = ls2 * corr2 + red2[r2] + red2[64 + r2];
        mo1 = mn1; mo2 = mn2;
#pragma unroll
        for (int nt = 0; nt < 4; nt++) {
            acc[nt][0] *= corr1; acc[nt][1] *= corr1;
            acc[nt][2] *= corr2; acc[nt][3] *= corr2;
        }

        // ---- PV: acc += ph.vh + ph.vl + pl.vh ----
#pragma unroll
        for (int st = 0; st < 12; st++) {
            int Ah = (st < 8) ? 0 : 8;
            int Bh = ((st >> 2) == 1) ? 8 : 0;
            int ks16 = st & 3;
            uint32_t a[4];
            {
                int row = wm + laneA_row;
                int ch = Ah + ks16 * 2 + laneA_ch;
                LDSM_X4(a[0], a[1], a[2], a[3], PS + row * 256 + ((ch ^ (row & 7)) << 4));
            }
#pragma unroll
            for (int g = 0; g < 2; g++) {
                int vrow = ks16 * 16 + laneV_row;
                int vch = Bh + (wn >> 3) + g * 2 + laneV_g;
                uint32_t v0, v1, v2, v3;
                LDSM_X4T(v0, v1, v2, v3, VS + vrow * 256 + ((vch ^ (vrow & 7)) << 4));
                MMA16816(acc[g*2],   a, v0, v1);
                MMA16816(acc[g*2+1], a, v2, v3);
            }
        }
    }

    // ---- epilogue ----
    if (mid) {
        float inv1 = 1.0f / ls1, inv2 = 1.0f / ls2;
#pragma unroll
        for (int nt = 0; nt < 4; nt++) {
            int col = wn + nt * 8 + (lane & 3) * 2;
            size_t o1 = ((size_t)(b * 4096 + qb * 64 + r1)) * 512 + h * 64 + col;
            size_t o2 = ((size_t)(b * 4096 + qb * 64 + r2)) * 512 + h * 64 + col;
            uint32_t hi, lo;
            split2(acc[nt][0] * inv1, acc[nt][1] * inv1, hi, lo);
            *(uint32_t*)&g_xhi[o1] = hi; *(uint32_t*)&g_xlo[o1] = lo;
            split2(acc[nt][2] * inv2, acc[nt][3] * inv2, hi, lo);
            *(uint32_t*)&g_xhi[o2] = hi; *(uint32_t*)&g_xlo[o2] = lo;
        }
    } else {
        int slot = (bh * 4 + di) * 8 + chunk;
        float* p = g_part + (size_t)slot * SLOT_F;
#pragma unroll
        for (int nt = 0; nt < 4; nt++) {
            int col = wn + nt * 8 + (lane & 3) * 2;
            *(float2*)&p[r1 * 64 + col] = make_float2(acc[nt][0], acc[nt][1]);
            *(float2*)&p[r2 * 64 + col] = make_float2(acc[nt][2], acc[nt][3]);
        }
        if (wni == 0 && (lane & 3) == 0) {
            p[4096 + r1] = mo1; p[4160 + r1] = ls1;
            p[4096 + r2] = mo2; p[4160 + r2] = ls2;
        }
    }
}

// ---------------------------------------------------------------------------
// Combine 8 dense split-K partials -> hi/lo bf16 ctx (into g_xhi/g_xlo)
// ---------------------------------------------------------------------------
__global__ __launch_bounds__(256) void combine_kernel()
{
    int g  = blockIdx.x;
    int bh = g >> 2, di = g & 3;
    int qb = (di < 2) ? di : (60 + di);
    int b  = bh >> 3, h = bh & 7;
    int t   = threadIdx.x;
    int row = t & 63;
    int c0  = (t >> 6) * 16;

    const float* base = g_part + (size_t)(g * 8) * SLOT_F;
    float m[8];
    float M = -INFINITY;
#pragma unroll
    for (int s = 0; s < 8; s++) { m[s] = base[s*SLOT_F + 4096 + row]; M = fmaxf(M, m[s]); }
    float wg[8]; float L = 0.f;
#pragma unroll
    for (int s = 0; s < 8; s++) { wg[s] = __expf(m[s] - M); L += base[s*SLOT_F + 4160 + row] * wg[s]; }
    float inv = 1.0f / L;

    float o[16];
#pragma unroll
    for (int c = 0; c < 16; c++) o[c] = 0.f;
#pragma unroll
    for (int s = 0; s < 8; s++) {
        const float* pa = base + s*SLOT_F + row*64 + c0;
        float ws = wg[s];
#pragma unroll
        for (int c4 = 0; c4 < 4; c4++) {
            float4 v4 = *(const float4*)&pa[c4*4];
            o[c4*4+0] += ws * v4.x; o[c4*4+1] += ws * v4.y;
            o[c4*4+2] += ws * v4.z; o[c4*4+3] += ws * v4.w;
        }
    }
    size_t dst = ((size_t)(b * 4096 + qb * 64 + row)) * 512 + h * 64 + c0;
#pragma unroll
    for (int cp = 0; cp < 8; cp++) {
        uint32_t hi, lo;
        split2(o[cp*2] * inv, o[cp*2+1] * inv, hi, lo);
        *(uint32_t*)&g_xhi[dst + cp*2] = hi;
        *(uint32_t*)&g_xlo[dst + cp*2] = lo;
    }
}

// ---------------------------------------------------------------------------
__global__ __launch_bounds__(256) void ln_kernel(const float* __restrict__ x,
                                                 const float* __restrict__ bo,
                                                 const float* __restrict__ gamma,
                                                 const float* __restrict__ beta,
                                                 float* __restrict__ out)
{
    int row = blockIdx.x;
    int t = threadIdx.x;
    size_t base = (size_t)row * 512;
    float h0 = g_h[base + t]       + bo[t]       + x[base + t];
    float h1 = g_h[base + t + 256] + bo[t + 256] + x[base + t + 256];
    float s = h0 + h1;
    float q = h0*h0 + h1*h1;
#pragma unroll
    for (int m = 16; m >= 1; m >>= 1) {
        s += __shfl_xor_sync(0xffffffffu, s, m);
        q += __shfl_xor_sync(0xffffffffu, q, m);
    }
    __shared__ float ss[8], qq[8];
    int w = t >> 5;
    if ((t & 31) == 0) { ss[w] = s; qq[w] = q; }
    __syncthreads();
    float S2 = 0.f, Q2 = 0.f;
#pragma unroll
    for (int i = 0; i < 8; i++) { S2 += ss[i]; Q2 += qq[i]; }
    float mu  = S2 * (1.0f / 512.0f);
    float var = Q2 * (1.0f / 512.0f) - mu * mu;
    float inv = rsqrtf(var + 1e-12f);
    out[base + t]       = (h0 - mu) * inv * gamma[t]       + beta[t];
    out[base + t + 256] = (h1 - mu) * inv * gamma[t + 256] + beta[t + 256];
}

// ---------------------------------------------------------------------------
extern "C" void kernel_launch(void* const* d_in, const int* in_sizes, int n_in,
                              void* d_out, int out_size)
{
    const float* x     = (const float*)d_in[0];
    const float* mask  = (const float*)d_in[1];
    const int*   rb    = (const int*)  d_in[2];
    const float* Wq    = (const float*)d_in[3];
    const float* Wk    = (const float*)d_in[4];
    const float* Wv    = (const float*)d_in[5];
    const float* Wo    = (const float*)d_in[6];
    const float* bo    = (const float*)d_in[7];
    const float* gamma = (const float*)d_in[8];
    const float* beta  = (const float*)d_in[9];
    float* out = (float*)d_out;

    float* hp;
    __nv_bfloat16 *xh, *xl, *wth, *wtl;
    cudaGetSymbolAddress((void**)&hp, g_h);
    cudaGetSymbolAddress((void**)&xh, g_xhi);
    cudaGetSymbolAddress((void**)&xl, g_xlo);
    cudaGetSymbolAddress((void**)&wth, g_wthi);
    cudaGetSymbolAddress((void**)&wtl, g_wtlo);

    cudaFuncSetAttribute(gemm_hmma, cudaFuncAttributeMaxDynamicSharedMemorySize, GEMM_SMEM);
    cudaFuncSetAttribute(gemm_qkv,  cudaFuncAttributeMaxDynamicSharedMemorySize, GEMM_SMEM);
    cudaFuncSetAttribute(attn_hmma, cudaFuncAttributeMaxDynamicSharedMemorySize, ATT_SMEM);

    dim3 wtg(16, 16), wtb(32, 8);
    conv_x<<<NROWS, 256>>>(x, xh, xl);
    conv_wt<<<wtg, wtb>>>(Wq, wth + 0*262144, wtl + 0*262144);
    conv_wt<<<wtg, wtb>>>(Wk, wth + 1*262144, wtl + 1*262144);
    conv_wt<<<wtg, wtb>>>(Wv, wth + 2*262144, wtl + 2*262144);
    conv_wt<<<wtg, wtb>>>(Wo, wth + 3*262144, wtl + 3*262144);

    dim3 gq(12, 64);                         // 1536/128 x 8192/128
    gemm_qkv<<<gq, 256, GEMM_SMEM>>>(xh, xl, wth, wtl);

    attn_hmma<<<16 * 92, 256, ATT_SMEM>>>(mask, rb);
    combine_kernel<<<64, 256>>>();

    dim3 go(4, 64);
    gemm_hmma<<<go, 256, GEMM_SMEM>>>(xh, xl, wth + 3*262144, wtl + 3*262144, hp, 1.0f);

    ln_kernel<<<Bb * Ss, 256>>>(x, bo, gamma, beta, out);
}

// round 6
// speedup vs baseline: 3.4452x; 1.0777x over previous
#include <cuda_runtime.h>
#include <cuda_bf16.h>
#include <math.h>
#include <stdint.h>

#define Bb 2
#define Ss 4096
#define Dd 512
#define NROWS (Bb*Ss)      // 8192
#define NEGF -1000000000.0f

// ---------------- scratch (device globals: allocation-free) ----------------
__device__ float g_h[NROWS*Dd];
#define SLOT_F 4224
__device__ float g_part[512 * SLOT_F];
__device__ __align__(16) __nv_bfloat16 g_xhi[NROWS*Dd];
__device__ __align__(16) __nv_bfloat16 g_xlo[NROWS*Dd];
__device__ __align__(16) __nv_bfloat16 g_wthi[4*Dd*Dd];   // W^T x4 (qkv 0..1535, Wo 1536..)
__device__ __align__(16) __nv_bfloat16 g_wtlo[4*Dd*Dd];
// per-head q/k/v: [bh][s][128] bf16, cols 0..63 = hi, 64..127 = lo
__device__ __align__(16) __nv_bfloat16 g_qc[16ULL*4096*128];
__device__ __align__(16) __nv_bfloat16 g_kc[16ULL*4096*128];
__device__ __align__(16) __nv_bfloat16 g_vc[16ULL*4096*128];

// ---------------- PTX helpers (base-target legal) ----------------
__device__ __forceinline__ uint32_t smem_u32(const void* p) {
    return (uint32_t)__cvta_generic_to_shared(p);
}
#define CPASYNC16(dst, src) \
    asm volatile("cp.async.cg.shared.global [%0], [%1], 16;" :: "r"(dst), "l"(src))
#define CPCOMMIT() asm volatile("cp.async.commit_group;" ::: "memory")
#define CPWAIT(n)  asm volatile("cp.async.wait_group %0;" :: "n"(n) : "memory")

#define LDSM_X4(r0, r1, r2, r3, a) \
    asm volatile("ldmatrix.sync.aligned.m8n8.x4.shared.b16 {%0,%1,%2,%3}, [%4];" \
                 : "=r"(r0), "=r"(r1), "=r"(r2), "=r"(r3) : "r"(a))
#define LDSM_X4T(r0, r1, r2, r3, a) \
    asm volatile("ldmatrix.sync.aligned.m8n8.x4.trans.shared.b16 {%0,%1,%2,%3}, [%4];" \
                 : "=r"(r0), "=r"(r1), "=r"(r2), "=r"(r3) : "r"(a))

#define MMA16816(D, A, B0, B1) \
    asm volatile("mma.sync.aligned.m16n8k16.row.col.f32.bf16.bf16.f32 " \
                 "{%0,%1,%2,%3},{%4,%5,%6,%7},{%8,%9},{%0,%1,%2,%3};" \
                 : "+f"((D)[0]), "+f"((D)[1]), "+f"((D)[2]), "+f"((D)[3]) \
                 : "r"((A)[0]), "r"((A)[1]), "r"((A)[2]), "r"((A)[3]), \
                   "r"(B0), "r"(B1))

__device__ __forceinline__ void split2(float a, float b, uint32_t& hi, uint32_t& lo) {
    __nv_bfloat16 ha = __float2bfloat16(a), hb = __float2bfloat16(b);
    float ra = a - __bfloat162float(ha), rb = b - __bfloat162float(hb);
    __nv_bfloat162 H; H.x = ha; H.y = hb;
    __nv_bfloat162 L = __floats2bfloat162_rn(ra, rb);
    hi = *(uint32_t*)&H; lo = *(uint32_t*)&L;
}

// ---------------------------------------------------------------------------
// Conversions
// ---------------------------------------------------------------------------
__global__ __launch_bounds__(256) void conv_x(const float* __restrict__ X,
                                              __nv_bfloat16* __restrict__ Hi,
                                              __nv_bfloat16* __restrict__ Lo)
{
    size_t i0 = (size_t)blockIdx.x * 512 + threadIdx.x;
#pragma unroll
    for (int s = 0; s < 2; s++) {
        size_t i = i0 + s * 256;
        float v = X[i];
        __nv_bfloat16 h = __float2bfloat16(v);
        Hi[i] = h;
        Lo[i] = __float2bfloat16(v - __bfloat162float(h));
    }
}

// All four W[512,512] -> W^T bf16 hi/lo in one launch. grid (16,16,4)
__global__ void conv_wt4(const float* __restrict__ W0, const float* __restrict__ W1,
                         const float* __restrict__ W2, const float* __restrict__ W3,
                         __nv_bfloat16* __restrict__ Th, __nv_bfloat16* __restrict__ Tl)
{
    __shared__ float tile[32][33];
    int z = blockIdx.z;
    const float* W = (z == 0) ? W0 : (z == 1) ? W1 : (z == 2) ? W2 : W3;
    __nv_bfloat16* th = Th + (size_t)z * 262144;
    __nv_bfloat16* tl = Tl + (size_t)z * 262144;
    int n0 = blockIdx.x * 32, k0 = blockIdx.y * 32;
    int tx = threadIdx.x, ty = threadIdx.y;
#pragma unroll
    for (int j = 0; j < 32; j += 8)
        tile[ty + j][tx] = W[(size_t)(k0 + ty + j) * 512 + n0 + tx];
    __syncthreads();
#pragma unroll
    for (int j = 0; j < 32; j += 8) {
        int row = ty + j;
        float v = tile[tx][row];
        __nv_bfloat16 h = __float2bfloat16(v);
        size_t o = (size_t)(n0 + row) * 512 + k0 + tx;
        th[o] = h;
        tl[o] = __float2bfloat16(v - __bfloat162float(h));
    }
}

// ---------------------------------------------------------------------------
// Shared GEMM mainloop (CTA 128x128, BK=64, cp.async double buffer)
// ---------------------------------------------------------------------------
#define GEMM_SMEM 65536

__device__ __forceinline__ void gemm_ld_chunk(const __nv_bfloat16* __restrict__ A,
                                              const __nv_bfloat16* __restrict__ Bt,
                                              int rowBase, int colBase, int k0,
                                              uint32_t Ab, uint32_t Bbuf, int t)
{
#pragma unroll
    for (int it = 0; it < 4; it++) {
        int idx = it * 256 + t;
        int r = idx >> 3, c = idx & 7;
        uint32_t d = Ab + r * 128 + ((c ^ (r & 7)) << 4);
        CPASYNC16(d, &A[(size_t)(rowBase + r) * 512 + k0 + c * 8]);
    }
#pragma unroll
    for (int it = 0; it < 4; it++) {
        int idx = it * 256 + t;
        int r = idx >> 3, c = idx & 7;
        uint32_t d = Bbuf + r * 128 + ((c ^ (r & 7)) << 4);
        CPASYNC16(d, &Bt[(size_t)(colBase + r) * 512 + k0 + c * 8]);
    }
    CPCOMMIT();
}

__device__ __forceinline__ void gemm_mainloop(const __nv_bfloat16* Ahi, const __nv_bfloat16* Alo,
                                              const __nv_bfloat16* Bhi, const __nv_bfloat16* Blo,
                                              int rowBase, int colBase, uint32_t sbase, int t,
                                              float acc[2][8][4])
{
    int w = t >> 5, lane = t & 31;
    int wm = (w & 3) * 32, wn = (w >> 2) * 64;
    int laneA_row = (((lane >> 3) & 1) << 3) + (lane & 7);
    int laneA_ch  = (lane >> 4);
    int laneB_row = ((lane >> 4) << 3) + (lane & 7);
    int laneB_ch  = ((lane >> 3) & 1);

    gemm_ld_chunk(Ahi, Bhi, rowBase, colBase, 0, sbase, sbase + 16384u, t);

    for (int i = 0; i < 24; i++) {
        int buf = i & 1;
        if (i < 23) {
            int j = i + 1, seg = j >> 3, k0 = (j & 7) * 64;
            const __nv_bfloat16* As = (seg < 2)  ? Ahi : Alo;
            const __nv_bfloat16* Bs = (seg == 1) ? Blo : Bhi;
            uint32_t Ab = sbase + (buf ? 0u : 32768u);
            gemm_ld_chunk(As, Bs, rowBase, colBase, k0, Ab, Ab + 16384u, t);
            CPWAIT(1);
        } else {
            CPWAIT(0);
        }
        __syncthreads();

        uint32_t Ab = sbase + (buf ? 32768u : 0u);
        uint32_t Bbuf = Ab + 16384u;
#pragma unroll
        for (int ks = 0; ks < 4; ks++) {
            uint32_t afr[2][4];
#pragma unroll
            for (int mt = 0; mt < 2; mt++) {
                int row = wm + mt * 16 + laneA_row;
                int ch  = ks * 2 + laneA_ch;
                uint32_t a = Ab + row * 128 + ((ch ^ (row & 7)) << 4);
                LDSM_X4(afr[mt][0], afr[mt][1], afr[mt][2], afr[mt][3], a);
            }
#pragma unroll
            for (int p = 0; p < 4; p++) {
                int row = wn + p * 16 + laneB_row;
                int ch  = ks * 2 + laneB_ch;
                uint32_t a = Bbuf + row * 128 + ((ch ^ (row & 7)) << 4);
                uint32_t b0, b1, b2, b3;
                LDSM_X4(b0, b1, b2, b3, a);
#pragma unroll
                for (int mt = 0; mt < 2; mt++) {
                    MMA16816(acc[mt][p*2],   afr[mt], b0, b1);
                    MMA16816(acc[mt][p*2+1], afr[mt], b2, b3);
                }
            }
        }
        __syncthreads();
    }
}

// Generic GEMM: Y fp32, stride 512
__global__ __launch_bounds__(256, 2)
void gemm_hmma(const __nv_bfloat16* __restrict__ Ahi,
               const __nv_bfloat16* __restrict__ Alo,
               const __nv_bfloat16* __restrict__ Bhi,
               const __nv_bfloat16* __restrict__ Blo,
               float* __restrict__ Y, float alpha)
{
    extern __shared__ __align__(128) char sm[];
    uint32_t sbase = smem_u32(sm);
    int t = threadIdx.x, w = t >> 5, lane = t & 31;
    int rowBase = blockIdx.y * 128, colBase = blockIdx.x * 128;
    int wm = (w & 3) * 32, wn = (w >> 2) * 64;

    float acc[2][8][4];
#pragma unroll
    for (int mt = 0; mt < 2; mt++)
#pragma unroll
        for (int nt = 0; nt < 8; nt++)
#pragma unroll
            for (int e = 0; e < 4; e++) acc[mt][nt][e] = 0.f;

    gemm_mainloop(Ahi, Alo, Bhi, Blo, rowBase, colBase, sbase, t, acc);

#pragma unroll
    for (int mt = 0; mt < 2; mt++)
#pragma unroll
        for (int nt = 0; nt < 8; nt++) {
            float* a4 = acc[mt][nt];
            int r0 = rowBase + wm + mt * 16 + (lane >> 2);
            int c0 = colBase + wn + nt * 8 + (lane & 3) * 2;
            *(float2*)&Y[(size_t)r0 * 512 + c0] = make_float2(a4[0]*alpha, a4[1]*alpha);
            *(float2*)&Y[(size_t)(r0+8) * 512 + c0] = make_float2(a4[2]*alpha, a4[3]*alpha);
        }
}

// QKV GEMM: B rows span 1536 (Wq|Wk|Wv ^T). Epilogue -> per-head hi/lo bf16.
__global__ __launch_bounds__(256, 2)
void gemm_qkv(const __nv_bfloat16* __restrict__ Ahi,
              const __nv_bfloat16* __restrict__ Alo,
              const __nv_bfloat16* __restrict__ Bhi,
              const __nv_bfloat16* __restrict__ Blo)
{
    extern __shared__ __align__(128) char sm[];
    uint32_t sbase = smem_u32(sm);
    int t = threadIdx.x, w = t >> 5, lane = t & 31;
    int rowBase = blockIdx.y * 128, colBase = blockIdx.x * 128;
    int wm = (w & 3) * 32, wn = (w >> 2) * 64;

    float acc[2][8][4];
#pragma unroll
    for (int mt = 0; mt < 2; mt++)
#pragma unroll
        for (int nt = 0; nt < 8; nt++)
#pragma unroll
            for (int e = 0; e < 4; e++) acc[mt][nt][e] = 0.f;

    gemm_mainloop(Ahi, Alo, Bhi, Blo, rowBase, colBase, sbase, t, acc);

    int tensor = colBase >> 9;
    float alpha = (tensor == 0) ? 0.125f : 1.0f;
    __nv_bfloat16* dst = (tensor == 0) ? g_qc : (tensor == 1) ? g_kc : g_vc;

#pragma unroll
    for (int mt = 0; mt < 2; mt++)
#pragma unroll
        for (int nt = 0; nt < 8; nt++) {
            float* a4 = acc[mt][nt];
            int r0 = rowBase + wm + mt * 16 + (lane >> 2);
            int cc = (colBase & 511) + wn + nt * 8 + (lane & 3) * 2;
            int hh = cc >> 6, dd = cc & 63;
            int b = r0 >> 12, s = r0 & 4095;
            size_t off = ((size_t)((b << 3) + hh) * 4096 + s) * 128 + dd;
            uint32_t hi, lo;
            split2(a4[0]*alpha, a4[1]*alpha, hi, lo);
            *(uint32_t*)&dst[off] = hi;
            *(uint32_t*)&dst[off + 64] = lo;
            size_t off2 = off + 8ULL * 128;
            split2(a4[2]*alpha, a4[3]*alpha, hi, lo);
            *(uint32_t*)&dst[off2] = hi;
            *(uint32_t*)&dst[off2 + 64] = lo;
        }
}

// ---------------------------------------------------------------------------
// HMMA attention, cp.async double-buffered K/V prefetch.
// smem: QS 16K | KS0 16K | KS1 16K | VS0 16K | VS1 16K | PS 16K | km 512 |
//       red1 512 | redL 512
// ---------------------------------------------------------------------------
#define OFF_KS 16384
#define OFF_VS 49152
#define OFF_PS 81920
#define OFF_KM 98304
#define OFF_R1 98816
#define OFF_RL 99328
#define ATT_SMEM 99840

__device__ __forceinline__ int kb_of(bool mid, int qb, int chunk, int itk,
                                     const int* __restrict__ rand_blocks)
{
    if (!mid) return chunk * 8 + itk;
    if (itk < 3) return qb - 1 + itk;
    if (itk == 3) return 0;
    if (itk == 4) return 63;
    return rand_blocks[(qb - 2) * 3 + (itk - 5)];
}

__device__ __forceinline__ void attn_prefetch_kv(int bh, int kb, uint32_t KSb,
                                                 uint32_t VSb, int t)
{
    size_t koff = ((size_t)bh * 4096 + kb * 64) * 128;
#pragma unroll
    for (int it = 0; it < 4; it++) {
        int idx = it * 256 + t;
        int r = idx >> 4, c = idx & 15;
        CPASYNC16(KSb + r * 256 + ((c ^ (r & 7)) << 4), &g_kc[koff + r * 128 + c * 8]);
    }
#pragma unroll
    for (int it = 0; it < 4; it++) {
        int idx = it * 256 + t;
        int r = idx >> 4, c = idx & 15;
        CPASYNC16(VSb + r * 256 + ((c ^ (r & 7)) << 4), &g_vc[koff + r * 128 + c * 8]);
    }
    CPCOMMIT();
}

__global__ __launch_bounds__(256, 2)
void attn_hmma(const float* __restrict__ mask, const int* __restrict__ rand_blocks)
{
    extern __shared__ __align__(128) char sm[];
    uint32_t sb = smem_u32(sm);
    const uint32_t QS = sb, PS = sb + OFF_PS;
    float* km   = (float*)(sm + OFF_KM);    // [2][64]
    float* red1 = (float*)(sm + OFF_R1);
    float* redL = (float*)(sm + OFF_RL);

    int t = threadIdx.x, w = t >> 5, lane = t & 31;
    int wm = (w & 3) * 16, wn = (w >> 2) * 32;
    int wni = w >> 2;

    int u  = blockIdx.x % 92;
    int bh = blockIdx.x / 92;
    int b  = bh >> 3, h = bh & 7;

    bool mid = (u < 60);
    int qb, chunk = 0, di = 0;
    if (mid) { qb = u + 2; }
    else {
        int d = u - 60;
        di = d >> 3; chunk = d & 7;
        qb = (di < 2) ? di : (60 + di);
    }

    // ---- prologue: Q + K0/V0 via cp.async (one group), km[0], row masks ----
    {
        size_t qoff = ((size_t)bh * 4096 + qb * 64) * 128;
#pragma unroll
        for (int it = 0; it < 4; it++) {
            int idx = it * 256 + t;
            int r = idx >> 4, c = idx & 15;
            CPASYNC16(QS + r * 256 + ((c ^ (r & 7)) << 4), &g_qc[qoff + r * 128 + c * 8]);
        }
        int kb0 = kb_of(mid, qb, chunk, 0, rand_blocks);
        attn_prefetch_kv(bh, kb0, sb + OFF_KS, sb + OFF_VS, t);  // commits Q+K0+V0
        if (t < 64) km[t] = mask[b * 4096 + kb0 * 64 + t];
    }

    int r1 = wm + (lane >> 2), r2 = r1 + 8;
    float mq1 = mask[b * 4096 + qb * 64 + r1];
    float mq2 = mask[b * 4096 + qb * 64 + r2];

    float acc[4][4];
#pragma unroll
    for (int nt = 0; nt < 4; nt++)
#pragma unroll
        for (int e = 0; e < 4; e++) acc[nt][e] = 0.f;
    float mo1 = -INFINITY, mo2 = -INFINITY, ls1 = 0.f, ls2 = 0.f;

    int laneA_row = (((lane >> 3) & 1) << 3) + (lane & 7);
    int laneA_ch  = lane >> 4;
    int laneB_row = ((lane >> 4) << 3) + (lane & 7);
    int laneB_ch  = (lane >> 3) & 1;
    int laneV_row = lane & 15;
    int laneV_g   = lane >> 4;

    for (int itk = 0; itk < 8; itk++) {
        int buf = itk & 1;
        bool band = mid && (itk < 3);

        __syncthreads();   // release buf^1 (prev-prev iter's tiles fully consumed)
        if (itk < 7) {
            int kbn = kb_of(mid, qb, chunk, itk + 1, rand_blocks);
            attn_prefetch_kv(bh, kbn, sb + OFF_KS + (buf ^ 1) * 16384,
                             sb + OFF_VS + (buf ^ 1) * 16384, t);
            if (t < 64) km[(buf ^ 1) * 64 + t] = mask[b * 4096 + kbn * 64 + t];
            CPWAIT(1);
        } else {
            CPWAIT(0);
        }
        __syncthreads();   // current buf data visible to all

        uint32_t KSb = sb + OFF_KS + buf * 16384;
        uint32_t VSb = sb + OFF_VS + buf * 16384;
        const float* kmask_s = km + buf * 64;

        // ---- QK: s = qh.kh + qh.kl + ql.kh (12 k16 steps) ----
        float sc[4][4];
#pragma unroll
        for (int nt = 0; nt < 4; nt++)
#pragma unroll
            for (int e = 0; e < 4; e++) sc[nt][e] = 0.f;

#pragma unroll
        for (int st = 0; st < 12; st++) {
            int Ah = (st < 8) ? 0 : 8;
            int Bh = ((st >> 2) == 1) ? 8 : 0;
            int kc2 = (st & 3) * 2;
            uint32_t a[4];
            {
                int row = wm + laneA_row;
                int ch = Ah + kc2 + laneA_ch;
                LDSM_X4(a[0], a[1], a[2], a[3], QS + row * 256 + ((ch ^ (row & 7)) << 4));
            }
#pragma unroll
            for (int g = 0; g < 2; g++) {
                int row = wn + g * 16 + laneB_row;
                int ch = Bh + kc2 + laneB_ch;
                uint32_t b0, b1, b2, b3;
                LDSM_X4(b0, b1, b2, b3, KSb + row * 256 + ((ch ^ (row & 7)) << 4));
                MMA16816(sc[g*2],   a, b0, b1);
                MMA16816(sc[g*2+1], a, b2, b3);
            }
        }

        // ---- mask ----
#pragma unroll
        for (int nt = 0; nt < 4; nt++) {
            int col = wn + nt * 8 + (lane & 3) * 2;
            float mk0 = kmask_s[col], mk1 = kmask_s[col + 1];
            float m00 = band ? mk0 * mq1 : mk0;
            float m01 = band ? mk1 * mq1 : mk1;
            float m10 = band ? mk0 * mq2 : mk0;
            float m11 = band ? mk1 * mq2 : mk1;
            sc[nt][0] += (1.0f - m00) * NEGF;
            sc[nt][1] += (1.0f - m01) * NEGF;
            sc[nt][2] += (1.0f - m10) * NEGF;
            sc[nt][3] += (1.0f - m11) * NEGF;
        }

        // ---- row max (in-warp 32 cols, then cross-half via smem) ----
        float m1 = -INFINITY, m2 = -INFINITY;
#pragma unroll
        for (int nt = 0; nt < 4; nt++) {
            m1 = fmaxf(m1, fmaxf(sc[nt][0], sc[nt][1]));
            m2 = fmaxf(m2, fmaxf(sc[nt][2], sc[nt][3]));
        }
        m1 = fmaxf(m1, __shfl_xor_sync(0xffffffffu, m1, 1));
        m1 = fmaxf(m1, __shfl_xor_sync(0xffffffffu, m1, 2));
        m2 = fmaxf(m2, __shfl_xor_sync(0xffffffffu, m2, 1));
        m2 = fmaxf(m2, __shfl_xor_sync(0xffffffffu, m2, 2));
        if ((lane & 3) == 0) {
            red1[wni * 64 + r1] = m1;
            red1[wni * 64 + r2] = m2;
        }
        __syncthreads();
        float mn1 = fmaxf(mo1, fmaxf(red1[r1], red1[64 + r1]));
        float mn2 = fmaxf(mo2, fmaxf(red1[r2], red1[64 + r2]));
        float corr1 = __expf(mo1 - mn1);
        float corr2 = __expf(mo2 - mn2);

        // ---- exp, p hi/lo store, quad-local partial sums (no per-iter combine) ----
        float sum1 = 0.f, sum2 = 0.f;
#pragma unroll
        for (int nt = 0; nt < 4; nt++) {
            float p00 = __expf(sc[nt][0] - mn1), p01 = __expf(sc[nt][1] - mn1);
            float p10 = __expf(sc[nt][2] - mn2), p11 = __expf(sc[nt][3] - mn2);
            sum1 += p00 + p01; sum2 += p10 + p11;
            uint32_t hi, lo;
            int chb = (wn >> 3) + nt;
            int within = (lane & 3) * 4;
            split2(p00, p01, hi, lo);
            *(uint32_t*)(sm + OFF_PS + r1 * 256 + ((chb ^ (r1 & 7)) << 4) + within) = hi;
            *(uint32_t*)(sm + OFF_PS + r1 * 256 + (((chb + 8) ^ (r1 & 7)) << 4) + within) = lo;
            split2(p10, p11, hi, lo);
            *(uint32_t*)(sm + OFF_PS + r2 * 256 + ((chb ^ (r2 & 7)) << 4) + within) = hi;
            *(uint32_t*)(sm + OFF_PS + r2 * 256 + (((chb + 8) ^ (r2 & 7)) << 4) + within) = lo;
        }
        ls1 = ls1 * corr1 + sum1;
        ls2 = ls2 * corr2 + sum2;
        mo1 = mn1; mo2 = mn2;
#pragma unroll
        for (int nt = 0; nt < 4; nt++) {
            acc[nt][0] *= corr1; acc[nt][1] *= corr1;
            acc[nt][2] *= corr2; acc[nt][3] *= corr2;
        }
        __syncthreads();   // PS visible before PV ldsm

        // ---- PV: acc += ph.vh + ph.vl + pl.vh ----
#pragma unroll
        for (int st = 0; st < 12; st++) {
            int Ah = (st < 8) ? 0 : 8;
            int Bh = ((st >> 2) == 1) ? 8 : 0;
            int ks16 = st & 3;
            uint32_t a[4];
            {
                int row = wm + laneA_row;
                int ch = Ah + ks16 * 2 + laneA_ch;
                LDSM_X4(a[0], a[1], a[2], a[3], PS + row * 256 + ((ch ^ (row & 7)) << 4));
            }
#pragma unroll
            for (int g = 0; g < 2; g++) {
                int vrow = ks16 * 16 + laneV_row;
                int vch = Bh + (wn >> 3) + g * 2 + laneV_g;
                uint32_t v0, v1, v2, v3;
                LDSM_X4T(v0, v1, v2, v3, VSb + vrow * 256 + ((vch ^ (vrow & 7)) << 4));
                MMA16816(acc[g*2],   a, v0, v1);
                MMA16816(acc[g*2+1], a, v2, v3);
            }
        }
    }

    // ---- final ls combine (once): quad shfl + cross-half smem ----
    ls1 += __shfl_xor_sync(0xffffffffu, ls1, 1);
    ls1 += __shfl_xor_sync(0xffffffffu, ls1, 2);
    ls2 += __shfl_xor_sync(0xffffffffu, ls2, 1);
    ls2 += __shfl_xor_sync(0xffffffffu, ls2, 2);
    if ((lane & 3) == 0) {
        redL[wni * 64 + r1] = ls1;
        redL[wni * 64 + r2] = ls2;
    }
    __syncthreads();
    ls1 = redL[r1] + redL[64 + r1];
    ls2 = redL[r2] + redL[64 + r2];

    // ---- epilogue ----
    if (mid) {
        float inv1 = 1.0f / ls1, inv2 = 1.0f / ls2;
#pragma unroll
        for (int nt = 0; nt < 4; nt++) {
            int col = wn + nt * 8 + (lane & 3) * 2;
            size_t o1 = ((size_t)(b * 4096 + qb * 64 + r1)) * 512 + h * 64 + col;
            size_t o2 = ((size_t)(b * 4096 + qb * 64 + r2)) * 512 + h * 64 + col;
            uint32_t hi, lo;
            split2(acc[nt][0] * inv1, acc[nt][1] * inv1, hi, lo);
            *(uint32_t*)&g_xhi[o1] = hi; *(uint32_t*)&g_xlo[o1] = lo;
            split2(acc[nt][2] * inv2, acc[nt][3] * inv2, hi, lo);
            *(uint32_t*)&g_xhi[o2] = hi; *(uint32_t*)&g_xlo[o2] = lo;
        }
    } else {
        int slot = (bh * 4 + di) * 8 + chunk;
        float* p = g_part + (size_t)slot * SLOT_F;
#pragma unroll
        for (int nt = 0; nt < 4; nt++) {
            int col = wn + nt * 8 + (lane & 3) * 2;
            *(float2*)&p[r1 * 64 + col] = make_float2(acc[nt][0], acc[nt][1]);
            *(float2*)&p[r2 * 64 + col] = make_float2(acc[nt][2], acc[nt][3]);
        }
        if (wni == 0 && (lane & 3) == 0) {
            p[4096 + r1] = mo1; p[4160 + r1] = ls1;
            p[4096 + r2] = mo2; p[4160 + r2] = ls2;
        }
    }
}

// ---------------------------------------------------------------------------
// Combine 8 dense split-K partials -> hi/lo bf16 ctx
// ---------------------------------------------------------------------------
__global__ __launch_bounds__(256) void combine_kernel()
{
    int g  = blockIdx.x;
    int bh = g >> 2, di = g & 3;
    int qb = (di < 2) ? di : (60 + di);
    int b  = bh >> 3, h = bh & 7;
    int t   = threadIdx.x;
    int row = t & 63;
    int c0  = (t >> 6) * 16;

    const float* base = g_part + (size_t)(g * 8) * SLOT_F;
    float m[8];
    float M = -INFINITY;
#pragma unroll
    for (int s = 0; s < 8; s++) { m[s] = base[s*SLOT_F + 4096 + row]; M = fmaxf(M, m[s]); }
    float wg[8]; float L = 0.f;
#pragma unroll
    for (int s = 0; s < 8; s++) { wg[s] = __expf(m[s] - M); L += base[s*SLOT_F + 4160 + row] * wg[s]; }
    float inv = 1.0f / L;

    float o[16];
#pragma unroll
    for (int c = 0; c < 16; c++) o[c] = 0.f;
#pragma unroll
    for (int s = 0; s < 8; s++) {
        const float* pa = base + s*SLOT_F + row*64 + c0;
        float ws = wg[s];
#pragma unroll
        for (int c4 = 0; c4 < 4; c4++) {
            float4 v4 = *(const float4*)&pa[c4*4];
            o[c4*4+0] += ws * v4.x; o[c4*4+1] += ws * v4.y;
            o[c4*4+2] += ws * v4.z; o[c4*4+3] += ws * v4.w;
        }
    }
    size_t dst = ((size_t)(b * 4096 + qb * 64 + row)) * 512 + h * 64 + c0;
#pragma unroll
    for (int cp = 0; cp < 8; cp++) {
        uint32_t hi, lo;
        split2(o[cp*2] * inv, o[cp*2+1] * inv, hi, lo);
        *(uint32_t*)&g_xhi[dst + cp*2] = hi;
        *(uint32_t*)&g_xlo[dst + cp*2] = lo;
    }
}

// ---------------------------------------------------------------------------
__global__ __launch_bounds__(256) void ln_kernel(const float* __restrict__ x,
                                                 const float* __restrict__ bo,
                                                 const float* __restrict__ gamma,
                                                 const float* __restrict__ beta,
                                                 float* __restrict__ out)
{
    int row = blockIdx.x;
    int t = threadIdx.x;
    size_t base = (size_t)row * 512;
    float h0 = g_h[base + t]       + bo[t]       + x[base + t];
    float h1 = g_h[base + t + 256] + bo[t + 256] + x[base + t + 256];
    float s = h0 + h1;
    float q = h0*h0 + h1*h1;
#pragma unroll
    for (int m = 16; m >= 1; m >>= 1) {
        s += __shfl_xor_sync(0xffffffffu, s, m);
        q += __shfl_xor_sync(0xffffffffu, q, m);
    }
    __shared__ float ss[8], qq[8];
    int w = t >> 5;
    if ((t & 31) == 0) { ss[w] = s; qq[w] = q; }
    __syncthreads();
    float S2 = 0.f, Q2 = 0.f;
#pragma unroll
    for (int i = 0; i < 8; i++) { S2 += ss[i]; Q2 += qq[i]; }
    float mu  = S2 * (1.0f / 512.0f);
    float var = Q2 * (1.0f / 512.0f) - mu * mu;
    float inv = rsqrtf(var + 1e-12f);
    out[base + t]       = (h0 - mu) * inv * gamma[t]       + beta[t];
    out[base + t + 256] = (h1 - mu) * inv * gamma[t + 256] + beta[t + 256];
}

// ---------------------------------------------------------------------------
extern "C" void kernel_launch(void* const* d_in, const int* in_sizes, int n_in,
                              void* d_out, int out_size)
{
    const float* x     = (const float*)d_in[0];
    const float* mask  = (const float*)d_in[1];
    const int*   rb    = (const int*)  d_in[2];
    const float* Wq    = (const float*)d_in[3];
    const float* Wk    = (const float*)d_in[4];
    const float* Wv    = (const float*)d_in[5];
    const float* Wo    = (const float*)d_in[6];
    const float* bo    = (const float*)d_in[7];
    const float* gamma = (const float*)d_in[8];
    const float* beta  = (const float*)d_in[9];
    float* out = (float*)d_out;

    float* hp;
    __nv_bfloat16 *xh, *xl, *wth, *wtl;
    cudaGetSymbolAddress((void**)&hp, g_h);
    cudaGetSymbolAddress((void**)&xh, g_xhi);
    cudaGetSymbolAddress((void**)&xl, g_xlo);
    cudaGetSymbolAddress((void**)&wth, g_wthi);
    cudaGetSymbolAddress((void**)&wtl, g_wtlo);

    cudaFuncSetAttribute(gemm_hmma, cudaFuncAttributeMaxDynamicSharedMemorySize, GEMM_SMEM);
    cudaFuncSetAttribute(gemm_qkv,  cudaFuncAttributeMaxDynamicSharedMemorySize, GEMM_SMEM);
    cudaFuncSetAttribute(attn_hmma, cudaFuncAttributeMaxDynamicSharedMemorySize, ATT_SMEM);

    conv_x<<<NROWS, 256>>>(x, xh, xl);
    dim3 wtg(16, 16, 4), wtb(32, 8);
    conv_wt4<<<wtg, wtb>>>(Wq, Wk, Wv, Wo, wth, wtl);

    dim3 gq(12, 64);                         // 1536/128 x 8192/128
    gemm_qkv<<<gq, 256, GEMM_SMEM>>>(xh, xl, wth, wtl);

    attn_hmma<<<16 * 92, 256, ATT_SMEM>>>(mask, rb);
    combine_kernel<<<64, 256>>>();

    dim3 go(4, 64);
    gemm_hmma<<<go, 256, GEMM_SMEM>>>(xh, xl, wth + 3*262144, wtl + 3*262144, hp, 1.0f);

    ln_kernel<<<Bb * Ss, 256>>>(x, bo, gamma, beta, out);
}

// round 7
// speedup vs baseline: 3.5481x; 1.0299x over previous
#include <cuda_runtime.h>
#include <cuda_bf16.h>
#include <math.h>
#include <stdint.h>

#define Bb 2
#define Ss 4096
#define Dd 512
#define NROWS (Bb*Ss)      // 8192
#define NEGF -1000000000.0f

// ---------------- scratch (device globals: allocation-free) ----------------
__device__ float g_h[NROWS*Dd];
#define SLOT_F 4224
__device__ float g_part[512 * SLOT_F];
__device__ __align__(16) __nv_bfloat16 g_xhi[NROWS*Dd];
__device__ __align__(16) __nv_bfloat16 g_xlo[NROWS*Dd];
__device__ __align__(16) __nv_bfloat16 g_wthi[4*Dd*Dd];   // W^T x4 (qkv 0..1535, Wo 1536..)
__device__ __align__(16) __nv_bfloat16 g_wtlo[4*Dd*Dd];
// per-head q/k/v: [bh][s][128] bf16, cols 0..63 = hi, 64..127 = lo
__device__ __align__(16) __nv_bfloat16 g_qc[16ULL*4096*128];
__device__ __align__(16) __nv_bfloat16 g_kc[16ULL*4096*128];
__device__ __align__(16) __nv_bfloat16 g_vc[16ULL*4096*128];

// ---------------- PTX helpers (base-target legal) ----------------
__device__ __forceinline__ uint32_t smem_u32(const void* p) {
    return (uint32_t)__cvta_generic_to_shared(p);
}
#define CPASYNC16(dst, src) \
    asm volatile("cp.async.cg.shared.global [%0], [%1], 16;" :: "r"(dst), "l"(src))
#define CPCOMMIT() asm volatile("cp.async.commit_group;" ::: "memory")
#define CPWAIT(n)  asm volatile("cp.async.wait_group %0;" :: "n"(n) : "memory")

#define LDSM_X4(r0, r1, r2, r3, a) \
    asm volatile("ldmatrix.sync.aligned.m8n8.x4.shared.b16 {%0,%1,%2,%3}, [%4];" \
                 : "=r"(r0), "=r"(r1), "=r"(r2), "=r"(r3) : "r"(a))
#define LDSM_X4T(r0, r1, r2, r3, a) \
    asm volatile("ldmatrix.sync.aligned.m8n8.x4.trans.shared.b16 {%0,%1,%2,%3}, [%4];" \
                 : "=r"(r0), "=r"(r1), "=r"(r2), "=r"(r3) : "r"(a))

#define MMA16816(D, A, B0, B1) \
    asm volatile("mma.sync.aligned.m16n8k16.row.col.f32.bf16.bf16.f32 " \
                 "{%0,%1,%2,%3},{%4,%5,%6,%7},{%8,%9},{%0,%1,%2,%3};" \
                 : "+f"((D)[0]), "+f"((D)[1]), "+f"((D)[2]), "+f"((D)[3]) \
                 : "r"((A)[0]), "r"((A)[1]), "r"((A)[2]), "r"((A)[3]), \
                   "r"(B0), "r"(B1))

__device__ __forceinline__ void split2(float a, float b, uint32_t& hi, uint32_t& lo) {
    __nv_bfloat16 ha = __float2bfloat16(a), hb = __float2bfloat16(b);
    float ra = a - __bfloat162float(ha), rb = b - __bfloat162float(hb);
    __nv_bfloat162 H; H.x = ha; H.y = hb;
    __nv_bfloat162 L = __floats2bfloat162_rn(ra, rb);
    hi = *(uint32_t*)&H; lo = *(uint32_t*)&L;
}

// ---------------------------------------------------------------------------
// Conversions
// ---------------------------------------------------------------------------
__global__ __launch_bounds__(256) void conv_x(const float* __restrict__ X,
                                              __nv_bfloat16* __restrict__ Hi,
                                              __nv_bfloat16* __restrict__ Lo)
{
    size_t i0 = (size_t)blockIdx.x * 512 + threadIdx.x;
#pragma unroll
    for (int s = 0; s < 2; s++) {
        size_t i = i0 + s * 256;
        float v = X[i];
        __nv_bfloat16 h = __float2bfloat16(v);
        Hi[i] = h;
        Lo[i] = __float2bfloat16(v - __bfloat162float(h));
    }
}

// All four W[512,512] -> W^T bf16 hi/lo in one launch. grid (16,16,4)
__global__ void conv_wt4(const float* __restrict__ W0, const float* __restrict__ W1,
                         const float* __restrict__ W2, const float* __restrict__ W3,
                         __nv_bfloat16* __restrict__ Th, __nv_bfloat16* __restrict__ Tl)
{
    __shared__ float tile[32][33];
    int z = blockIdx.z;
    const float* W = (z == 0) ? W0 : (z == 1) ? W1 : (z == 2) ? W2 : W3;
    __nv_bfloat16* th = Th + (size_t)z * 262144;
    __nv_bfloat16* tl = Tl + (size_t)z * 262144;
    int n0 = blockIdx.x * 32, k0 = blockIdx.y * 32;
    int tx = threadIdx.x, ty = threadIdx.y;
#pragma unroll
    for (int j = 0; j < 32; j += 8)
        tile[ty + j][tx] = W[(size_t)(k0 + ty + j) * 512 + n0 + tx];
    __syncthreads();
#pragma unroll
    for (int j = 0; j < 32; j += 8) {
        int row = ty + j;
        float v = tile[tx][row];
        __nv_bfloat16 h = __float2bfloat16(v);
        size_t o = (size_t)(n0 + row) * 512 + k0 + tx;
        th[o] = h;
        tl[o] = __float2bfloat16(v - __bfloat162float(h));
    }
}

// ---------------------------------------------------------------------------
// Shared GEMM mainloop (CTA 128x128, BK=64, cp.async double buffer)
// ---------------------------------------------------------------------------
#define GEMM_SMEM 65536

__device__ __forceinline__ void gemm_ld_chunk(const __nv_bfloat16* __restrict__ A,
                                              const __nv_bfloat16* __restrict__ Bt,
                                              int rowBase, int colBase, int k0,
                                              uint32_t Ab, uint32_t Bbuf, int t)
{
#pragma unroll
    for (int it = 0; it < 4; it++) {
        int idx = it * 256 + t;
        int r = idx >> 3, c = idx & 7;
        uint32_t d = Ab + r * 128 + ((c ^ (r & 7)) << 4);
        CPASYNC16(d, &A[(size_t)(rowBase + r) * 512 + k0 + c * 8]);
    }
#pragma unroll
    for (int it = 0; it < 4; it++) {
        int idx = it * 256 + t;
        int r = idx >> 3, c = idx & 7;
        uint32_t d = Bbuf + r * 128 + ((c ^ (r & 7)) << 4);
        CPASYNC16(d, &Bt[(size_t)(colBase + r) * 512 + k0 + c * 8]);
    }
    CPCOMMIT();
}

__device__ __forceinline__ void gemm_mainloop(const __nv_bfloat16* Ahi, const __nv_bfloat16* Alo,
                                              const __nv_bfloat16* Bhi, const __nv_bfloat16* Blo,
                                              int rowBase, int colBase, uint32_t sbase, int t,
                                              float acc[2][8][4])
{
    int w = t >> 5, lane = t & 31;
    int wm = (w & 3) * 32, wn = (w >> 2) * 64;
    int laneA_row = (((lane >> 3) & 1) << 3) + (lane & 7);
    int laneA_ch  = (lane >> 4);
    int laneB_row = ((lane >> 4) << 3) + (lane & 7);
    int laneB_ch  = ((lane >> 3) & 1);

    gemm_ld_chunk(Ahi, Bhi, rowBase, colBase, 0, sbase, sbase + 16384u, t);

    for (int i = 0; i < 24; i++) {
        int buf = i & 1;
        if (i < 23) {
            int j = i + 1, seg = j >> 3, k0 = (j & 7) * 64;
            const __nv_bfloat16* As = (seg < 2)  ? Ahi : Alo;
            const __nv_bfloat16* Bs = (seg == 1) ? Blo : Bhi;
            uint32_t Ab = sbase + (buf ? 0u : 32768u);
            gemm_ld_chunk(As, Bs, rowBase, colBase, k0, Ab, Ab + 16384u, t);
            CPWAIT(1);
        } else {
            CPWAIT(0);
        }
        __syncthreads();

        uint32_t Ab = sbase + (buf ? 32768u : 0u);
        uint32_t Bbuf = Ab + 16384u;
#pragma unroll
        for (int ks = 0; ks < 4; ks++) {
            uint32_t afr[2][4];
#pragma unroll
            for (int mt = 0; mt < 2; mt++) {
                int row = wm + mt * 16 + laneA_row;
                int ch  = ks * 2 + laneA_ch;
                uint32_t a = Ab + row * 128 + ((ch ^ (row & 7)) << 4);
                LDSM_X4(afr[mt][0], afr[mt][1], afr[mt][2], afr[mt][3], a);
            }
#pragma unroll
            for (int p = 0; p < 4; p++) {
                int row = wn + p * 16 + laneB_row;
                int ch  = ks * 2 + laneB_ch;
                uint32_t a = Bbuf + row * 128 + ((ch ^ (row & 7)) << 4);
                uint32_t b0, b1, b2, b3;
                LDSM_X4(b0, b1, b2, b3, a);
#pragma unroll
                for (int mt = 0; mt < 2; mt++) {
                    MMA16816(acc[mt][p*2],   afr[mt], b0, b1);
                    MMA16816(acc[mt][p*2+1], afr[mt], b2, b3);
                }
            }
        }
        __syncthreads();
    }
}

// Generic GEMM: Y fp32, stride 512
__global__ __launch_bounds__(256, 2)
void gemm_hmma(const __nv_bfloat16* __restrict__ Ahi,
               const __nv_bfloat16* __restrict__ Alo,
               const __nv_bfloat16* __restrict__ Bhi,
               const __nv_bfloat16* __restrict__ Blo,
               float* __restrict__ Y, float alpha)
{
    extern __shared__ __align__(128) char sm[];
    uint32_t sbase = smem_u32(sm);
    int t = threadIdx.x, w = t >> 5, lane = t & 31;
    int rowBase = blockIdx.y * 128, colBase = blockIdx.x * 128;
    int wm = (w & 3) * 32, wn = (w >> 2) * 64;

    float acc[2][8][4];
#pragma unroll
    for (int mt = 0; mt < 2; mt++)
#pragma unroll
        for (int nt = 0; nt < 8; nt++)
#pragma unroll
            for (int e = 0; e < 4; e++) acc[mt][nt][e] = 0.f;

    gemm_mainloop(Ahi, Alo, Bhi, Blo, rowBase, colBase, sbase, t, acc);

#pragma unroll
    for (int mt = 0; mt < 2; mt++)
#pragma unroll
        for (int nt = 0; nt < 8; nt++) {
            float* a4 = acc[mt][nt];
            int r0 = rowBase + wm + mt * 16 + (lane >> 2);
            int c0 = colBase + wn + nt * 8 + (lane & 3) * 2;
            *(float2*)&Y[(size_t)r0 * 512 + c0] = make_float2(a4[0]*alpha, a4[1]*alpha);
            *(float2*)&Y[(size_t)(r0+8) * 512 + c0] = make_float2(a4[2]*alpha, a4[3]*alpha);
        }
}

// QKV GEMM: B rows span 1536 (Wq|Wk|Wv ^T). Epilogue -> per-head hi/lo bf16.
__global__ __launch_bounds__(256, 2)
void gemm_qkv(const __nv_bfloat16* __restrict__ Ahi,
              const __nv_bfloat16* __restrict__ Alo,
              const __nv_bfloat16* __restrict__ Bhi,
              const __nv_bfloat16* __restrict__ Blo)
{
    extern __shared__ __align__(128) char sm[];
    uint32_t sbase = smem_u32(sm);
    int t = threadIdx.x, w = t >> 5, lane = t & 31;
    int rowBase = blockIdx.y * 128, colBase = blockIdx.x * 128;
    int wm = (w & 3) * 32, wn = (w >> 2) * 64;

    float acc[2][8][4];
#pragma unroll
    for (int mt = 0; mt < 2; mt++)
#pragma unroll
        for (int nt = 0; nt < 8; nt++)
#pragma unroll
            for (int e = 0; e < 4; e++) acc[mt][nt][e] = 0.f;

    gemm_mainloop(Ahi, Alo, Bhi, Blo, rowBase, colBase, sbase, t, acc);

    int tensor = colBase >> 9;
    float alpha = (tensor == 0) ? 0.125f : 1.0f;
    __nv_bfloat16* dst = (tensor == 0) ? g_qc : (tensor == 1) ? g_kc : g_vc;

#pragma unroll
    for (int mt = 0; mt < 2; mt++)
#pragma unroll
        for (int nt = 0; nt < 8; nt++) {
            float* a4 = acc[mt][nt];
            int r0 = rowBase + wm + mt * 16 + (lane >> 2);
            int cc = (colBase & 511) + wn + nt * 8 + (lane & 3) * 2;
            int hh = cc >> 6, dd = cc & 63;
            int b = r0 >> 12, s = r0 & 4095;
            size_t off = ((size_t)((b << 3) + hh) * 4096 + s) * 128 + dd;
            uint32_t hi, lo;
            split2(a4[0]*alpha, a4[1]*alpha, hi, lo);
            *(uint32_t*)&dst[off] = hi;
            *(uint32_t*)&dst[off + 64] = lo;
            size_t off2 = off + 8ULL * 128;
            split2(a4[2]*alpha, a4[3]*alpha, hi, lo);
            *(uint32_t*)&dst[off2] = hi;
            *(uint32_t*)&dst[off2 + 64] = lo;
        }
}

// ---------------------------------------------------------------------------
// HMMA attention, FA2-style register-resident p (no smem p round-trip).
// Each warp: rows wm..wm+15, score-cols wn..wn+31 (k-half), full d=64 output;
// cross-half output reduction once at the end.
// smem: QS 16K | KS0/1 32K | VS0/1 32K | EX ~16.5K | km | red1 | redL
// ---------------------------------------------------------------------------
#define OFF_KS 16384
#define OFF_VS 49152
#define OFF_EX 81920
#define EX_PITCH 66
#define OFF_KM 98816
#define OFF_R1 99328
#define OFF_RL 99840
#define ATT_SMEM 100352

__device__ __forceinline__ int kb_of(bool mid, int qb, int chunk, int itk,
                                     const int* __restrict__ rand_blocks)
{
    if (!mid) return chunk * 8 + itk;
    if (itk < 3) return qb - 1 + itk;
    if (itk == 3) return 0;
    if (itk == 4) return 63;
    return rand_blocks[(qb - 2) * 3 + (itk - 5)];
}

__device__ __forceinline__ void attn_prefetch_kv(int bh, int kb, uint32_t KSb,
                                                 uint32_t VSb, int t)
{
    size_t koff = ((size_t)bh * 4096 + kb * 64) * 128;
#pragma unroll
    for (int it = 0; it < 4; it++) {
        int idx = it * 256 + t;
        int r = idx >> 4, c = idx & 15;
        CPASYNC16(KSb + r * 256 + ((c ^ (r & 7)) << 4), &g_kc[koff + r * 128 + c * 8]);
    }
#pragma unroll
    for (int it = 0; it < 4; it++) {
        int idx = it * 256 + t;
        int r = idx >> 4, c = idx & 15;
        CPASYNC16(VSb + r * 256 + ((c ^ (r & 7)) << 4), &g_vc[koff + r * 128 + c * 8]);
    }
    CPCOMMIT();
}

__global__ __launch_bounds__(256, 2)
void attn_hmma(const float* __restrict__ mask, const int* __restrict__ rand_blocks)
{
    extern __shared__ __align__(128) char sm[];
    uint32_t sb = smem_u32(sm);
    const uint32_t QS = sb;
    float* km   = (float*)(sm + OFF_KM);    // [2][64]
    float* red1 = (float*)(sm + OFF_R1);
    float* redL = (float*)(sm + OFF_RL);
    float* ex   = (float*)(sm + OFF_EX);    // [64][EX_PITCH]

    int t = threadIdx.x, w = t >> 5, lane = t & 31;
    int wm = (w & 3) * 16;
    int wni = w >> 2;
    int wn  = wni * 32;

    int u  = blockIdx.x % 92;
    int bh = blockIdx.x / 92;
    int b  = bh >> 3, h = bh & 7;

    bool mid = (u < 60);
    int qb, chunk = 0, di = 0;
    if (mid) { qb = u + 2; }
    else {
        int d = u - 60;
        di = d >> 3; chunk = d & 7;
        qb = (di < 2) ? di : (60 + di);
    }

    // ---- prologue: Q + K0/V0 via cp.async (one group), km[0] ----
    {
        size_t qoff = ((size_t)bh * 4096 + qb * 64) * 128;
#pragma unroll
        for (int it = 0; it < 4; it++) {
            int idx = it * 256 + t;
            int r = idx >> 4, c = idx & 15;
            CPASYNC16(QS + r * 256 + ((c ^ (r & 7)) << 4), &g_qc[qoff + r * 128 + c * 8]);
        }
        int kb0 = kb_of(mid, qb, chunk, 0, rand_blocks);
        attn_prefetch_kv(bh, kb0, sb + OFF_KS, sb + OFF_VS, t);  // commits Q+K0+V0
        if (t < 64) km[t] = mask[b * 4096 + kb0 * 64 + t];
    }

    int r1 = wm + (lane >> 2), r2 = r1 + 8;
    float mq1 = mask[b * 4096 + qb * 64 + r1];
    float mq2 = mask[b * 4096 + qb * 64 + r2];

    float acc[8][4];
#pragma unroll
    for (int nn = 0; nn < 8; nn++)
#pragma unroll
        for (int e = 0; e < 4; e++) acc[nn][e] = 0.f;
    float mo1 = -INFINITY, mo2 = -INFINITY, ls1 = 0.f, ls2 = 0.f;

    int laneA_row = (((lane >> 3) & 1) << 3) + (lane & 7);
    int laneA_ch  = lane >> 4;
    int laneB_row = ((lane >> 4) << 3) + (lane & 7);
    int laneB_ch  = (lane >> 3) & 1;
    int laneV_row = lane & 15;
    int laneV_g   = lane >> 4;

    uint32_t qh[4][4];   // hoisted Q-hi fragments, one per k16 step

    for (int itk = 0; itk < 8; itk++) {
        int buf = itk & 1;
        bool band = mid && (itk < 3);

        __syncthreads();   // buf^1 tiles fully consumed (prev-prev iter)
        if (itk < 7) {
            int kbn = kb_of(mid, qb, chunk, itk + 1, rand_blocks);
            attn_prefetch_kv(bh, kbn, sb + OFF_KS + (buf ^ 1) * 16384,
                             sb + OFF_VS + (buf ^ 1) * 16384, t);
            if (t < 64) km[(buf ^ 1) * 64 + t] = mask[b * 4096 + kbn * 64 + t];
            CPWAIT(1);
        } else {
            CPWAIT(0);
        }
        __syncthreads();   // current buf visible

        if (itk == 0) {
#pragma unroll
            for (int ks = 0; ks < 4; ks++) {
                int row = wm + laneA_row;
                int ch = ks * 2 + laneA_ch;
                LDSM_X4(qh[ks][0], qh[ks][1], qh[ks][2], qh[ks][3],
                        QS + row * 256 + ((ch ^ (row & 7)) << 4));
            }
        }

        uint32_t KSb = sb + OFF_KS + buf * 16384;
        uint32_t VSb = sb + OFF_VS + buf * 16384;
        const float* kmask_s = km + buf * 64;

        // ---- QK: s = qh.kh + ql.kh + qh.kl ----
        float sc[4][4];
#pragma unroll
        for (int nt = 0; nt < 4; nt++)
#pragma unroll
            for (int e = 0; e < 4; e++) sc[nt][e] = 0.f;

#pragma unroll
        for (int ks = 0; ks < 4; ks++) {
            int kc2 = ks * 2;
            uint32_t kh[2][4];
#pragma unroll
            for (int g = 0; g < 2; g++) {
                int row = wn + g * 16 + laneB_row;
                int ch = kc2 + laneB_ch;
                LDSM_X4(kh[g][0], kh[g][1], kh[g][2], kh[g][3],
                        KSb + row * 256 + ((ch ^ (row & 7)) << 4));
            }
#pragma unroll
            for (int g = 0; g < 2; g++) {
                MMA16816(sc[g*2],   qh[ks], kh[g][0], kh[g][1]);
                MMA16816(sc[g*2+1], qh[ks], kh[g][2], kh[g][3]);
            }
            uint32_t ql[4];
            {
                int row = wm + laneA_row;
                int ch = 8 + kc2 + laneA_ch;
                LDSM_X4(ql[0], ql[1], ql[2], ql[3],
                        QS + row * 256 + ((ch ^ (row & 7)) << 4));
            }
#pragma unroll
            for (int g = 0; g < 2; g++) {
                MMA16816(sc[g*2],   ql, kh[g][0], kh[g][1]);
                MMA16816(sc[g*2+1], ql, kh[g][2], kh[g][3]);
            }
#pragma unroll
            for (int g = 0; g < 2; g++) {
                uint32_t kl[4];
                int row = wn + g * 16 + laneB_row;
                int ch = 8 + kc2 + laneB_ch;
                LDSM_X4(kl[0], kl[1], kl[2], kl[3],
                        KSb + row * 256 + ((ch ^ (row & 7)) << 4));
                MMA16816(sc[g*2],   qh[ks], kl[0], kl[1]);
                MMA16816(sc[g*2+1], qh[ks], kl[2], kl[3]);
            }
        }

        // ---- mask ----
#pragma unroll
        for (int nt = 0; nt < 4; nt++) {
            int col = wn + nt * 8 + (lane & 3) * 2;
            float mk0 = kmask_s[col], mk1 = kmask_s[col + 1];
            float m00 = band ? mk0 * mq1 : mk0;
            float m01 = band ? mk1 * mq1 : mk1;
            float m10 = band ? mk0 * mq2 : mk0;
            float m11 = band ? mk1 * mq2 : mk1;
            sc[nt][0] += (1.0f - m00) * NEGF;
            sc[nt][1] += (1.0f - m01) * NEGF;
            sc[nt][2] += (1.0f - m10) * NEGF;
            sc[nt][3] += (1.0f - m11) * NEGF;
        }

        // ---- row max (in-warp 32 cols, cross-half via smem) ----
        float m1 = -INFINITY, m2 = -INFINITY;
#pragma unroll
        for (int nt = 0; nt < 4; nt++) {
            m1 = fmaxf(m1, fmaxf(sc[nt][0], sc[nt][1]));
            m2 = fmaxf(m2, fmaxf(sc[nt][2], sc[nt][3]));
        }
        m1 = fmaxf(m1, __shfl_xor_sync(0xffffffffu, m1, 1));
        m1 = fmaxf(m1, __shfl_xor_sync(0xffffffffu, m1, 2));
        m2 = fmaxf(m2, __shfl_xor_sync(0xffffffffu, m2, 1));
        m2 = fmaxf(m2, __shfl_xor_sync(0xffffffffu, m2, 2));
        if ((lane & 3) == 0) {
            red1[wni * 64 + r1] = m1;
            red1[wni * 64 + r2] = m2;
        }
        __syncthreads();
        float mn1 = fmaxf(mo1, fmaxf(red1[r1], red1[64 + r1]));
        float mn2 = fmaxf(mo2, fmaxf(red1[r2], red1[64 + r2]));
        float corr1 = __expf(mo1 - mn1);
        float corr2 = __expf(mo2 - mn2);

        // ---- exp, register hi/lo pack into A fragments ----
        float sum1 = 0.f, sum2 = 0.f;
        uint32_t aph[2][4], apl[2][4];
#pragma unroll
        for (int nt = 0; nt < 4; nt++) {
            float p00 = __expf(sc[nt][0] - mn1), p01 = __expf(sc[nt][1] - mn1);
            float p10 = __expf(sc[nt][2] - mn2), p11 = __expf(sc[nt][3] - mn2);
            sum1 += p00 + p01; sum2 += p10 + p11;
            int j = nt >> 1, hf = (nt & 1) * 2;
            uint32_t hiA, loA, hiB, loB;
            split2(p00, p01, hiA, loA);
            split2(p10, p11, hiB, loB);
            aph[j][hf]     = hiA;  aph[j][hf + 1] = hiB;
            apl[j][hf]     = loA;  apl[j][hf + 1] = loB;
        }
        ls1 = ls1 * corr1 + sum1;
        ls2 = ls2 * corr2 + sum2;
        mo1 = mn1; mo2 = mn2;
#pragma unroll
        for (int nn = 0; nn < 8; nn++) {
            acc[nn][0] *= corr1; acc[nn][1] *= corr1;
            acc[nn][2] *= corr2; acc[nn][3] *= corr2;
        }

        // ---- PV: acc += ph.vh + pl.vh + ph.vl  (k = own 32 score-cols) ----
#pragma unroll
        for (int j = 0; j < 2; j++) {
            int vrow = wn + j * 16 + laneV_row;
            uint32_t vbase = VSb + vrow * 256;
            int sw = (vrow & 7) << 4;
#pragma unroll
            for (int np = 0; np < 4; np++) {
                uint32_t vh4[4];
                int ch = np * 2 + laneV_g;
                LDSM_X4T(vh4[0], vh4[1], vh4[2], vh4[3], vbase + ((ch << 4) ^ sw));
                MMA16816(acc[np*2],   aph[j], vh4[0], vh4[1]);
                MMA16816(acc[np*2+1], aph[j], vh4[2], vh4[3]);
                MMA16816(acc[np*2],   apl[j], vh4[0], vh4[1]);
                MMA16816(acc[np*2+1], apl[j], vh4[2], vh4[3]);
                uint32_t vl4[4];
                int chl = 8 + np * 2 + laneV_g;
                LDSM_X4T(vl4[0], vl4[1], vl4[2], vl4[3], vbase + ((chl << 4) ^ sw));
                MMA16816(acc[np*2],   aph[j], vl4[0], vl4[1]);
                MMA16816(acc[np*2+1], aph[j], vl4[2], vl4[3]);
            }
        }
    }

    // ---- final ls combine: quad shfl + cross-half smem ----
    ls1 += __shfl_xor_sync(0xffffffffu, ls1, 1);
    ls1 += __shfl_xor_sync(0xffffffffu, ls1, 2);
    ls2 += __shfl_xor_sync(0xffffffffu, ls2, 1);
    ls2 += __shfl_xor_sync(0xffffffffu, ls2, 2);
    if ((lane & 3) == 0) {
        redL[wni * 64 + r1] = ls1;
        redL[wni * 64 + r2] = ls2;
    }
    __syncthreads();
    ls1 = redL[r1] + redL[64 + r1];
    ls2 = redL[r2] + redL[64 + r2];

    // ---- cross-half acc reduction: half 1 -> smem, half 0 adds ----
    if (wni == 1) {
#pragma unroll
        for (int nn = 0; nn < 8; nn++) {
            int col = nn * 8 + (lane & 3) * 2;
            *(float2*)&ex[r1 * EX_PITCH + col] = make_float2(acc[nn][0], acc[nn][1]);
            *(float2*)&ex[r2 * EX_PITCH + col] = make_float2(acc[nn][2], acc[nn][3]);
        }
    }
    __syncthreads();
    if (wni == 0) {
#pragma unroll
        for (int nn = 0; nn < 8; nn++) {
            int col = nn * 8 + (lane & 3) * 2;
            float2 v1 = *(float2*)&ex[r1 * EX_PITCH + col];
            float2 v2 = *(float2*)&ex[r2 * EX_PITCH + col];
            acc[nn][0] += v1.x; acc[nn][1] += v1.y;
            acc[nn][2] += v2.x; acc[nn][3] += v2.y;
        }

        if (mid) {
            float inv1 = 1.0f / ls1, inv2 = 1.0f / ls2;
#pragma unroll
            for (int nn = 0; nn < 8; nn++) {
                int col = nn * 8 + (lane & 3) * 2;
                size_t o1 = ((size_t)(b * 4096 + qb * 64 + r1)) * 512 + h * 64 + col;
                size_t o2 = ((size_t)(b * 4096 + qb * 64 + r2)) * 512 + h * 64 + col;
                uint32_t hi, lo;
                split2(acc[nn][0] * inv1, acc[nn][1] * inv1, hi, lo);
                *(uint32_t*)&g_xhi[o1] = hi; *(uint32_t*)&g_xlo[o1] = lo;
                split2(acc[nn][2] * inv2, acc[nn][3] * inv2, hi, lo);
                *(uint32_t*)&g_xhi[o2] = hi; *(uint32_t*)&g_xlo[o2] = lo;
            }
        } else {
            int slot = (bh * 4 + di) * 8 + chunk;
            float* p = g_part + (size_t)slot * SLOT_F;
#pragma unroll
            for (int nn = 0; nn < 8; nn++) {
                int col = nn * 8 + (lane & 3) * 2;
                *(float2*)&p[r1 * 64 + col] = make_float2(acc[nn][0], acc[nn][1]);
                *(float2*)&p[r2 * 64 + col] = make_float2(acc[nn][2], acc[nn][3]);
            }
            if ((lane & 3) == 0) {
                p[4096 + r1] = mo1; p[4160 + r1] = ls1;
                p[4096 + r2] = mo2; p[4160 + r2] = ls2;
            }
        }
    }
}

// ---------------------------------------------------------------------------
// Combine 8 dense split-K partials -> hi/lo bf16 ctx
// ---------------------------------------------------------------------------
__global__ __launch_bounds__(256) void combine_kernel()
{
    int g  = blockIdx.x;
    int bh = g >> 2, di = g & 3;
    int qb = (di < 2) ? di : (60 + di);
    int b  = bh >> 3, h = bh & 7;
    int t   = threadIdx.x;
    int row = t & 63;
    int c0  = (t >> 6) * 16;

    const float* base = g_part + (size_t)(g * 8) * SLOT_F;
    float m[8];
    float M = -INFINITY;
#pragma unroll
    for (int s = 0; s < 8; s++) { m[s] = base[s*SLOT_F + 4096 + row]; M = fmaxf(M, m[s]); }
    float wg[8]; float L = 0.f;
#pragma unroll
    for (int s = 0; s < 8; s++) { wg[s] = __expf(m[s] - M); L += base[s*SLOT_F + 4160 + row] * wg[s]; }
    float inv = 1.0f / L;

    float o[16];
#pragma unroll
    for (int c = 0; c < 16; c++) o[c] = 0.f;
#pragma unroll
    for (int s = 0; s < 8; s++) {
        const float* pa = base + s*SLOT_F + row*64 + c0;
        float ws = wg[s];
#pragma unroll
        for (int c4 = 0; c4 < 4; c4++) {
            float4 v4 = *(const float4*)&pa[c4*4];
            o[c4*4+0] += ws * v4.x; o[c4*4+1] += ws * v4.y;
            o[c4*4+2] += ws * v4.z; o[c4*4+3] += ws * v4.w;
        }
    }
    size_t dst = ((size_t)(b * 4096 + qb * 64 + row)) * 512 + h * 64 + c0;
#pragma unroll
    for (int cp = 0; cp < 8; cp++) {
        uint32_t hi, lo;
        split2(o[cp*2] * inv, o[cp*2+1] * inv, hi, lo);
        *(uint32_t*)&g_xhi[dst + cp*2] = hi;
        *(uint32_t*)&g_xlo[dst + cp*2] = lo;
    }
}

// ---------------------------------------------------------------------------
__global__ __launch_bounds__(256) void ln_kernel(const float* __restrict__ x,
                                                 const float* __restrict__ bo,
                                                 const float* __restrict__ gamma,
                                                 const float* __restrict__ beta,
                                                 float* __restrict__ out)
{
    int row = blockIdx.x;
    int t = threadIdx.x;
    size_t base = (size_t)row * 512;
    float h0 = g_h[base + t]       + bo[t]       + x[base + t];
    float h1 = g_h[base + t + 256] + bo[t + 256] + x[base + t + 256];
    float s = h0 + h1;
    float q = h0*h0 + h1*h1;
#pragma unroll
    for (int m = 16; m >= 1; m >>= 1) {
        s += __shfl_xor_sync(0xffffffffu, s, m);
        q += __shfl_xor_sync(0xffffffffu, q, m);
    }
    __shared__ float ss[8], qq[8];
    int w = t >> 5;
    if ((t & 31) == 0) { ss[w] = s; qq[w] = q; }
    __syncthreads();
    float S2 = 0.f, Q2 = 0.f;
#pragma unroll
    for (int i = 0; i < 8; i++) { S2 += ss[i]; Q2 += qq[i]; }
    float mu  = S2 * (1.0f / 512.0f);
    float var = Q2 * (1.0f / 512.0f) - mu * mu;
    float inv = rsqrtf(var + 1e-12f);
    out[base + t]       = (h0 - mu) * inv * gamma[t]       + beta[t];
    out[base + t + 256] = (h1 - mu) * inv * gamma[t + 256] + beta[t + 256];
}

// ---------------------------------------------------------------------------
extern "C" void kernel_launch(void* const* d_in, const int* in_sizes, int n_in,
                              void* d_out, int out_size)
{
    const float* x     = (const float*)d_in[0];
    const float* mask  = (const float*)d_in[1];
    const int*   rb    = (const int*)  d_in[2];
    const float* Wq    = (const float*)d_in[3];
    const float* Wk    = (const float*)d_in[4];
    const float* Wv    = (const float*)d_in[5];
    const float* Wo    = (const float*)d_in[6];
    const float* bo    = (const float*)d_in[7];
    const float* gamma = (const float*)d_in[8];
    const float* beta  = (const float*)d_in[9];
    float* out = (float*)d_out;

    float* hp;
    __nv_bfloat16 *xh, *xl, *wth, *wtl;
    cudaGetSymbolAddress((void**)&hp, g_h);
    cudaGetSymbolAddress((void**)&xh, g_xhi);
    cudaGetSymbolAddress((void**)&xl, g_xlo);
    cudaGetSymbolAddress((void**)&wth, g_wthi);
    cudaGetSymbolAddress((void**)&wtl, g_wtlo);

    cudaFuncSetAttribute(gemm_hmma, cudaFuncAttributeMaxDynamicSharedMemorySize, GEMM_SMEM);
    cudaFuncSetAttribute(gemm_qkv,  cudaFuncAttributeMaxDynamicSharedMemorySize, GEMM_SMEM);
    cudaFuncSetAttribute(attn_hmma, cudaFuncAttributeMaxDynamicSharedMemorySize, ATT_SMEM);

    conv_x<<<NROWS, 256>>>(x, xh, xl);
    dim3 wtg(16, 16, 4), wtb(32, 8);
    conv_wt4<<<wtg, wtb>>>(Wq, Wk, Wv, Wo, wth, wtl);

    dim3 gq(12, 64);                         // 1536/128 x 8192/128
    gemm_qkv<<<gq, 256, GEMM_SMEM>>>(xh, xl, wth, wtl);

    attn_hmma<<<16 * 92, 256, ATT_SMEM>>>(mask, rb);
    combine_kernel<<<64, 256>>>();

    dim3 go(4, 64);
    gemm_hmma<<<go, 256, GEMM_SMEM>>>(xh, xl, wth + 3*262144, wtl + 3*262144, hp, 1.0f);

    ln_kernel<<<Bb * Ss, 256>>>(x, bo, gamma, beta, out);
}

// round 8
// speedup vs baseline: 3.7957x; 1.0698x over previous
#include <cuda_runtime.h>
#include <cuda_bf16.h>
#include <math.h>
#include <stdint.h>

#define Bb 2
#define Ss 4096
#define Dd 512
#define NROWS (Bb*Ss)      // 8192
#define NEGF -1000000000.0f

// ---------------- scratch (device globals: allocation-free) ----------------
__device__ float g_h[NROWS*Dd];
#define SLOT_F 4224
__device__ float g_part[512 * SLOT_F];
__device__ __align__(16) __nv_bfloat16 g_xhi[NROWS*Dd];
__device__ __align__(16) __nv_bfloat16 g_xlo[NROWS*Dd];
__device__ __align__(16) __nv_bfloat16 g_wthi[4*Dd*Dd];   // W^T x4 (qkv 0..1535, Wo 1536..)
__device__ __align__(16) __nv_bfloat16 g_wtlo[4*Dd*Dd];
// per-head q/k/v: [bh][s][128] bf16, cols 0..63 = hi, 64..127 = lo
__device__ __align__(16) __nv_bfloat16 g_qc[16ULL*4096*128];
__device__ __align__(16) __nv_bfloat16 g_kc[16ULL*4096*128];
__device__ __align__(16) __nv_bfloat16 g_vc[16ULL*4096*128];

// ---------------- PTX helpers (base-target legal) ----------------
__device__ __forceinline__ uint32_t smem_u32(const void* p) {
    return (uint32_t)__cvta_generic_to_shared(p);
}
#define CPASYNC16(dst, src) \
    asm volatile("cp.async.cg.shared.global [%0], [%1], 16;" :: "r"(dst), "l"(src))
#define CPCOMMIT() asm volatile("cp.async.commit_group;" ::: "memory")
#define CPWAIT(n)  asm volatile("cp.async.wait_group %0;" :: "n"(n) : "memory")

#define LDSM_X4(r0, r1, r2, r3, a) \
    asm volatile("ldmatrix.sync.aligned.m8n8.x4.shared.b16 {%0,%1,%2,%3}, [%4];" \
                 : "=r"(r0), "=r"(r1), "=r"(r2), "=r"(r3) : "r"(a))
#define LDSM_X4T(r0, r1, r2, r3, a) \
    asm volatile("ldmatrix.sync.aligned.m8n8.x4.trans.shared.b16 {%0,%1,%2,%3}, [%4];" \
                 : "=r"(r0), "=r"(r1), "=r"(r2), "=r"(r3) : "r"(a))

#define MMA16816(D, A, B0, B1) \
    asm volatile("mma.sync.aligned.m16n8k16.row.col.f32.bf16.bf16.f32 " \
                 "{%0,%1,%2,%3},{%4,%5,%6,%7},{%8,%9},{%0,%1,%2,%3};" \
                 : "+f"((D)[0]), "+f"((D)[1]), "+f"((D)[2]), "+f"((D)[3]) \
                 : "r"((A)[0]), "r"((A)[1]), "r"((A)[2]), "r"((A)[3]), \
                   "r"(B0), "r"(B1))

__device__ __forceinline__ uint32_t pack_hi(float a, float b) {
    __nv_bfloat162 h = __floats2bfloat162_rn(a, b);
    return *(uint32_t*)&h;
}
__device__ __forceinline__ void split2(float a, float b, uint32_t& hi, uint32_t& lo) {
    __nv_bfloat16 ha = __float2bfloat16(a), hb = __float2bfloat16(b);
    float ra = a - __bfloat162float(ha), rb = b - __bfloat162float(hb);
    __nv_bfloat162 H; H.x = ha; H.y = hb;
    __nv_bfloat162 L = __floats2bfloat162_rn(ra, rb);
    hi = *(uint32_t*)&H; lo = *(uint32_t*)&L;
}

// ---------------------------------------------------------------------------
// Conversions
// ---------------------------------------------------------------------------
__global__ __launch_bounds__(256) void conv_x(const float* __restrict__ X,
                                              __nv_bfloat16* __restrict__ Hi,
                                              __nv_bfloat16* __restrict__ Lo)
{
    size_t i0 = (size_t)blockIdx.x * 512 + threadIdx.x;
#pragma unroll
    for (int s = 0; s < 2; s++) {
        size_t i = i0 + s * 256;
        float v = X[i];
        __nv_bfloat16 h = __float2bfloat16(v);
        Hi[i] = h;
        Lo[i] = __float2bfloat16(v - __bfloat162float(h));
    }
}

// All four W[512,512] -> W^T bf16 hi/lo in one launch. grid (16,16,4)
__global__ void conv_wt4(const float* __restrict__ W0, const float* __restrict__ W1,
                         const float* __restrict__ W2, const float* __restrict__ W3,
                         __nv_bfloat16* __restrict__ Th, __nv_bfloat16* __restrict__ Tl)
{
    __shared__ float tile[32][33];
    int z = blockIdx.z;
    const float* W = (z == 0) ? W0 : (z == 1) ? W1 : (z == 2) ? W2 : W3;
    __nv_bfloat16* th = Th + (size_t)z * 262144;
    __nv_bfloat16* tl = Tl + (size_t)z * 262144;
    int n0 = blockIdx.x * 32, k0 = blockIdx.y * 32;
    int tx = threadIdx.x, ty = threadIdx.y;
#pragma unroll
    for (int j = 0; j < 32; j += 8)
        tile[ty + j][tx] = W[(size_t)(k0 + ty + j) * 512 + n0 + tx];
    __syncthreads();
#pragma unroll
    for (int j = 0; j < 32; j += 8) {
        int row = ty + j;
        float v = tile[tx][row];
        __nv_bfloat16 h = __float2bfloat16(v);
        size_t o = (size_t)(n0 + row) * 512 + k0 + tx;
        th[o] = h;
        tl[o] = __float2bfloat16(v - __bfloat162float(h));
    }
}

// ---------------------------------------------------------------------------
// Shared GEMM mainloop (CTA 128x128, BK=64, cp.async double buffer)
// ---------------------------------------------------------------------------
#define GEMM_SMEM 65536

__device__ __forceinline__ void gemm_ld_chunk(const __nv_bfloat16* __restrict__ A,
                                              const __nv_bfloat16* __restrict__ Bt,
                                              int rowBase, int colBase, int k0,
                                              uint32_t Ab, uint32_t Bbuf, int t)
{
#pragma unroll
    for (int it = 0; it < 4; it++) {
        int idx = it * 256 + t;
        int r = idx >> 3, c = idx & 7;
        uint32_t d = Ab + r * 128 + ((c ^ (r & 7)) << 4);
        CPASYNC16(d, &A[(size_t)(rowBase + r) * 512 + k0 + c * 8]);
    }
#pragma unroll
    for (int it = 0; it < 4; it++) {
        int idx = it * 256 + t;
        int r = idx >> 3, c = idx & 7;
        uint32_t d = Bbuf + r * 128 + ((c ^ (r & 7)) << 4);
        CPASYNC16(d, &Bt[(size_t)(colBase + r) * 512 + k0 + c * 8]);
    }
    CPCOMMIT();
}

__device__ __forceinline__ void gemm_mainloop(const __nv_bfloat16* Ahi, const __nv_bfloat16* Alo,
                                              const __nv_bfloat16* Bhi, const __nv_bfloat16* Blo,
                                              int rowBase, int colBase, uint32_t sbase, int t,
                                              float acc[2][8][4])
{
    int w = t >> 5, lane = t & 31;
    int wm = (w & 3) * 32, wn = (w >> 2) * 64;
    int laneA_row = (((lane >> 3) & 1) << 3) + (lane & 7);
    int laneA_ch  = (lane >> 4);
    int laneB_row = ((lane >> 4) << 3) + (lane & 7);
    int laneB_ch  = ((lane >> 3) & 1);

    gemm_ld_chunk(Ahi, Bhi, rowBase, colBase, 0, sbase, sbase + 16384u, t);

    for (int i = 0; i < 24; i++) {
        int buf = i & 1;
        if (i < 23) {
            int j = i + 1, seg = j >> 3, k0 = (j & 7) * 64;
            const __nv_bfloat16* As = (seg < 2)  ? Ahi : Alo;
            const __nv_bfloat16* Bs = (seg == 1) ? Blo : Bhi;
            uint32_t Ab = sbase + (buf ? 0u : 32768u);
            gemm_ld_chunk(As, Bs, rowBase, colBase, k0, Ab, Ab + 16384u, t);
            CPWAIT(1);
        } else {
            CPWAIT(0);
        }
        __syncthreads();

        uint32_t Ab = sbase + (buf ? 32768u : 0u);
        uint32_t Bbuf = Ab + 16384u;
#pragma unroll
        for (int ks = 0; ks < 4; ks++) {
            uint32_t afr[2][4];
#pragma unroll
            for (int mt = 0; mt < 2; mt++) {
                int row = wm + mt * 16 + laneA_row;
                int ch  = ks * 2 + laneA_ch;
                uint32_t a = Ab + row * 128 + ((ch ^ (row & 7)) << 4);
                LDSM_X4(afr[mt][0], afr[mt][1], afr[mt][2], afr[mt][3], a);
            }
#pragma unroll
            for (int p = 0; p < 4; p++) {
                int row = wn + p * 16 + laneB_row;
                int ch  = ks * 2 + laneB_ch;
                uint32_t a = Bbuf + row * 128 + ((ch ^ (row & 7)) << 4);
                uint32_t b0, b1, b2, b3;
                LDSM_X4(b0, b1, b2, b3, a);
#pragma unroll
                for (int mt = 0; mt < 2; mt++) {
                    MMA16816(acc[mt][p*2],   afr[mt], b0, b1);
                    MMA16816(acc[mt][p*2+1], afr[mt], b2, b3);
                }
            }
        }
        __syncthreads();
    }
}

// Generic GEMM: Y fp32, stride 512
__global__ __launch_bounds__(256, 2)
void gemm_hmma(const __nv_bfloat16* __restrict__ Ahi,
               const __nv_bfloat16* __restrict__ Alo,
               const __nv_bfloat16* __restrict__ Bhi,
               const __nv_bfloat16* __restrict__ Blo,
               float* __restrict__ Y, float alpha)
{
    extern __shared__ __align__(128) char sm[];
    uint32_t sbase = smem_u32(sm);
    int t = threadIdx.x, w = t >> 5, lane = t & 31;
    int rowBase = blockIdx.y * 128, colBase = blockIdx.x * 128;
    int wm = (w & 3) * 32, wn = (w >> 2) * 64;

    float acc[2][8][4];
#pragma unroll
    for (int mt = 0; mt < 2; mt++)
#pragma unroll
        for (int nt = 0; nt < 8; nt++)
#pragma unroll
            for (int e = 0; e < 4; e++) acc[mt][nt][e] = 0.f;

    gemm_mainloop(Ahi, Alo, Bhi, Blo, rowBase, colBase, sbase, t, acc);

#pragma unroll
    for (int mt = 0; mt < 2; mt++)
#pragma unroll
        for (int nt = 0; nt < 8; nt++) {
            float* a4 = acc[mt][nt];
            int r0 = rowBase + wm + mt * 16 + (lane >> 2);
            int c0 = colBase + wn + nt * 8 + (lane & 3) * 2;
            *(float2*)&Y[(size_t)r0 * 512 + c0] = make_float2(a4[0]*alpha, a4[1]*alpha);
            *(float2*)&Y[(size_t)(r0+8) * 512 + c0] = make_float2(a4[2]*alpha, a4[3]*alpha);
        }
}

// QKV GEMM: B rows span 1536 (Wq|Wk|Wv ^T). Epilogue -> per-head hi/lo bf16.
__global__ __launch_bounds__(256, 2)
void gemm_qkv(const __nv_bfloat16* __restrict__ Ahi,
              const __nv_bfloat16* __restrict__ Alo,
              const __nv_bfloat16* __restrict__ Bhi,
              const __nv_bfloat16* __restrict__ Blo)
{
    extern __shared__ __align__(128) char sm[];
    uint32_t sbase = smem_u32(sm);
    int t = threadIdx.x, w = t >> 5, lane = t & 31;
    int rowBase = blockIdx.y * 128, colBase = blockIdx.x * 128;
    int wm = (w & 3) * 32, wn = (w >> 2) * 64;

    float acc[2][8][4];
#pragma unroll
    for (int mt = 0; mt < 2; mt++)
#pragma unroll
        for (int nt = 0; nt < 8; nt++)
#pragma unroll
            for (int e = 0; e < 4; e++) acc[mt][nt][e] = 0.f;

    gemm_mainloop(Ahi, Alo, Bhi, Blo, rowBase, colBase, sbase, t, acc);

    int tensor = colBase >> 9;
    float alpha = (tensor == 0) ? 0.125f : 1.0f;
    __nv_bfloat16* dst = (tensor == 0) ? g_qc : (tensor == 1) ? g_kc : g_vc;

#pragma unroll
    for (int mt = 0; mt < 2; mt++)
#pragma unroll
        for (int nt = 0; nt < 8; nt++) {
            float* a4 = acc[mt][nt];
            int r0 = rowBase + wm + mt * 16 + (lane >> 2);
            int cc = (colBase & 511) + wn + nt * 8 + (lane & 3) * 2;
            int hh = cc >> 6, dd = cc & 63;
            int b = r0 >> 12, s = r0 & 4095;
            size_t off = ((size_t)((b << 3) + hh) * 4096 + s) * 128 + dd;
            uint32_t hi, lo;
            split2(a4[0]*alpha, a4[1]*alpha, hi, lo);
            *(uint32_t*)&dst[off] = hi;
            *(uint32_t*)&dst[off + 64] = lo;
            size_t off2 = off + 8ULL * 128;
            split2(a4[2]*alpha, a4[3]*alpha, hi, lo);
            *(uint32_t*)&dst[off2] = hi;
            *(uint32_t*)&dst[off2 + 64] = lo;
        }
}

// ---------------------------------------------------------------------------
// HMMA attention, no-max softmax (scores bounded; masked -> exp underflow 0).
// p stored as plain bf16 fragments (register-resident). PV = ph.vh + ph.vl.
// smem: QS 16K | KS0/1 32K | VS0/1 32K | EX ~16.5K | km | redL
// ---------------------------------------------------------------------------
#define OFF_KS 16384
#define OFF_VS 49152
#define OFF_EX 81920
#define EX_PITCH 66
#define OFF_KM 98816
#define OFF_RL 99328
#define ATT_SMEM 99840

__device__ __forceinline__ int kb_of(bool mid, int qb, int chunk, int itk,
                                     const int* __restrict__ rand_blocks)
{
    if (!mid) return chunk * 8 + itk;
    if (itk < 3) return qb - 1 + itk;
    if (itk == 3) return 0;
    if (itk == 4) return 63;
    return rand_blocks[(qb - 2) * 3 + (itk - 5)];
}

__device__ __forceinline__ void attn_prefetch_kv(int bh, int kb, uint32_t KSb,
                                                 uint32_t VSb, int t)
{
    size_t koff = ((size_t)bh * 4096 + kb * 64) * 128;
#pragma unroll
    for (int it = 0; it < 4; it++) {
        int idx = it * 256 + t;
        int r = idx >> 4, c = idx & 15;
        CPASYNC16(KSb + r * 256 + ((c ^ (r & 7)) << 4), &g_kc[koff + r * 128 + c * 8]);
    }
#pragma unroll
    for (int it = 0; it < 4; it++) {
        int idx = it * 256 + t;
        int r = idx >> 4, c = idx & 15;
        CPASYNC16(VSb + r * 256 + ((c ^ (r & 7)) << 4), &g_vc[koff + r * 128 + c * 8]);
    }
    CPCOMMIT();
}

__global__ __launch_bounds__(256, 2)
void attn_hmma(const float* __restrict__ mask, const int* __restrict__ rand_blocks)
{
    extern __shared__ __align__(128) char sm[];
    uint32_t sb = smem_u32(sm);
    const uint32_t QS = sb;
    float* km   = (float*)(sm + OFF_KM);    // [2][64]
    float* redL = (float*)(sm + OFF_RL);
    float* ex   = (float*)(sm + OFF_EX);    // [64][EX_PITCH]

    int t = threadIdx.x, w = t >> 5, lane = t & 31;
    int wm = (w & 3) * 16;
    int wni = w >> 2;
    int wn  = wni * 32;

    int u  = blockIdx.x % 92;
    int bh = blockIdx.x / 92;
    int b  = bh >> 3, h = bh & 7;

    bool mid = (u < 60);
    int qb, chunk = 0, di = 0;
    if (mid) { qb = u + 2; }
    else {
        int d = u - 60;
        di = d >> 3; chunk = d & 7;
        qb = (di < 2) ? di : (60 + di);
    }

    // ---- prologue: Q + K0/V0 via cp.async (one group), km[0] ----
    {
        size_t qoff = ((size_t)bh * 4096 + qb * 64) * 128;
#pragma unroll
        for (int it = 0; it < 4; it++) {
            int idx = it * 256 + t;
            int r = idx >> 4, c = idx & 15;
            CPASYNC16(QS + r * 256 + ((c ^ (r & 7)) << 4), &g_qc[qoff + r * 128 + c * 8]);
        }
        int kb0 = kb_of(mid, qb, chunk, 0, rand_blocks);
        attn_prefetch_kv(bh, kb0, sb + OFF_KS, sb + OFF_VS, t);  // commits Q+K0+V0
        if (t < 64) km[t] = mask[b * 4096 + kb0 * 64 + t];
    }

    int r1 = wm + (lane >> 2), r2 = r1 + 8;
    float mq1 = mask[b * 4096 + qb * 64 + r1];
    float mq2 = mask[b * 4096 + qb * 64 + r2];

    float acc[8][4];
#pragma unroll
    for (int nn = 0; nn < 8; nn++)
#pragma unroll
        for (int e = 0; e < 4; e++) acc[nn][e] = 0.f;
    float ls1 = 0.f, ls2 = 0.f;

    int laneA_row = (((lane >> 3) & 1) << 3) + (lane & 7);
    int laneA_ch  = lane >> 4;
    int laneB_row = ((lane >> 4) << 3) + (lane & 7);
    int laneB_ch  = (lane >> 3) & 1;
    int laneV_row = lane & 15;
    int laneV_g   = lane >> 4;

    uint32_t qh[4][4], ql[4][4];   // hoisted Q hi/lo fragments

    for (int itk = 0; itk < 8; itk++) {
        int buf = itk & 1;
        bool band = mid && (itk < 3);

        __syncthreads();   // buf^1 tiles fully consumed (prev-prev iter)
        if (itk < 7) {
            int kbn = kb_of(mid, qb, chunk, itk + 1, rand_blocks);
            attn_prefetch_kv(bh, kbn, sb + OFF_KS + (buf ^ 1) * 16384,
                             sb + OFF_VS + (buf ^ 1) * 16384, t);
            if (t < 64) km[(buf ^ 1) * 64 + t] = mask[b * 4096 + kbn * 64 + t];
            CPWAIT(1);
        } else {
            CPWAIT(0);
        }
        __syncthreads();   // current buf visible

        if (itk == 0) {
            int row = wm + laneA_row;
#pragma unroll
            for (int ks = 0; ks < 4; ks++) {
                int ch = ks * 2 + laneA_ch;
                LDSM_X4(qh[ks][0], qh[ks][1], qh[ks][2], qh[ks][3],
                        QS + row * 256 + ((ch ^ (row & 7)) << 4));
                int chl = 8 + ks * 2 + laneA_ch;
                LDSM_X4(ql[ks][0], ql[ks][1], ql[ks][2], ql[ks][3],
                        QS + row * 256 + ((chl ^ (row & 7)) << 4));
            }
        }

        uint32_t KSb = sb + OFF_KS + buf * 16384;
        uint32_t VSb = sb + OFF_VS + buf * 16384;
        const float* kmask_s = km + buf * 64;

        // ---- QK: s = qh.kh + ql.kh + qh.kl ----
        float sc[4][4];
#pragma unroll
        for (int nt = 0; nt < 4; nt++)
#pragma unroll
            for (int e = 0; e < 4; e++) sc[nt][e] = 0.f;

#pragma unroll
        for (int ks = 0; ks < 4; ks++) {
            int kc2 = ks * 2;
            uint32_t kh[2][4];
#pragma unroll
            for (int g = 0; g < 2; g++) {
                int row = wn + g * 16 + laneB_row;
                int ch = kc2 + laneB_ch;
                LDSM_X4(kh[g][0], kh[g][1], kh[g][2], kh[g][3],
                        KSb + row * 256 + ((ch ^ (row & 7)) << 4));
            }
#pragma unroll
            for (int g = 0; g < 2; g++) {
                MMA16816(sc[g*2],   qh[ks], kh[g][0], kh[g][1]);
                MMA16816(sc[g*2+1], qh[ks], kh[g][2], kh[g][3]);
                MMA16816(sc[g*2],   ql[ks], kh[g][0], kh[g][1]);
                MMA16816(sc[g*2+1], ql[ks], kh[g][2], kh[g][3]);
            }
#pragma unroll
            for (int g = 0; g < 2; g++) {
                uint32_t kl[4];
                int row = wn + g * 16 + laneB_row;
                int ch = 8 + kc2 + laneB_ch;
                LDSM_X4(kl[0], kl[1], kl[2], kl[3],
                        KSb + row * 256 + ((ch ^ (row & 7)) << 4));
                MMA16816(sc[g*2],   qh[ks], kl[0], kl[1]);
                MMA16816(sc[g*2+1], qh[ks], kl[2], kl[3]);
            }
        }

        // ---- mask ----
#pragma unroll
        for (int nt = 0; nt < 4; nt++) {
            int col = wn + nt * 8 + (lane & 3) * 2;
            float mk0 = kmask_s[col], mk1 = kmask_s[col + 1];
            float m00 = band ? mk0 * mq1 : mk0;
            float m01 = band ? mk1 * mq1 : mk1;
            float m10 = band ? mk0 * mq2 : mk0;
            float m11 = band ? mk1 * mq2 : mk1;
            sc[nt][0] += (1.0f - m00) * NEGF;
            sc[nt][1] += (1.0f - m01) * NEGF;
            sc[nt][2] += (1.0f - m10) * NEGF;
            sc[nt][3] += (1.0f - m11) * NEGF;
        }

        // ---- exp (no max: scores bounded, masked underflow to 0), bf16 pack ----
        uint32_t aph[2][4];
#pragma unroll
        for (int nt = 0; nt < 4; nt++) {
            float p00 = __expf(sc[nt][0]), p01 = __expf(sc[nt][1]);
            float p10 = __expf(sc[nt][2]), p11 = __expf(sc[nt][3]);
            ls1 += p00 + p01; ls2 += p10 + p11;
            int j = nt >> 1, hf = (nt & 1) * 2;
            aph[j][hf]     = pack_hi(p00, p01);
            aph[j][hf + 1] = pack_hi(p10, p11);
        }

        // ---- PV: acc += ph.vh + ph.vl  (k = own 32 score-cols) ----
#pragma unroll
        for (int j = 0; j < 2; j++) {
            int vrow = wn + j * 16 + laneV_row;
            uint32_t vbase = VSb + vrow * 256;
            int sw = (vrow & 7) << 4;
#pragma unroll
            for (int np = 0; np < 4; np++) {
                uint32_t vh4[4];
                int ch = np * 2 + laneV_g;
                LDSM_X4T(vh4[0], vh4[1], vh4[2], vh4[3], vbase + ((ch << 4) ^ sw));
                MMA16816(acc[np*2],   aph[j], vh4[0], vh4[1]);
                MMA16816(acc[np*2+1], aph[j], vh4[2], vh4[3]);
                uint32_t vl4[4];
                int chl = 8 + np * 2 + laneV_g;
                LDSM_X4T(vl4[0], vl4[1], vl4[2], vl4[3], vbase + ((chl << 4) ^ sw));
                MMA16816(acc[np*2],   aph[j], vl4[0], vl4[1]);
                MMA16816(acc[np*2+1], aph[j], vl4[2], vl4[3]);
            }
        }
    }

    // ---- final ls combine: quad shfl + cross-half smem ----
    ls1 += __shfl_xor_sync(0xffffffffu, ls1, 1);
    ls1 += __shfl_xor_sync(0xffffffffu, ls1, 2);
    ls2 += __shfl_xor_sync(0xffffffffu, ls2, 1);
    ls2 += __shfl_xor_sync(0xffffffffu, ls2, 2);
    if ((lane & 3) == 0) {
        redL[wni * 64 + r1] = ls1;
        redL[wni * 64 + r2] = ls2;
    }
    __syncthreads();
    ls1 = redL[r1] + redL[64 + r1];
    ls2 = redL[r2] + redL[64 + r2];

    // ---- cross-half acc reduction: half 1 -> smem, half 0 adds ----
    if (wni == 1) {
#pragma unroll
        for (int nn = 0; nn < 8; nn++) {
            int col = nn * 8 + (lane & 3) * 2;
            *(float2*)&ex[r1 * EX_PITCH + col] = make_float2(acc[nn][0], acc[nn][1]);
            *(float2*)&ex[r2 * EX_PITCH + col] = make_float2(acc[nn][2], acc[nn][3]);
        }
    }
    __syncthreads();
    if (wni == 0) {
#pragma unroll
        for (int nn = 0; nn < 8; nn++) {
            int col = nn * 8 + (lane & 3) * 2;
            float2 v1 = *(float2*)&ex[r1 * EX_PITCH + col];
            float2 v2 = *(float2*)&ex[r2 * EX_PITCH + col];
            acc[nn][0] += v1.x; acc[nn][1] += v1.y;
            acc[nn][2] += v2.x; acc[nn][3] += v2.y;
        }

        if (mid) {
            float inv1 = 1.0f / ls1, inv2 = 1.0f / ls2;
#pragma unroll
            for (int nn = 0; nn < 8; nn++) {
                int col = nn * 8 + (lane & 3) * 2;
                size_t o1 = ((size_t)(b * 4096 + qb * 64 + r1)) * 512 + h * 64 + col;
                size_t o2 = ((size_t)(b * 4096 + qb * 64 + r2)) * 512 + h * 64 + col;
                uint32_t hi, lo;
                split2(acc[nn][0] * inv1, acc[nn][1] * inv1, hi, lo);
                *(uint32_t*)&g_xhi[o1] = hi; *(uint32_t*)&g_xlo[o1] = lo;
                split2(acc[nn][2] * inv2, acc[nn][3] * inv2, hi, lo);
                *(uint32_t*)&g_xhi[o2] = hi; *(uint32_t*)&g_xlo[o2] = lo;
            }
        } else {
            int slot = (bh * 4 + di) * 8 + chunk;
            float* p = g_part + (size_t)slot * SLOT_F;
#pragma unroll
            for (int nn = 0; nn < 8; nn++) {
                int col = nn * 8 + (lane & 3) * 2;
                *(float2*)&p[r1 * 64 + col] = make_float2(acc[nn][0], acc[nn][1]);
                *(float2*)&p[r2 * 64 + col] = make_float2(acc[nn][2], acc[nn][3]);
            }
            if ((lane & 3) == 0) {
                p[4096 + r1] = ls1;
                p[4096 + r2] = ls2;
            }
        }
    }
}

// ---------------------------------------------------------------------------
// Combine 8 dense split-K partials (plain sums, no max) -> hi/lo bf16 ctx
// ---------------------------------------------------------------------------
__global__ __launch_bounds__(256) void combine_kernel()
{
    int g  = blockIdx.x;
    int bh = g >> 2, di = g & 3;
    int qb = (di < 2) ? di : (60 + di);
    int b  = bh >> 3, h = bh & 7;
    int t   = threadIdx.x;
    int row = t & 63;
    int c0  = (t >> 6) * 16;

    const float* base = g_part + (size_t)(g * 8) * SLOT_F;
    float L = 0.f;
#pragma unroll
    for (int s = 0; s < 8; s++) L += base[s*SLOT_F + 4096 + row];
    float inv = 1.0f / L;

    float o[16];
#pragma unroll
    for (int c = 0; c < 16; c++) o[c] = 0.f;
#pragma unroll
    for (int s = 0; s < 8; s++) {
        const float* pa = base + s*SLOT_F + row*64 + c0;
#pragma unroll
        for (int c4 = 0; c4 < 4; c4++) {
            float4 v4 = *(const float4*)&pa[c4*4];
            o[c4*4+0] += v4.x; o[c4*4+1] += v4.y;
            o[c4*4+2] += v4.z; o[c4*4+3] += v4.w;
        }
    }
    size_t dst = ((size_t)(b * 4096 + qb * 64 + row)) * 512 + h * 64 + c0;
#pragma unroll
    for (int cp = 0; cp < 8; cp++) {
        uint32_t hi, lo;
        split2(o[cp*2] * inv, o[cp*2+1] * inv, hi, lo);
        *(uint32_t*)&g_xhi[dst + cp*2] = hi;
        *(uint32_t*)&g_xlo[dst + cp*2] = lo;
    }
}

// ---------------------------------------------------------------------------
__global__ __launch_bounds__(256) void ln_kernel(const float* __restrict__ x,
                                                 const float* __restrict__ bo,
                                                 const float* __restrict__ gamma,
                                                 const float* __restrict__ beta,
                                                 float* __restrict__ out)
{
    int row = blockIdx.x;
    int t = threadIdx.x;
    size_t base = (size_t)row * 512;
    float h0 = g_h[base + t]       + bo[t]       + x[base + t];
    float h1 = g_h[base + t + 256] + bo[t + 256] + x[base + t + 256];
    float s = h0 + h1;
    float q = h0*h0 + h1*h1;
#pragma unroll
    for (int m = 16; m >= 1; m >>= 1) {
        s += __shfl_xor_sync(0xffffffffu, s, m);
        q += __shfl_xor_sync(0xffffffffu, q, m);
    }
    __shared__ float ss[8], qq[8];
    int w = t >> 5;
    if ((t & 31) == 0) { ss[w] = s; qq[w] = q; }
    __syncthreads();
    float S2 = 0.f, Q2 = 0.f;
#pragma unroll
    for (int i = 0; i < 8; i++) { S2 += ss[i]; Q2 += qq[i]; }
    float mu  = S2 * (1.0f / 512.0f);
    float var = Q2 * (1.0f / 512.0f) - mu * mu;
    float inv = rsqrtf(var + 1e-12f);
    out[base + t]       = (h0 - mu) * inv * gamma[t]       + beta[t];
    out[base + t + 256] = (h1 - mu) * inv * gamma[t + 256] + beta[t + 256];
}

// ---------------------------------------------------------------------------
extern "C" void kernel_launch(void* const* d_in, const int* in_sizes, int n_in,
                              void* d_out, int out_size)
{
    const float* x     = (const float*)d_in[0];
    const float* mask  = (const float*)d_in[1];
    const int*   rb    = (const int*)  d_in[2];
    const float* Wq    = (const float*)d_in[3];
    const float* Wk    = (const float*)d_in[4];
    const float* Wv    = (const float*)d_in[5];
    const float* Wo    = (const float*)d_in[6];
    const float* bo    = (const float*)d_in[7];
    const float* gamma = (const float*)d_in[8];
    const float* beta  = (const float*)d_in[9];
    float* out = (float*)d_out;

    float* hp;
    __nv_bfloat16 *xh, *xl, *wth, *wtl;
    cudaGetSymbolAddress((void**)&hp, g_h);
    cudaGetSymbolAddress((void**)&xh, g_xhi);
    cudaGetSymbolAddress((void**)&xl, g_xlo);
    cudaGetSymbolAddress((void**)&wth, g_wthi);
    cudaGetSymbolAddress((void**)&wtl, g_wtlo);

    cudaFuncSetAttribute(gemm_hmma, cudaFuncAttributeMaxDynamicSharedMemorySize, GEMM_SMEM);
    cudaFuncSetAttribute(gemm_qkv,  cudaFuncAttributeMaxDynamicSharedMemorySize, GEMM_SMEM);
    cudaFuncSetAttribute(attn_hmma, cudaFuncAttributeMaxDynamicSharedMemorySize, ATT_SMEM);

    conv_x<<<NROWS, 256>>>(x, xh, xl);
    dim3 wtg(16, 16, 4), wtb(32, 8);
    conv_wt4<<<wtg, wtb>>>(Wq, Wk, Wv, Wo, wth, wtl);

    dim3 gq(12, 64);                         // 1536/128 x 8192/128
    gemm_qkv<<<gq, 256, GEMM_SMEM>>>(xh, xl, wth, wtl);

    attn_hmma<<<16 * 92, 256, ATT_SMEM>>>(mask, rb);
    combine_kernel<<<64, 256>>>();

    dim3 go(4, 64);
    gemm_hmma<<<go, 256, GEMM_SMEM>>>(xh, xl, wth + 3*262144, wtl + 3*262144, hp, 1.0f);

    ln_kernel<<<Bb * Ss, 256>>>(x, bo, gamma, beta, out);
}

// round 9
// speedup vs baseline: 4.5928x; 1.2100x over previous
#include <cuda_runtime.h>
#include <cuda_bf16.h>
#include <math.h>
#include <stdint.h>

#define Bb 2
#define Ss 4096
#define Dd 512
#define NROWS (Bb*Ss)      // 8192
#define NEGF -1000000000.0f

// ---------------- scratch (device globals: allocation-free) ----------------
__device__ float g_h[NROWS*Dd];
#define SLOT_F 4224
__device__ float g_part[512 * SLOT_F];
__device__ __align__(16) __nv_bfloat16 g_xhi[NROWS*Dd];
__device__ __align__(16) __nv_bfloat16 g_xlo[NROWS*Dd];
__device__ __align__(16) __nv_bfloat16 g_wthi[4*Dd*Dd];   // W^T x4 (qkv 0..1535, Wo 1536..)
__device__ __align__(16) __nv_bfloat16 g_wtlo[4*Dd*Dd];
// per-head q/k/v: [bh][s][64] plain bf16 (attention runs single-bf16)
__device__ __align__(16) __nv_bfloat16 g_qc[16ULL*4096*64];
__device__ __align__(16) __nv_bfloat16 g_kc[16ULL*4096*64];
__device__ __align__(16) __nv_bfloat16 g_vc[16ULL*4096*64];

// ---------------- PTX helpers (base-target legal) ----------------
__device__ __forceinline__ uint32_t smem_u32(const void* p) {
    return (uint32_t)__cvta_generic_to_shared(p);
}
#define CPASYNC16(dst, src) \
    asm volatile("cp.async.cg.shared.global [%0], [%1], 16;" :: "r"(dst), "l"(src))
#define CPCOMMIT() asm volatile("cp.async.commit_group;" ::: "memory")
#define CPWAIT(n)  asm volatile("cp.async.wait_group %0;" :: "n"(n) : "memory")

#define LDSM_X4(r0, r1, r2, r3, a) \
    asm volatile("ldmatrix.sync.aligned.m8n8.x4.shared.b16 {%0,%1,%2,%3}, [%4];" \
                 : "=r"(r0), "=r"(r1), "=r"(r2), "=r"(r3) : "r"(a))
#define LDSM_X4T(r0, r1, r2, r3, a) \
    asm volatile("ldmatrix.sync.aligned.m8n8.x4.trans.shared.b16 {%0,%1,%2,%3}, [%4];" \
                 : "=r"(r0), "=r"(r1), "=r"(r2), "=r"(r3) : "r"(a))

#define MMA16816(D, A, B0, B1) \
    asm volatile("mma.sync.aligned.m16n8k16.row.col.f32.bf16.bf16.f32 " \
                 "{%0,%1,%2,%3},{%4,%5,%6,%7},{%8,%9},{%0,%1,%2,%3};" \
                 : "+f"((D)[0]), "+f"((D)[1]), "+f"((D)[2]), "+f"((D)[3]) \
                 : "r"((A)[0]), "r"((A)[1]), "r"((A)[2]), "r"((A)[3]), \
                   "r"(B0), "r"(B1))

__device__ __forceinline__ uint32_t pack_hi(float a, float b) {
    __nv_bfloat162 h = __floats2bfloat162_rn(a, b);
    return *(uint32_t*)&h;
}
__device__ __forceinline__ void split2(float a, float b, uint32_t& hi, uint32_t& lo) {
    __nv_bfloat16 ha = __float2bfloat16(a), hb = __float2bfloat16(b);
    float ra = a - __bfloat162float(ha), rb = b - __bfloat162float(hb);
    __nv_bfloat162 H; H.x = ha; H.y = hb;
    __nv_bfloat162 L = __floats2bfloat162_rn(ra, rb);
    hi = *(uint32_t*)&H; lo = *(uint32_t*)&L;
}

// ---------------------------------------------------------------------------
// Conversions
// ---------------------------------------------------------------------------
__global__ __launch_bounds__(256) void conv_x(const float* __restrict__ X,
                                              __nv_bfloat16* __restrict__ Hi,
                                              __nv_bfloat16* __restrict__ Lo)
{
    size_t i0 = (size_t)blockIdx.x * 512 + threadIdx.x;
#pragma unroll
    for (int s = 0; s < 2; s++) {
        size_t i = i0 + s * 256;
        float v = X[i];
        __nv_bfloat16 h = __float2bfloat16(v);
        Hi[i] = h;
        Lo[i] = __float2bfloat16(v - __bfloat162float(h));
    }
}

// All four W[512,512] -> W^T bf16 hi/lo in one launch. grid (16,16,4)
__global__ void conv_wt4(const float* __restrict__ W0, const float* __restrict__ W1,
                         const float* __restrict__ W2, const float* __restrict__ W3,
                         __nv_bfloat16* __restrict__ Th, __nv_bfloat16* __restrict__ Tl)
{
    __shared__ float tile[32][33];
    int z = blockIdx.z;
    const float* W = (z == 0) ? W0 : (z == 1) ? W1 : (z == 2) ? W2 : W3;
    __nv_bfloat16* th = Th + (size_t)z * 262144;
    __nv_bfloat16* tl = Tl + (size_t)z * 262144;
    int n0 = blockIdx.x * 32, k0 = blockIdx.y * 32;
    int tx = threadIdx.x, ty = threadIdx.y;
#pragma unroll
    for (int j = 0; j < 32; j += 8)
        tile[ty + j][tx] = W[(size_t)(k0 + ty + j) * 512 + n0 + tx];
    __syncthreads();
#pragma unroll
    for (int j = 0; j < 32; j += 8) {
        int row = ty + j;
        float v = tile[tx][row];
        __nv_bfloat16 h = __float2bfloat16(v);
        size_t o = (size_t)(n0 + row) * 512 + k0 + tx;
        th[o] = h;
        tl[o] = __float2bfloat16(v - __bfloat162float(h));
    }
}

// ---------------------------------------------------------------------------
// Shared GEMM mainloop (CTA 128x128, BK=64, cp.async double buffer)
// ---------------------------------------------------------------------------
#define GEMM_SMEM 65536

__device__ __forceinline__ void gemm_ld_chunk(const __nv_bfloat16* __restrict__ A,
                                              const __nv_bfloat16* __restrict__ Bt,
                                              int rowBase, int colBase, int k0,
                                              uint32_t Ab, uint32_t Bbuf, int t)
{
#pragma unroll
    for (int it = 0; it < 4; it++) {
        int idx = it * 256 + t;
        int r = idx >> 3, c = idx & 7;
        uint32_t d = Ab + r * 128 + ((c ^ (r & 7)) << 4);
        CPASYNC16(d, &A[(size_t)(rowBase + r) * 512 + k0 + c * 8]);
    }
#pragma unroll
    for (int it = 0; it < 4; it++) {
        int idx = it * 256 + t;
        int r = idx >> 3, c = idx & 7;
        uint32_t d = Bbuf + r * 128 + ((c ^ (r & 7)) << 4);
        CPASYNC16(d, &Bt[(size_t)(colBase + r) * 512 + k0 + c * 8]);
    }
    CPCOMMIT();
}

__device__ __forceinline__ void gemm_mainloop(const __nv_bfloat16* Ahi, const __nv_bfloat16* Alo,
                                              const __nv_bfloat16* Bhi, const __nv_bfloat16* Blo,
                                              int rowBase, int colBase, uint32_t sbase, int t,
                                              float acc[2][8][4])
{
    int w = t >> 5, lane = t & 31;
    int wm = (w & 3) * 32, wn = (w >> 2) * 64;
    int laneA_row = (((lane >> 3) & 1) << 3) + (lane & 7);
    int laneA_ch  = (lane >> 4);
    int laneB_row = ((lane >> 4) << 3) + (lane & 7);
    int laneB_ch  = ((lane >> 3) & 1);

    gemm_ld_chunk(Ahi, Bhi, rowBase, colBase, 0, sbase, sbase + 16384u, t);

    for (int i = 0; i < 24; i++) {
        int buf = i & 1;
        if (i < 23) {
            int j = i + 1, seg = j >> 3, k0 = (j & 7) * 64;
            const __nv_bfloat16* As = (seg < 2)  ? Ahi : Alo;
            const __nv_bfloat16* Bs = (seg == 1) ? Blo : Bhi;
            uint32_t Ab = sbase + (buf ? 0u : 32768u);
            gemm_ld_chunk(As, Bs, rowBase, colBase, k0, Ab, Ab + 16384u, t);
            CPWAIT(1);
        } else {
            CPWAIT(0);
        }
        __syncthreads();

        uint32_t Ab = sbase + (buf ? 32768u : 0u);
        uint32_t Bbuf = Ab + 16384u;
#pragma unroll
        for (int ks = 0; ks < 4; ks++) {
            uint32_t afr[2][4];
#pragma unroll
            for (int mt = 0; mt < 2; mt++) {
                int row = wm + mt * 16 + laneA_row;
                int ch  = ks * 2 + laneA_ch;
                uint32_t a = Ab + row * 128 + ((ch ^ (row & 7)) << 4);
                LDSM_X4(afr[mt][0], afr[mt][1], afr[mt][2], afr[mt][3], a);
            }
#pragma unroll
            for (int p = 0; p < 4; p++) {
                int row = wn + p * 16 + laneB_row;
                int ch  = ks * 2 + laneB_ch;
                uint32_t a = Bbuf + row * 128 + ((ch ^ (row & 7)) << 4);
                uint32_t b0, b1, b2, b3;
                LDSM_X4(b0, b1, b2, b3, a);
#pragma unroll
                for (int mt = 0; mt < 2; mt++) {
                    MMA16816(acc[mt][p*2],   afr[mt], b0, b1);
                    MMA16816(acc[mt][p*2+1], afr[mt], b2, b3);
                }
            }
        }
        __syncthreads();
    }
}

// Generic GEMM: Y fp32, stride 512
__global__ __launch_bounds__(256, 2)
void gemm_hmma(const __nv_bfloat16* __restrict__ Ahi,
               const __nv_bfloat16* __restrict__ Alo,
               const __nv_bfloat16* __restrict__ Bhi,
               const __nv_bfloat16* __restrict__ Blo,
               float* __restrict__ Y, float alpha)
{
    extern __shared__ __align__(128) char sm[];
    uint32_t sbase = smem_u32(sm);
    int t = threadIdx.x, w = t >> 5, lane = t & 31;
    int rowBase = blockIdx.y * 128, colBase = blockIdx.x * 128;
    int wm = (w & 3) * 32, wn = (w >> 2) * 64;

    float acc[2][8][4];
#pragma unroll
    for (int mt = 0; mt < 2; mt++)
#pragma unroll
        for (int nt = 0; nt < 8; nt++)
#pragma unroll
            for (int e = 0; e < 4; e++) acc[mt][nt][e] = 0.f;

    gemm_mainloop(Ahi, Alo, Bhi, Blo, rowBase, colBase, sbase, t, acc);

#pragma unroll
    for (int mt = 0; mt < 2; mt++)
#pragma unroll
        for (int nt = 0; nt < 8; nt++) {
            float* a4 = acc[mt][nt];
            int r0 = rowBase + wm + mt * 16 + (lane >> 2);
            int c0 = colBase + wn + nt * 8 + (lane & 3) * 2;
            *(float2*)&Y[(size_t)r0 * 512 + c0] = make_float2(a4[0]*alpha, a4[1]*alpha);
            *(float2*)&Y[(size_t)(r0+8) * 512 + c0] = make_float2(a4[2]*alpha, a4[3]*alpha);
        }
}

// QKV GEMM: B rows span 1536 (Wq|Wk|Wv ^T). Epilogue -> per-head plain bf16
// into [bh][s][64] (q scaled by 0.125).
__global__ __launch_bounds__(256, 2)
void gemm_qkv(const __nv_bfloat16* __restrict__ Ahi,
              const __nv_bfloat16* __restrict__ Alo,
              const __nv_bfloat16* __restrict__ Bhi,
              const __nv_bfloat16* __restrict__ Blo)
{
    extern __shared__ __align__(128) char sm[];
    uint32_t sbase = smem_u32(sm);
    int t = threadIdx.x, w = t >> 5, lane = t & 31;
    int rowBase = blockIdx.y * 128, colBase = blockIdx.x * 128;
    int wm = (w & 3) * 32, wn = (w >> 2) * 64;

    float acc[2][8][4];
#pragma unroll
    for (int mt = 0; mt < 2; mt++)
#pragma unroll
        for (int nt = 0; nt < 8; nt++)
#pragma unroll
            for (int e = 0; e < 4; e++) acc[mt][nt][e] = 0.f;

    gemm_mainloop(Ahi, Alo, Bhi, Blo, rowBase, colBase, sbase, t, acc);

    int tensor = colBase >> 9;
    float alpha = (tensor == 0) ? 0.125f : 1.0f;
    __nv_bfloat16* dst = (tensor == 0) ? g_qc : (tensor == 1) ? g_kc : g_vc;

#pragma unroll
    for (int mt = 0; mt < 2; mt++)
#pragma unroll
        for (int nt = 0; nt < 8; nt++) {
            float* a4 = acc[mt][nt];
            int r0 = rowBase + wm + mt * 16 + (lane >> 2);
            int cc = (colBase & 511) + wn + nt * 8 + (lane & 3) * 2;
            int hh = cc >> 6, dd = cc & 63;
            int b = r0 >> 12, s = r0 & 4095;
            size_t off = ((size_t)((b << 3) + hh) * 4096 + s) * 64 + dd;
            *(uint32_t*)&dst[off] = pack_hi(a4[0]*alpha, a4[1]*alpha);
            *(uint32_t*)&dst[off + 8ULL*64] = pack_hi(a4[2]*alpha, a4[3]*alpha);
        }
}

// ---------------------------------------------------------------------------
// HMMA attention, single-bf16 q/k/v (fp32 accum), no-max softmax,
// register-resident p. Tiles [64][64] bf16, pitch 128B, chunk swizzle.
// smem: QS 8K | KS0/1 16K | VS0/1 16K | EX 16.9K | km 512 | redL 512
// ---------------------------------------------------------------------------
#define OFF_KS 8192
#define OFF_VS 24576
#define OFF_EX 40960
#define EX_PITCH 66
#define OFF_KM 57856
#define OFF_RL 58368
#define ATT_SMEM 58880

__device__ __forceinline__ int kb_of(bool mid, int qb, int chunk, int itk,
                                     const int* __restrict__ rand_blocks)
{
    if (!mid) return chunk * 8 + itk;
    if (itk < 3) return qb - 1 + itk;
    if (itk == 3) return 0;
    if (itk == 4) return 63;
    return rand_blocks[(qb - 2) * 3 + (itk - 5)];
}

__device__ __forceinline__ void attn_prefetch_kv(int bh, int kb, uint32_t KSb,
                                                 uint32_t VSb, int t)
{
    size_t koff = ((size_t)bh * 4096 + kb * 64) * 64;
#pragma unroll
    for (int it = 0; it < 2; it++) {
        int idx = it * 256 + t;
        int r = idx >> 3, c = idx & 7;
        CPASYNC16(KSb + r * 128 + ((c ^ (r & 7)) << 4), &g_kc[koff + r * 64 + c * 8]);
    }
#pragma unroll
    for (int it = 0; it < 2; it++) {
        int idx = it * 256 + t;
        int r = idx >> 3, c = idx & 7;
        CPASYNC16(VSb + r * 128 + ((c ^ (r & 7)) << 4), &g_vc[koff + r * 64 + c * 8]);
    }
    CPCOMMIT();
}

__global__ __launch_bounds__(256, 2)
void attn_hmma(const float* __restrict__ mask, const int* __restrict__ rand_blocks)
{
    extern __shared__ __align__(128) char sm[];
    uint32_t sb = smem_u32(sm);
    const uint32_t QS = sb;
    float* km   = (float*)(sm + OFF_KM);    // [2][64]
    float* redL = (float*)(sm + OFF_RL);
    float* ex   = (float*)(sm + OFF_EX);    // [64][EX_PITCH]

    int t = threadIdx.x, w = t >> 5, lane = t & 31;
    int wm = (w & 3) * 16;
    int wni = w >> 2;
    int wn  = wni * 32;

    int u  = blockIdx.x % 92;
    int bh = blockIdx.x / 92;
    int b  = bh >> 3, h = bh & 7;

    bool mid = (u < 60);
    int qb, chunk = 0, di = 0;
    if (mid) { qb = u + 2; }
    else {
        int d = u - 60;
        di = d >> 3; chunk = d & 7;
        qb = (di < 2) ? di : (60 + di);
    }

    // ---- prologue: Q + K0/V0 via cp.async (one group), km[0] ----
    {
        size_t qoff = ((size_t)bh * 4096 + qb * 64) * 64;
#pragma unroll
        for (int it = 0; it < 2; it++) {
            int idx = it * 256 + t;
            int r = idx >> 3, c = idx & 7;
            CPASYNC16(QS + r * 128 + ((c ^ (r & 7)) << 4), &g_qc[qoff + r * 64 + c * 8]);
        }
        int kb0 = kb_of(mid, qb, chunk, 0, rand_blocks);
        attn_prefetch_kv(bh, kb0, sb + OFF_KS, sb + OFF_VS, t);  // commits Q+K0+V0
        if (t < 64) km[t] = mask[b * 4096 + kb0 * 64 + t];
    }

    int r1 = wm + (lane >> 2), r2 = r1 + 8;
    float mq1 = mask[b * 4096 + qb * 64 + r1];
    float mq2 = mask[b * 4096 + qb * 64 + r2];

    float acc[8][4];
#pragma unroll
    for (int nn = 0; nn < 8; nn++)
#pragma unroll
        for (int e = 0; e < 4; e++) acc[nn][e] = 0.f;
    float ls1 = 0.f, ls2 = 0.f;

    int laneA_row = (((lane >> 3) & 1) << 3) + (lane & 7);
    int laneA_ch  = lane >> 4;
    int laneB_row = ((lane >> 4) << 3) + (lane & 7);
    int laneB_ch  = (lane >> 3) & 1;
    int laneV_row = lane & 15;
    int laneV_g   = lane >> 4;

    uint32_t qh[4][4];   // hoisted Q fragments (one per k16 step)

    for (int itk = 0; itk < 8; itk++) {
        int buf = itk & 1;
        bool band = mid && (itk < 3);

        __syncthreads();   // buf^1 tiles fully consumed (prev-prev iter)
        if (itk < 7) {
            int kbn = kb_of(mid, qb, chunk, itk + 1, rand_blocks);
            attn_prefetch_kv(bh, kbn, sb + OFF_KS + (buf ^ 1) * 8192,
                             sb + OFF_VS + (buf ^ 1) * 8192, t);
            if (t < 64) km[(buf ^ 1) * 64 + t] = mask[b * 4096 + kbn * 64 + t];
            CPWAIT(1);
        } else {
            CPWAIT(0);
        }
        __syncthreads();   // current buf visible

        if (itk == 0) {
            int row = wm + laneA_row;
#pragma unroll
            for (int ks = 0; ks < 4; ks++) {
                int ch = ks * 2 + laneA_ch;
                LDSM_X4(qh[ks][0], qh[ks][1], qh[ks][2], qh[ks][3],
                        QS + row * 128 + ((ch ^ (row & 7)) << 4));
            }
        }

        uint32_t KSb = sb + OFF_KS + buf * 8192;
        uint32_t VSb = sb + OFF_VS + buf * 8192;
        const float* kmask_s = km + buf * 64;

        // ---- QK (single bf16 term) ----
        float sc[4][4];
#pragma unroll
        for (int nt = 0; nt < 4; nt++)
#pragma unroll
            for (int e = 0; e < 4; e++) sc[nt][e] = 0.f;

#pragma unroll
        for (int ks = 0; ks < 4; ks++) {
            int kc2 = ks * 2;
#pragma unroll
            for (int g = 0; g < 2; g++) {
                uint32_t kh[4];
                int row = wn + g * 16 + laneB_row;
                int ch = kc2 + laneB_ch;
                LDSM_X4(kh[0], kh[1], kh[2], kh[3],
                        KSb + row * 128 + ((ch ^ (row & 7)) << 4));
                MMA16816(sc[g*2],   qh[ks], kh[0], kh[1]);
                MMA16816(sc[g*2+1], qh[ks], kh[2], kh[3]);
            }
        }

        // ---- mask ----
#pragma unroll
        for (int nt = 0; nt < 4; nt++) {
            int col = wn + nt * 8 + (lane & 3) * 2;
            float mk0 = kmask_s[col], mk1 = kmask_s[col + 1];
            float m00 = band ? mk0 * mq1 : mk0;
            float m01 = band ? mk1 * mq1 : mk1;
            float m10 = band ? mk0 * mq2 : mk0;
            float m11 = band ? mk1 * mq2 : mk1;
            sc[nt][0] += (1.0f - m00) * NEGF;
            sc[nt][1] += (1.0f - m01) * NEGF;
            sc[nt][2] += (1.0f - m10) * NEGF;
            sc[nt][3] += (1.0f - m11) * NEGF;
        }

        // ---- exp (no max: scores bounded; masked underflow to 0), bf16 pack ----
        uint32_t aph[2][4];
#pragma unroll
        for (int nt = 0; nt < 4; nt++) {
            float p00 = __expf(sc[nt][0]), p01 = __expf(sc[nt][1]);
            float p10 = __expf(sc[nt][2]), p11 = __expf(sc[nt][3]);
            ls1 += p00 + p01; ls2 += p10 + p11;
            int j = nt >> 1, hf = (nt & 1) * 2;
            aph[j][hf]     = pack_hi(p00, p01);
            aph[j][hf + 1] = pack_hi(p10, p11);
        }

        // ---- PV (single bf16 term; k = own 32 score-cols) ----
#pragma unroll
        for (int j = 0; j < 2; j++) {
            int vrow = wn + j * 16 + laneV_row;
            uint32_t vbase = VSb + vrow * 128;
            int sw = (vrow & 7) << 4;
#pragma unroll
            for (int np = 0; np < 4; np++) {
                uint32_t vh4[4];
                int ch = np * 2 + laneV_g;
                LDSM_X4T(vh4[0], vh4[1], vh4[2], vh4[3], vbase + ((ch << 4) ^ sw));
                MMA16816(acc[np*2],   aph[j], vh4[0], vh4[1]);
                MMA16816(acc[np*2+1], aph[j], vh4[2], vh4[3]);
            }
        }
    }

    // ---- final ls combine: quad shfl + cross-half smem ----
    ls1 += __shfl_xor_sync(0xffffffffu, ls1, 1);
    ls1 += __shfl_xor_sync(0xffffffffu, ls1, 2);
    ls2 += __shfl_xor_sync(0xffffffffu, ls2, 1);
    ls2 += __shfl_xor_sync(0xffffffffu, ls2, 2);
    if ((lane & 3) == 0) {
        redL[wni * 64 + r1] = ls1;
        redL[wni * 64 + r2] = ls2;
    }
    __syncthreads();
    ls1 = redL[r1] + redL[64 + r1];
    ls2 = redL[r2] + redL[64 + r2];

    // ---- cross-half acc reduction: half 1 -> smem, half 0 adds ----
    if (wni == 1) {
#pragma unroll
        for (int nn = 0; nn < 8; nn++) {
            int col = nn * 8 + (lane & 3) * 2;
            *(float2*)&ex[r1 * EX_PITCH + col] = make_float2(acc[nn][0], acc[nn][1]);
            *(float2*)&ex[r2 * EX_PITCH + col] = make_float2(acc[nn][2], acc[nn][3]);
        }
    }
    __syncthreads();
    if (wni == 0) {
#pragma unroll
        for (int nn = 0; nn < 8; nn++) {
            int col = nn * 8 + (lane & 3) * 2;
            float2 v1 = *(float2*)&ex[r1 * EX_PITCH + col];
            float2 v2 = *(float2*)&ex[r2 * EX_PITCH + col];
            acc[nn][0] += v1.x; acc[nn][1] += v1.y;
            acc[nn][2] += v2.x; acc[nn][3] += v2.y;
        }

        if (mid) {
            float inv1 = 1.0f / ls1, inv2 = 1.0f / ls2;
#pragma unroll
            for (int nn = 0; nn < 8; nn++) {
                int col = nn * 8 + (lane & 3) * 2;
                size_t o1 = ((size_t)(b * 4096 + qb * 64 + r1)) * 512 + h * 64 + col;
                size_t o2 = ((size_t)(b * 4096 + qb * 64 + r2)) * 512 + h * 64 + col;
                uint32_t hi, lo;
                split2(acc[nn][0] * inv1, acc[nn][1] * inv1, hi, lo);
                *(uint32_t*)&g_xhi[o1] = hi; *(uint32_t*)&g_xlo[o1] = lo;
                split2(acc[nn][2] * inv2, acc[nn][3] * inv2, hi, lo);
                *(uint32_t*)&g_xhi[o2] = hi; *(uint32_t*)&g_xlo[o2] = lo;
            }
        } else {
            int slot = (bh * 4 + di) * 8 + chunk;
            float* p = g_part + (size_t)slot * SLOT_F;
#pragma unroll
            for (int nn = 0; nn < 8; nn++) {
                int col = nn * 8 + (lane & 3) * 2;
                *(float2*)&p[r1 * 64 + col] = make_float2(acc[nn][0], acc[nn][1]);
                *(float2*)&p[r2 * 64 + col] = make_float2(acc[nn][2], acc[nn][3]);
            }
            if ((lane & 3) == 0) {
                p[4096 + r1] = ls1;
                p[4096 + r2] = ls2;
            }
        }
    }
}

// ---------------------------------------------------------------------------
// Combine 8 dense split-K partials (plain sums, no max) -> hi/lo bf16 ctx
// ---------------------------------------------------------------------------
__global__ __launch_bounds__(256) void combine_kernel()
{
    int g  = blockIdx.x;
    int bh = g >> 2, di = g & 3;
    int qb = (di < 2) ? di : (60 + di);
    int b  = bh >> 3, h = bh & 7;
    int t   = threadIdx.x;
    int row = t & 63;
    int c0  = (t >> 6) * 16;

    const float* base = g_part + (size_t)(g * 8) * SLOT_F;
    float L = 0.f;
#pragma unroll
    for (int s = 0; s < 8; s++) L += base[s*SLOT_F + 4096 + row];
    float inv = 1.0f / L;

    float o[16];
#pragma unroll
    for (int c = 0; c < 16; c++) o[c] = 0.f;
#pragma unroll
    for (int s = 0; s < 8; s++) {
        const float* pa = base + s*SLOT_F + row*64 + c0;
#pragma unroll
        for (int c4 = 0; c4 < 4; c4++) {
            float4 v4 = *(const float4*)&pa[c4*4];
            o[c4*4+0] += v4.x; o[c4*4+1] += v4.y;
            o[c4*4+2] += v4.z; o[c4*4+3] += v4.w;
        }
    }
    size_t dst = ((size_t)(b * 4096 + qb * 64 + row)) * 512 + h * 64 + c0;
#pragma unroll
    for (int cp = 0; cp < 8; cp++) {
        uint32_t hi, lo;
        split2(o[cp*2] * inv, o[cp*2+1] * inv, hi, lo);
        *(uint32_t*)&g_xhi[dst + cp*2] = hi;
        *(uint32_t*)&g_xlo[dst + cp*2] = lo;
    }
}

// ---------------------------------------------------------------------------
__global__ __launch_bounds__(256) void ln_kernel(const float* __restrict__ x,
                                                 const float* __restrict__ bo,
                                                 const float* __restrict__ gamma,
                                                 const float* __restrict__ beta,
                                                 float* __restrict__ out)
{
    int row = blockIdx.x;
    int t = threadIdx.x;
    size_t base = (size_t)row * 512;
    float h0 = g_h[base + t]       + bo[t]       + x[base + t];
    float h1 = g_h[base + t + 256] + bo[t + 256] + x[base + t + 256];
    float s = h0 + h1;
    float q = h0*h0 + h1*h1;
#pragma unroll
    for (int m = 16; m >= 1; m >>= 1) {
        s += __shfl_xor_sync(0xffffffffu, s, m);
        q += __shfl_xor_sync(0xffffffffu, q, m);
    }
    __shared__ float ss[8], qq[8];
    int w = t >> 5;
    if ((t & 31) == 0) { ss[w] = s; qq[w] = q; }
    __syncthreads();
    float S2 = 0.f, Q2 = 0.f;
#pragma unroll
    for (int i = 0; i < 8; i++) { S2 += ss[i]; Q2 += qq[i]; }
    float mu  = S2 * (1.0f / 512.0f);
    float var = Q2 * (1.0f / 512.0f) - mu * mu;
    float inv = rsqrtf(var + 1e-12f);
    out[base + t]       = (h0 - mu) * inv * gamma[t]       + beta[t];
    out[base + t + 256] = (h1 - mu) * inv * gamma[t + 256] + beta[t + 256];
}

// ---------------------------------------------------------------------------
extern "C" void kernel_launch(void* const* d_in, const int* in_sizes, int n_in,
                              void* d_out, int out_size)
{
    const float* x     = (const float*)d_in[0];
    const float* mask  = (const float*)d_in[1];
    const int*   rb    = (const int*)  d_in[2];
    const float* Wq    = (const float*)d_in[3];
    const float* Wk    = (const float*)d_in[4];
    const float* Wv    = (const float*)d_in[5];
    const float* Wo    = (const float*)d_in[6];
    const float* bo    = (const float*)d_in[7];
    const float* gamma = (const float*)d_in[8];
    const float* beta  = (const float*)d_in[9];
    float* out = (float*)d_out;

    float* hp;
    __nv_bfloat16 *xh, *xl, *wth, *wtl;
    cudaGetSymbolAddress((void**)&hp, g_h);
    cudaGetSymbolAddress((void**)&xh, g_xhi);
    cudaGetSymbolAddress((void**)&xl, g_xlo);
    cudaGetSymbolAddress((void**)&wth, g_wthi);
    cudaGetSymbolAddress((void**)&wtl, g_wtlo);

    cudaFuncSetAttribute(gemm_hmma, cudaFuncAttributeMaxDynamicSharedMemorySize, GEMM_SMEM);
    cudaFuncSetAttribute(gemm_qkv,  cudaFuncAttributeMaxDynamicSharedMemorySize, GEMM_SMEM);
    cudaFuncSetAttribute(attn_hmma, cudaFuncAttributeMaxDynamicSharedMemorySize, ATT_SMEM);

    conv_x<<<NROWS, 256>>>(x, xh, xl);
    dim3 wtg(16, 16, 4), wtb(32, 8);
    conv_wt4<<<wtg, wtb>>>(Wq, Wk, Wv, Wo, wth, wtl);

    dim3 gq(12, 64);                         // 1536/128 x 8192/128
    gemm_qkv<<<gq, 256, GEMM_SMEM>>>(xh, xl, wth, wtl);

    attn_hmma<<<16 * 92, 256, ATT_SMEM>>>(mask, rb);
    combine_kernel<<<64, 256>>>();

    dim3 go(4, 64);
    gemm_hmma<<<go, 256, GEMM_SMEM>>>(xh, xl, wth + 3*262144, wtl + 3*262144, hp, 1.0f);

    ln_kernel<<<Bb * Ss, 256>>>(x, bo, gamma, beta, out);
}

// round 10
// speedup vs baseline: 7.5168x; 1.6366x over previous
#include <cuda_runtime.h>
#include <cuda_bf16.h>
#include <math.h>
#include <stdint.h>

#define Bb 2
#define Ss 4096
#define Dd 512
#define NROWS (Bb*Ss)      // 8192
#define NEGF -1000000000.0f

// ---------------- scratch (device globals: allocation-free) ----------------
__device__ float g_h[NROWS*Dd];
#define SLOT_F 4224
__device__ float g_part[512 * SLOT_F];
__device__ __align__(16) __nv_bfloat16 g_xb[NROWS*Dd];    // x bf16, later ctx bf16
__device__ __align__(16) __nv_bfloat16 g_wtb[4*Dd*Dd];    // W^T bf16 x4 (qkv 0..1535, Wo 1536..)
// per-head q/k/v: [bh][s][64] plain bf16
__device__ __align__(16) __nv_bfloat16 g_qc[16ULL*4096*64];
__device__ __align__(16) __nv_bfloat16 g_kc[16ULL*4096*64];
__device__ __align__(16) __nv_bfloat16 g_vc[16ULL*4096*64];

// ---------------- PTX helpers (base-target legal) ----------------
__device__ __forceinline__ uint32_t smem_u32(const void* p) {
    return (uint32_t)__cvta_generic_to_shared(p);
}
#define CPASYNC16(dst, src) \
    asm volatile("cp.async.cg.shared.global [%0], [%1], 16;" :: "r"(dst), "l"(src))
#define CPCOMMIT() asm volatile("cp.async.commit_group;" ::: "memory")
#define CPWAIT(n)  asm volatile("cp.async.wait_group %0;" :: "n"(n) : "memory")

#define LDSM_X4(r0, r1, r2, r3, a) \
    asm volatile("ldmatrix.sync.aligned.m8n8.x4.shared.b16 {%0,%1,%2,%3}, [%4];" \
                 : "=r"(r0), "=r"(r1), "=r"(r2), "=r"(r3) : "r"(a))
#define LDSM_X4T(r0, r1, r2, r3, a) \
    asm volatile("ldmatrix.sync.aligned.m8n8.x4.trans.shared.b16 {%0,%1,%2,%3}, [%4];" \
                 : "=r"(r0), "=r"(r1), "=r"(r2), "=r"(r3) : "r"(a))

#define MMA16816(D, A, B0, B1) \
    asm volatile("mma.sync.aligned.m16n8k16.row.col.f32.bf16.bf16.f32 " \
                 "{%0,%1,%2,%3},{%4,%5,%6,%7},{%8,%9},{%0,%1,%2,%3};" \
                 : "+f"((D)[0]), "+f"((D)[1]), "+f"((D)[2]), "+f"((D)[3]) \
                 : "r"((A)[0]), "r"((A)[1]), "r"((A)[2]), "r"((A)[3]), \
                   "r"(B0), "r"(B1))

__device__ __forceinline__ uint32_t pack_hi(float a, float b) {
    __nv_bfloat162 h = __floats2bfloat162_rn(a, b);
    return *(uint32_t*)&h;
}

// ---------------------------------------------------------------------------
// Conversions (bf16 only)
// ---------------------------------------------------------------------------
__global__ __launch_bounds__(256) void conv_x(const float* __restrict__ X,
                                              __nv_bfloat16* __restrict__ Hi)
{
    size_t i0 = (size_t)blockIdx.x * 1024 + threadIdx.x * 2;
    float2 v0 = *(const float2*)&X[i0];
    float2 v1 = *(const float2*)&X[i0 + 512];
    *(uint32_t*)&Hi[i0]       = pack_hi(v0.x, v0.y);
    *(uint32_t*)&Hi[i0 + 512] = pack_hi(v1.x, v1.y);
}

// All four W[512,512] -> W^T bf16 in one launch. grid (16,16,4)
__global__ void conv_wt4(const float* __restrict__ W0, const float* __restrict__ W1,
                         const float* __restrict__ W2, const float* __restrict__ W3,
                         __nv_bfloat16* __restrict__ Th)
{
    __shared__ float tile[32][33];
    int z = blockIdx.z;
    const float* W = (z == 0) ? W0 : (z == 1) ? W1 : (z == 2) ? W2 : W3;
    __nv_bfloat16* th = Th + (size_t)z * 262144;
    int n0 = blockIdx.x * 32, k0 = blockIdx.y * 32;
    int tx = threadIdx.x, ty = threadIdx.y;
#pragma unroll
    for (int j = 0; j < 32; j += 8)
        tile[ty + j][tx] = W[(size_t)(k0 + ty + j) * 512 + n0 + tx];
    __syncthreads();
#pragma unroll
    for (int j = 0; j < 32; j += 8) {
        int row = ty + j;
        th[(size_t)(n0 + row) * 512 + k0 + tx] = __float2bfloat16(tile[tx][row]);
    }
}

// ---------------------------------------------------------------------------
// Single-term GEMM mainloop (CTA 128x128, BK=64, K=512 -> 8 chunks, dbl buf)
// ---------------------------------------------------------------------------
#define GEMM_SMEM 65536

__device__ __forceinline__ void gemm_ld_chunk(const __nv_bfloat16* __restrict__ A,
                                              const __nv_bfloat16* __restrict__ Bt,
                                              int rowBase, int colBase, int k0,
                                              uint32_t Ab, uint32_t Bbuf, int t)
{
#pragma unroll
    for (int it = 0; it < 4; it++) {
        int idx = it * 256 + t;
        int r = idx >> 3, c = idx & 7;
        uint32_t d = Ab + r * 128 + ((c ^ (r & 7)) << 4);
        CPASYNC16(d, &A[(size_t)(rowBase + r) * 512 + k0 + c * 8]);
    }
#pragma unroll
    for (int it = 0; it < 4; it++) {
        int idx = it * 256 + t;
        int r = idx >> 3, c = idx & 7;
        uint32_t d = Bbuf + r * 128 + ((c ^ (r & 7)) << 4);
        CPASYNC16(d, &Bt[(size_t)(colBase + r) * 512 + k0 + c * 8]);
    }
    CPCOMMIT();
}

__device__ __forceinline__ void gemm1_mainloop(const __nv_bfloat16* A, const __nv_bfloat16* Bt,
                                               int rowBase, int colBase, uint32_t sbase, int t,
                                               float acc[2][8][4])
{
    int w = t >> 5, lane = t & 31;
    int wm = (w & 3) * 32, wn = (w >> 2) * 64;
    int laneA_row = (((lane >> 3) & 1) << 3) + (lane & 7);
    int laneA_ch  = (lane >> 4);
    int laneB_row = ((lane >> 4) << 3) + (lane & 7);
    int laneB_ch  = ((lane >> 3) & 1);

    gemm_ld_chunk(A, Bt, rowBase, colBase, 0, sbase, sbase + 16384u, t);

    for (int i = 0; i < 8; i++) {
        int buf = i & 1;
        if (i < 7) {
            uint32_t Ab = sbase + (buf ? 0u : 32768u);
            gemm_ld_chunk(A, Bt, rowBase, colBase, (i + 1) * 64, Ab, Ab + 16384u, t);
            CPWAIT(1);
        } else {
            CPWAIT(0);
        }
        __syncthreads();

        uint32_t Ab = sbase + (buf ? 32768u : 0u);
        uint32_t Bbuf = Ab + 16384u;
#pragma unroll
        for (int ks = 0; ks < 4; ks++) {
            uint32_t afr[2][4];
#pragma unroll
            for (int mt = 0; mt < 2; mt++) {
                int row = wm + mt * 16 + laneA_row;
                int ch  = ks * 2 + laneA_ch;
                uint32_t a = Ab + row * 128 + ((ch ^ (row & 7)) << 4);
                LDSM_X4(afr[mt][0], afr[mt][1], afr[mt][2], afr[mt][3], a);
            }
#pragma unroll
            for (int p = 0; p < 4; p++) {
                int row = wn + p * 16 + laneB_row;
                int ch  = ks * 2 + laneB_ch;
                uint32_t a = Bbuf + row * 128 + ((ch ^ (row & 7)) << 4);
                uint32_t b0, b1, b2, b3;
                LDSM_X4(b0, b1, b2, b3, a);
#pragma unroll
                for (int mt = 0; mt < 2; mt++) {
                    MMA16816(acc[mt][p*2],   afr[mt], b0, b1);
                    MMA16816(acc[mt][p*2+1], afr[mt], b2, b3);
                }
            }
        }
        __syncthreads();
    }
}

// Wo GEMM: Y fp32 = A(bf16) @ Bt(bf16)^T
__global__ __launch_bounds__(256, 2)
void gemm_wo(const __nv_bfloat16* __restrict__ A,
             const __nv_bfloat16* __restrict__ Bt,
             float* __restrict__ Y)
{
    extern __shared__ __align__(128) char sm[];
    uint32_t sbase = smem_u32(sm);
    int t = threadIdx.x, w = t >> 5, lane = t & 31;
    int rowBase = blockIdx.y * 128, colBase = blockIdx.x * 128;
    int wm = (w & 3) * 32, wn = (w >> 2) * 64;

    float acc[2][8][4];
#pragma unroll
    for (int mt = 0; mt < 2; mt++)
#pragma unroll
        for (int nt = 0; nt < 8; nt++)
#pragma unroll
            for (int e = 0; e < 4; e++) acc[mt][nt][e] = 0.f;

    gemm1_mainloop(A, Bt, rowBase, colBase, sbase, t, acc);

#pragma unroll
    for (int mt = 0; mt < 2; mt++)
#pragma unroll
        for (int nt = 0; nt < 8; nt++) {
            float* a4 = acc[mt][nt];
            int r0 = rowBase + wm + mt * 16 + (lane >> 2);
            int c0 = colBase + wn + nt * 8 + (lane & 3) * 2;
            *(float2*)&Y[(size_t)r0 * 512 + c0] = make_float2(a4[0], a4[1]);
            *(float2*)&Y[(size_t)(r0+8) * 512 + c0] = make_float2(a4[2], a4[3]);
        }
}

// QKV GEMM: B rows span 1536 (Wq|Wk|Wv ^T). Epilogue -> per-head bf16 [bh][s][64]
__global__ __launch_bounds__(256, 2)
void gemm_qkv(const __nv_bfloat16* __restrict__ A,
              const __nv_bfloat16* __restrict__ Bt)
{
    extern __shared__ __align__(128) char sm[];
    uint32_t sbase = smem_u32(sm);
    int t = threadIdx.x, w = t >> 5, lane = t & 31;
    int rowBase = blockIdx.y * 128, colBase = blockIdx.x * 128;
    int wm = (w & 3) * 32, wn = (w >> 2) * 64;

    float acc[2][8][4];
#pragma unroll
    for (int mt = 0; mt < 2; mt++)
#pragma unroll
        for (int nt = 0; nt < 8; nt++)
#pragma unroll
            for (int e = 0; e < 4; e++) acc[mt][nt][e] = 0.f;

    gemm1_mainloop(A, Bt, rowBase, colBase, sbase, t, acc);

    int tensor = colBase >> 9;
    float alpha = (tensor == 0) ? 0.125f : 1.0f;
    __nv_bfloat16* dst = (tensor == 0) ? g_qc : (tensor == 1) ? g_kc : g_vc;

#pragma unroll
    for (int mt = 0; mt < 2; mt++)
#pragma unroll
        for (int nt = 0; nt < 8; nt++) {
            float* a4 = acc[mt][nt];
            int r0 = rowBase + wm + mt * 16 + (lane >> 2);
            int cc = (colBase & 511) + wn + nt * 8 + (lane & 3) * 2;
            int hh = cc >> 6, dd = cc & 63;
            int b = r0 >> 12, s = r0 & 4095;
            size_t off = ((size_t)((b << 3) + hh) * 4096 + s) * 64 + dd;
            *(uint32_t*)&dst[off] = pack_hi(a4[0]*alpha, a4[1]*alpha);
            *(uint32_t*)&dst[off + 8ULL*64] = pack_hi(a4[2]*alpha, a4[3]*alpha);
        }
}

// ---------------------------------------------------------------------------
// HMMA attention (unchanged core from R9): single-bf16 q/k/v, no-max softmax,
// register-resident p. Ctx written as plain bf16 to g_xb.
// ---------------------------------------------------------------------------
#define OFF_KS 8192
#define OFF_VS 24576
#define OFF_EX 40960
#define EX_PITCH 66
#define OFF_KM 57856
#define OFF_RL 58368
#define ATT_SMEM 58880

__device__ __forceinline__ int kb_of(bool mid, int qb, int chunk, int itk,
                                     const int* __restrict__ rand_blocks)
{
    if (!mid) return chunk * 8 + itk;
    if (itk < 3) return qb - 1 + itk;
    if (itk == 3) return 0;
    if (itk == 4) return 63;
    return rand_blocks[(qb - 2) * 3 + (itk - 5)];
}

__device__ __forceinline__ void attn_prefetch_kv(int bh, int kb, uint32_t KSb,
                                                 uint32_t VSb, int t)
{
    size_t koff = ((size_t)bh * 4096 + kb * 64) * 64;
#pragma unroll
    for (int it = 0; it < 2; it++) {
        int idx = it * 256 + t;
        int r = idx >> 3, c = idx & 7;
        CPASYNC16(KSb + r * 128 + ((c ^ (r & 7)) << 4), &g_kc[koff + r * 64 + c * 8]);
    }
#pragma unroll
    for (int it = 0; it < 2; it++) {
        int idx = it * 256 + t;
        int r = idx >> 3, c = idx & 7;
        CPASYNC16(VSb + r * 128 + ((c ^ (r & 7)) << 4), &g_vc[koff + r * 64 + c * 8]);
    }
    CPCOMMIT();
}

__global__ __launch_bounds__(256, 2)
void attn_hmma(const float* __restrict__ mask, const int* __restrict__ rand_blocks)
{
    extern __shared__ __align__(128) char sm[];
    uint32_t sb = smem_u32(sm);
    const uint32_t QS = sb;
    float* km   = (float*)(sm + OFF_KM);    // [2][64]
    float* redL = (float*)(sm + OFF_RL);
    float* ex   = (float*)(sm + OFF_EX);    // [64][EX_PITCH]

    int t = threadIdx.x, w = t >> 5, lane = t & 31;
    int wm = (w & 3) * 16;
    int wni = w >> 2;
    int wn  = wni * 32;

    int u  = blockIdx.x % 92;
    int bh = blockIdx.x / 92;
    int b  = bh >> 3, h = bh & 7;

    bool mid = (u < 60);
    int qb, chunk = 0, di = 0;
    if (mid) { qb = u + 2; }
    else {
        int d = u - 60;
        di = d >> 3; chunk = d & 7;
        qb = (di < 2) ? di : (60 + di);
    }

    // ---- prologue: Q + K0/V0 via cp.async (one group), km[0] ----
    {
        size_t qoff = ((size_t)bh * 4096 + qb * 64) * 64;
#pragma unroll
        for (int it = 0; it < 2; it++) {
            int idx = it * 256 + t;
            int r = idx >> 3, c = idx & 7;
            CPASYNC16(QS + r * 128 + ((c ^ (r & 7)) << 4), &g_qc[qoff + r * 64 + c * 8]);
        }
        int kb0 = kb_of(mid, qb, chunk, 0, rand_blocks);
        attn_prefetch_kv(bh, kb0, sb + OFF_KS, sb + OFF_VS, t);
        if (t < 64) km[t] = mask[b * 4096 + kb0 * 64 + t];
    }

    int r1 = wm + (lane >> 2), r2 = r1 + 8;
    float mq1 = mask[b * 4096 + qb * 64 + r1];
    float mq2 = mask[b * 4096 + qb * 64 + r2];

    float acc[8][4];
#pragma unroll
    for (int nn = 0; nn < 8; nn++)
#pragma unroll
        for (int e = 0; e < 4; e++) acc[nn][e] = 0.f;
    float ls1 = 0.f, ls2 = 0.f;

    int laneA_row = (((lane >> 3) & 1) << 3) + (lane & 7);
    int laneA_ch  = lane >> 4;
    int laneB_row = ((lane >> 4) << 3) + (lane & 7);
    int laneB_ch  = (lane >> 3) & 1;
    int laneV_row = lane & 15;
    int laneV_g   = lane >> 4;

    uint32_t qh[4][4];

    for (int itk = 0; itk < 8; itk++) {
        int buf = itk & 1;
        bool band = mid && (itk < 3);

        __syncthreads();
        if (itk < 7) {
            int kbn = kb_of(mid, qb, chunk, itk + 1, rand_blocks);
            attn_prefetch_kv(bh, kbn, sb + OFF_KS + (buf ^ 1) * 8192,
                             sb + OFF_VS + (buf ^ 1) * 8192, t);
            if (t < 64) km[(buf ^ 1) * 64 + t] = mask[b * 4096 + kbn * 64 + t];
            CPWAIT(1);
        } else {
            CPWAIT(0);
        }
        __syncthreads();

        if (itk == 0) {
            int row = wm + laneA_row;
#pragma unroll
            for (int ks = 0; ks < 4; ks++) {
                int ch = ks * 2 + laneA_ch;
                LDSM_X4(qh[ks][0], qh[ks][1], qh[ks][2], qh[ks][3],
                        QS + row * 128 + ((ch ^ (row & 7)) << 4));
            }
        }

        uint32_t KSb = sb + OFF_KS + buf * 8192;
        uint32_t VSb = sb + OFF_VS + buf * 8192;
        const float* kmask_s = km + buf * 64;

        // ---- QK ----
        float sc[4][4];
#pragma unroll
        for (int nt = 0; nt < 4; nt++)
#pragma unroll
            for (int e = 0; e < 4; e++) sc[nt][e] = 0.f;

#pragma unroll
        for (int ks = 0; ks < 4; ks++) {
            int kc2 = ks * 2;
#pragma unroll
            for (int g = 0; g < 2; g++) {
                uint32_t kh[4];
                int row = wn + g * 16 + laneB_row;
                int ch = kc2 + laneB_ch;
                LDSM_X4(kh[0], kh[1], kh[2], kh[3],
                        KSb + row * 128 + ((ch ^ (row & 7)) << 4));
                MMA16816(sc[g*2],   qh[ks], kh[0], kh[1]);
                MMA16816(sc[g*2+1], qh[ks], kh[2], kh[3]);
            }
        }

        // ---- mask ----
#pragma unroll
        for (int nt = 0; nt < 4; nt++) {
            int col = wn + nt * 8 + (lane & 3) * 2;
            float mk0 = kmask_s[col], mk1 = kmask_s[col + 1];
            float m00 = band ? mk0 * mq1 : mk0;
            float m01 = band ? mk1 * mq1 : mk1;
            float m10 = band ? mk0 * mq2 : mk0;
            float m11 = band ? mk1 * mq2 : mk1;
            sc[nt][0] += (1.0f - m00) * NEGF;
            sc[nt][1] += (1.0f - m01) * NEGF;
            sc[nt][2] += (1.0f - m10) * NEGF;
            sc[nt][3] += (1.0f - m11) * NEGF;
        }

        // ---- exp + bf16 pack ----
        uint32_t aph[2][4];
#pragma unroll
        for (int nt = 0; nt < 4; nt++) {
            float p00 = __expf(sc[nt][0]), p01 = __expf(sc[nt][1]);
            float p10 = __expf(sc[nt][2]), p11 = __expf(sc[nt][3]);
            ls1 += p00 + p01; ls2 += p10 + p11;
            int j = nt >> 1, hf = (nt & 1) * 2;
            aph[j][hf]     = pack_hi(p00, p01);
            aph[j][hf + 1] = pack_hi(p10, p11);
        }

        // ---- PV ----
#pragma unroll
        for (int j = 0; j < 2; j++) {
            int vrow = wn + j * 16 + laneV_row;
            uint32_t vbase = VSb + vrow * 128;
            int sw = (vrow & 7) << 4;
#pragma unroll
            for (int np = 0; np < 4; np++) {
                uint32_t vh4[4];
                int ch = np * 2 + laneV_g;
                LDSM_X4T(vh4[0], vh4[1], vh4[2], vh4[3], vbase + ((ch << 4) ^ sw));
                MMA16816(acc[np*2],   aph[j], vh4[0], vh4[1]);
                MMA16816(acc[np*2+1], aph[j], vh4[2], vh4[3]);
            }
        }
    }

    // ---- final ls combine ----
    ls1 += __shfl_xor_sync(0xffffffffu, ls1, 1);
    ls1 += __shfl_xor_sync(0xffffffffu, ls1, 2);
    ls2 += __shfl_xor_sync(0xffffffffu, ls2, 1);
    ls2 += __shfl_xor_sync(0xffffffffu, ls2, 2);
    if ((lane & 3) == 0) {
        redL[wni * 64 + r1] = ls1;
        redL[wni * 64 + r2] = ls2;
    }
    __syncthreads();
    ls1 = redL[r1] + redL[64 + r1];
    ls2 = redL[r2] + redL[64 + r2];

    // ---- cross-half acc reduction ----
    if (wni == 1) {
#pragma unroll
        for (int nn = 0; nn < 8; nn++) {
            int col = nn * 8 + (lane & 3) * 2;
            *(float2*)&ex[r1 * EX_PITCH + col] = make_float2(acc[nn][0], acc[nn][1]);
            *(float2*)&ex[r2 * EX_PITCH + col] = make_float2(acc[nn][2], acc[nn][3]);
        }
    }
    __syncthreads();
    if (wni == 0) {
#pragma unroll
        for (int nn = 0; nn < 8; nn++) {
            int col = nn * 8 + (lane & 3) * 2;
            float2 v1 = *(float2*)&ex[r1 * EX_PITCH + col];
            float2 v2 = *(float2*)&ex[r2 * EX_PITCH + col];
            acc[nn][0] += v1.x; acc[nn][1] += v1.y;
            acc[nn][2] += v2.x; acc[nn][3] += v2.y;
        }

        if (mid) {
            float inv1 = 1.0f / ls1, inv2 = 1.0f / ls2;
#pragma unroll
            for (int nn = 0; nn < 8; nn++) {
                int col = nn * 8 + (lane & 3) * 2;
                size_t o1 = ((size_t)(b * 4096 + qb * 64 + r1)) * 512 + h * 64 + col;
                size_t o2 = ((size_t)(b * 4096 + qb * 64 + r2)) * 512 + h * 64 + col;
                *(uint32_t*)&g_xb[o1] = pack_hi(acc[nn][0] * inv1, acc[nn][1] * inv1);
                *(uint32_t*)&g_xb[o2] = pack_hi(acc[nn][2] * inv2, acc[nn][3] * inv2);
            }
        } else {
            int slot = (bh * 4 + di) * 8 + chunk;
            float* p = g_part + (size_t)slot * SLOT_F;
#pragma unroll
            for (int nn = 0; nn < 8; nn++) {
                int col = nn * 8 + (lane & 3) * 2;
                *(float2*)&p[r1 * 64 + col] = make_float2(acc[nn][0], acc[nn][1]);
                *(float2*)&p[r2 * 64 + col] = make_float2(acc[nn][2], acc[nn][3]);
            }
            if ((lane & 3) == 0) {
                p[4096 + r1] = ls1;
                p[4096 + r2] = ls2;
            }
        }
    }
}

// ---------------------------------------------------------------------------
// Combine 8 dense split-K partials (plain sums) -> bf16 ctx
// ---------------------------------------------------------------------------
__global__ __launch_bounds__(256) void combine_kernel()
{
    int g  = blockIdx.x;
    int bh = g >> 2, di = g & 3;
    int qb = (di < 2) ? di : (60 + di);
    int b  = bh >> 3, h = bh & 7;
    int t   = threadIdx.x;
    int row = t & 63;
    int c0  = (t >> 6) * 16;

    const float* base = g_part + (size_t)(g * 8) * SLOT_F;
    float L = 0.f;
#pragma unroll
    for (int s = 0; s < 8; s++) L += base[s*SLOT_F + 4096 + row];
    float inv = 1.0f / L;

    float o[16];
#pragma unroll
    for (int c = 0; c < 16; c++) o[c] = 0.f;
#pragma unroll
    for (int s = 0; s < 8; s++) {
        const float* pa = base + s*SLOT_F + row*64 + c0;
#pragma unroll
        for (int c4 = 0; c4 < 4; c4++) {
            float4 v4 = *(const float4*)&pa[c4*4];
            o[c4*4+0] += v4.x; o[c4*4+1] += v4.y;
            o[c4*4+2] += v4.z; o[c4*4+3] += v4.w;
        }
    }
    size_t dst = ((size_t)(b * 4096 + qb * 64 + row)) * 512 + h * 64 + c0;
#pragma unroll
    for (int cp = 0; cp < 8; cp++)
        *(uint32_t*)&g_xb[dst + cp*2] = pack_hi(o[cp*2] * inv, o[cp*2+1] * inv);
}

// ---------------------------------------------------------------------------
__global__ __launch_bounds__(256) void ln_kernel(const float* __restrict__ x,
                                                 const float* __restrict__ bo,
                                                 const float* __restrict__ gamma,
                                                 const float* __restrict__ beta,
                                                 float* __restrict__ out)
{
    int row = blockIdx.x;
    int t = threadIdx.x;
    size_t base = (size_t)row * 512;
    float h0 = g_h[base + t]       + bo[t]       + x[base + t];
    float h1 = g_h[base + t + 256] + bo[t + 256] + x[base + t + 256];
    float s = h0 + h1;
    float q = h0*h0 + h1*h1;
#pragma unroll
    for (int m = 16; m >= 1; m >>= 1) {
        s += __shfl_xor_sync(0xffffffffu, s, m);
        q += __shfl_xor_sync(0xffffffffu, q, m);
    }
    __shared__ float ss[8], qq[8];
    int w = t >> 5;
    if ((t & 31) == 0) { ss[w] = s; qq[w] = q; }
    __syncthreads();
    float S2 = 0.f, Q2 = 0.f;
#pragma unroll
    for (int i = 0; i < 8; i++) { S2 += ss[i]; Q2 += qq[i]; }
    float mu  = S2 * (1.0f / 512.0f);
    float var = Q2 * (1.0f / 512.0f) - mu * mu;
    float inv = rsqrtf(var + 1e-12f);
    out[base + t]       = (h0 - mu) * inv * gamma[t]       + beta[t];
    out[base + t + 256] = (h1 - mu) * inv * gamma[t + 256] + beta[t + 256];
}

// ---------------------------------------------------------------------------
extern "C" void kernel_launch(void* const* d_in, const int* in_sizes, int n_in,
                              void* d_out, int out_size)
{
    const float* x     = (const float*)d_in[0];
    const float* mask  = (const float*)d_in[1];
    const int*   rb    = (const int*)  d_in[2];
    const float* Wq    = (const float*)d_in[3];
    const float* Wk    = (const float*)d_in[4];
    const float* Wv    = (const float*)d_in[5];
    const float* Wo    = (const float*)d_in[6];
    const float* bo    = (const float*)d_in[7];
    const float* gamma = (const float*)d_in[8];
    const float* beta  = (const float*)d_in[9];
    float* out = (float*)d_out;

    float* hp;
    __nv_bfloat16 *xb, *wtb;
    cudaGetSymbolAddress((void**)&hp, g_h);
    cudaGetSymbolAddress((void**)&xb, g_xb);
    cudaGetSymbolAddress((void**)&wtb, g_wtb);

    cudaFuncSetAttribute(gemm_wo,  cudaFuncAttributeMaxDynamicSharedMemorySize, GEMM_SMEM);
    cudaFuncSetAttribute(gemm_qkv, cudaFuncAttributeMaxDynamicSharedMemorySize, GEMM_SMEM);
    cudaFuncSetAttribute(attn_hmma, cudaFuncAttributeMaxDynamicSharedMemorySize, ATT_SMEM);

    conv_x<<<NROWS / 2, 256>>>(x, xb);
    dim3 wtg(16, 16, 4), wtb2(32, 8);
    conv_wt4<<<wtg, wtb2>>>(Wq, Wk, Wv, Wo, wtb);

    dim3 gq(12, 64);                         // 1536/128 x 8192/128
    gemm_qkv<<<gq, 256, GEMM_SMEM>>>(xb, wtb);

    attn_hmma<<<16 * 92, 256, ATT_SMEM>>>(mask, rb);
    combine_kernel<<<64, 256>>>();

    dim3 go(4, 64);
    gemm_wo<<<go, 256, GEMM_SMEM>>>(xb, wtb + 3*262144, hp);

    ln_kernel<<<Bb * Ss, 256>>>(x, bo, gamma, beta, out);
}

// round 11
// speedup vs baseline: 7.5709x; 1.0072x over previous
#include <cuda_runtime.h>
#include <cuda_bf16.h>
#include <math.h>
#include <stdint.h>

#define Bb 2
#define Ss 4096
#define Dd 512
#define NROWS (Bb*Ss)      // 8192
#define NEGF -1000000000.0f

// ---------------- scratch (device globals: allocation-free) ----------------
__device__ float g_h[NROWS*Dd];
#define SLOT_F 4224
__device__ float g_part[512 * SLOT_F];
__device__ __align__(16) __nv_bfloat16 g_xb[NROWS*Dd];    // x bf16, later ctx bf16
__device__ __align__(16) __nv_bfloat16 g_wtb[4*Dd*Dd];    // W^T bf16 x4
__device__ __align__(16) __nv_bfloat16 g_qc[16ULL*4096*64];
__device__ __align__(16) __nv_bfloat16 g_kc[16ULL*4096*64];
__device__ __align__(16) __nv_bfloat16 g_vc[16ULL*4096*64];

// ---------------- PTX helpers ----------------
__device__ __forceinline__ uint32_t smem_u32(const void* p) {
    return (uint32_t)__cvta_generic_to_shared(p);
}
#define CPASYNC16(dst, src) \
    asm volatile("cp.async.cg.shared.global [%0], [%1], 16;" :: "r"(dst), "l"(src))
#define CPCOMMIT() asm volatile("cp.async.commit_group;" ::: "memory")
#define CPWAIT(n)  asm volatile("cp.async.wait_group %0;" :: "n"(n) : "memory")

#define LDSM_X4(r0, r1, r2, r3, a) \
    asm volatile("ldmatrix.sync.aligned.m8n8.x4.shared.b16 {%0,%1,%2,%3}, [%4];" \
                 : "=r"(r0), "=r"(r1), "=r"(r2), "=r"(r3) : "r"(a))
#define LDSM_X4T(r0, r1, r2, r3, a) \
    asm volatile("ldmatrix.sync.aligned.m8n8.x4.trans.shared.b16 {%0,%1,%2,%3}, [%4];" \
                 : "=r"(r0), "=r"(r1), "=r"(r2), "=r"(r3) : "r"(a))

#define MMA16816(D, A, B0, B1) \
    asm volatile("mma.sync.aligned.m16n8k16.row.col.f32.bf16.bf16.f32 " \
                 "{%0,%1,%2,%3},{%4,%5,%6,%7},{%8,%9},{%0,%1,%2,%3};" \
                 : "+f"((D)[0]), "+f"((D)[1]), "+f"((D)[2]), "+f"((D)[3]) \
                 : "r"((A)[0]), "r"((A)[1]), "r"((A)[2]), "r"((A)[3]), \
                   "r"(B0), "r"(B1))

__device__ __forceinline__ uint32_t pack_hi(float a, float b) {
    __nv_bfloat162 h = __floats2bfloat162_rn(a, b);
    return *(uint32_t*)&h;
}

// ---------------------------------------------------------------------------
// Fused prep: x -> bf16 (CTAs 0..4095) and 4x W -> W^T bf16 (CTAs 4096..5119)
// ---------------------------------------------------------------------------
__global__ __launch_bounds__(256) void prep_kernel(
    const float* __restrict__ X, __nv_bfloat16* __restrict__ Xb,
    const float* __restrict__ W0, const float* __restrict__ W1,
    const float* __restrict__ W2, const float* __restrict__ W3,
    __nv_bfloat16* __restrict__ Th)
{
    int cb = blockIdx.x;
    int t = threadIdx.x;
    if (cb < 4096) {
        size_t i0 = (size_t)cb * 1024 + t * 2;
        float2 v0 = *(const float2*)&X[i0];
        float2 v1 = *(const float2*)&X[i0 + 512];
        *(uint32_t*)&Xb[i0]       = pack_hi(v0.x, v0.y);
        *(uint32_t*)&Xb[i0 + 512] = pack_hi(v1.x, v1.y);
        return;
    }
    __shared__ float tile[32][33];
    int idx = cb - 4096;
    int z = idx >> 8;
    int rest = idx & 255;
    const float* W = (z == 0) ? W0 : (z == 1) ? W1 : (z == 2) ? W2 : W3;
    __nv_bfloat16* th = Th + (size_t)z * 262144;
    int n0 = (rest & 15) * 32, k0 = (rest >> 4) * 32;
    int tx = t & 31, ty = t >> 5;
#pragma unroll
    for (int j = 0; j < 32; j += 8)
        tile[ty + j][tx] = W[(size_t)(k0 + ty + j) * 512 + n0 + tx];
    __syncthreads();
#pragma unroll
    for (int j = 0; j < 32; j += 8) {
        int row = ty + j;
        th[(size_t)(n0 + row) * 512 + k0 + tx] = __float2bfloat16(tile[tx][row]);
    }
}

// ---------------------------------------------------------------------------
// Single-term GEMM mainloop (CTA 128x128, BK=64, K=512 -> 8 chunks, dbl buf)
// ---------------------------------------------------------------------------
#define GEMM_SMEM 65536

__device__ __forceinline__ void gemm_ld_chunk(const __nv_bfloat16* __restrict__ A,
                                              const __nv_bfloat16* __restrict__ Bt,
                                              int rowBase, int colBase, int k0,
                                              uint32_t Ab, uint32_t Bbuf, int t)
{
#pragma unroll
    for (int it = 0; it < 4; it++) {
        int idx = it * 256 + t;
        int r = idx >> 3, c = idx & 7;
        uint32_t d = Ab + r * 128 + ((c ^ (r & 7)) << 4);
        CPASYNC16(d, &A[(size_t)(rowBase + r) * 512 + k0 + c * 8]);
    }
#pragma unroll
    for (int it = 0; it < 4; it++) {
        int idx = it * 256 + t;
        int r = idx >> 3, c = idx & 7;
        uint32_t d = Bbuf + r * 128 + ((c ^ (r & 7)) << 4);
        CPASYNC16(d, &Bt[(size_t)(colBase + r) * 512 + k0 + c * 8]);
    }
    CPCOMMIT();
}

__device__ __forceinline__ void gemm1_mainloop(const __nv_bfloat16* A, const __nv_bfloat16* Bt,
                                               int rowBase, int colBase, uint32_t sbase, int t,
                                               float acc[2][8][4])
{
    int w = t >> 5, lane = t & 31;
    int wm = (w & 3) * 32, wn = (w >> 2) * 64;
    int laneA_row = (((lane >> 3) & 1) << 3) + (lane & 7);
    int laneA_ch  = (lane >> 4);
    int laneB_row = ((lane >> 4) << 3) + (lane & 7);
    int laneB_ch  = ((lane >> 3) & 1);

    gemm_ld_chunk(A, Bt, rowBase, colBase, 0, sbase, sbase + 16384u, t);

    for (int i = 0; i < 8; i++) {
        int buf = i & 1;
        if (i < 7) {
            uint32_t Ab = sbase + (buf ? 0u : 32768u);
            gemm_ld_chunk(A, Bt, rowBase, colBase, (i + 1) * 64, Ab, Ab + 16384u, t);
            CPWAIT(1);
        } else {
            CPWAIT(0);
        }
        __syncthreads();

        uint32_t Ab = sbase + (buf ? 32768u : 0u);
        uint32_t Bbuf = Ab + 16384u;
#pragma unroll
        for (int ks = 0; ks < 4; ks++) {
            uint32_t afr[2][4];
#pragma unroll
            for (int mt = 0; mt < 2; mt++) {
                int row = wm + mt * 16 + laneA_row;
                int ch  = ks * 2 + laneA_ch;
                uint32_t a = Ab + row * 128 + ((ch ^ (row & 7)) << 4);
                LDSM_X4(afr[mt][0], afr[mt][1], afr[mt][2], afr[mt][3], a);
            }
#pragma unroll
            for (int p = 0; p < 4; p++) {
                int row = wn + p * 16 + laneB_row;
                int ch  = ks * 2 + laneB_ch;
                uint32_t a = Bbuf + row * 128 + ((ch ^ (row & 7)) << 4);
                uint32_t b0, b1, b2, b3;
                LDSM_X4(b0, b1, b2, b3, a);
#pragma unroll
                for (int mt = 0; mt < 2; mt++) {
                    MMA16816(acc[mt][p*2],   afr[mt], b0, b1);
                    MMA16816(acc[mt][p*2+1], afr[mt], b2, b3);
                }
            }
        }
        __syncthreads();
    }
}

// Wo GEMM
__global__ __launch_bounds__(256, 2)
void gemm_wo(const __nv_bfloat16* __restrict__ A,
             const __nv_bfloat16* __restrict__ Bt,
             float* __restrict__ Y)
{
    extern __shared__ __align__(128) char sm[];
    uint32_t sbase = smem_u32(sm);
    int t = threadIdx.x, w = t >> 5, lane = t & 31;
    int rowBase = blockIdx.y * 128, colBase = blockIdx.x * 128;
    int wm = (w & 3) * 32, wn = (w >> 2) * 64;

    float acc[2][8][4];
#pragma unroll
    for (int mt = 0; mt < 2; mt++)
#pragma unroll
        for (int nt = 0; nt < 8; nt++)
#pragma unroll
            for (int e = 0; e < 4; e++) acc[mt][nt][e] = 0.f;

    gemm1_mainloop(A, Bt, rowBase, colBase, sbase, t, acc);

#pragma unroll
    for (int mt = 0; mt < 2; mt++)
#pragma unroll
        for (int nt = 0; nt < 8; nt++) {
            float* a4 = acc[mt][nt];
            int r0 = rowBase + wm + mt * 16 + (lane >> 2);
            int c0 = colBase + wn + nt * 8 + (lane & 3) * 2;
            *(float2*)&Y[(size_t)r0 * 512 + c0] = make_float2(a4[0], a4[1]);
            *(float2*)&Y[(size_t)(r0+8) * 512 + c0] = make_float2(a4[2], a4[3]);
        }
}

// QKV GEMM -> per-head bf16 [bh][s][64]
__global__ __launch_bounds__(256, 2)
void gemm_qkv(const __nv_bfloat16* __restrict__ A,
              const __nv_bfloat16* __restrict__ Bt)
{
    extern __shared__ __align__(128) char sm[];
    uint32_t sbase = smem_u32(sm);
    int t = threadIdx.x, w = t >> 5, lane = t & 31;
    int rowBase = blockIdx.y * 128, colBase = blockIdx.x * 128;
    int wm = (w & 3) * 32, wn = (w >> 2) * 64;

    float acc[2][8][4];
#pragma unroll
    for (int mt = 0; mt < 2; mt++)
#pragma unroll
        for (int nt = 0; nt < 8; nt++)
#pragma unroll
            for (int e = 0; e < 4; e++) acc[mt][nt][e] = 0.f;

    gemm1_mainloop(A, Bt, rowBase, colBase, sbase, t, acc);

    int tensor = colBase >> 9;
    float alpha = (tensor == 0) ? 0.125f : 1.0f;
    __nv_bfloat16* dst = (tensor == 0) ? g_qc : (tensor == 1) ? g_kc : g_vc;

#pragma unroll
    for (int mt = 0; mt < 2; mt++)
#pragma unroll
        for (int nt = 0; nt < 8; nt++) {
            float* a4 = acc[mt][nt];
            int r0 = rowBase + wm + mt * 16 + (lane >> 2);
            int cc = (colBase & 511) + wn + nt * 8 + (lane & 3) * 2;
            int hh = cc >> 6, dd = cc & 63;
            int b = r0 >> 12, s = r0 & 4095;
            size_t off = ((size_t)((b << 3) + hh) * 4096 + s) * 64 + dd;
            *(uint32_t*)&dst[off] = pack_hi(a4[0]*alpha, a4[1]*alpha);
            *(uint32_t*)&dst[off + 8ULL*64] = pack_hi(a4[2]*alpha, a4[3]*alpha);
        }
}

// ---------------------------------------------------------------------------
// HMMA attention: 4-stage cp.async ring, ONE barrier per iteration.
// smem: QS 8K | KS[4] 32K | VS[4] 32K | EX 16.9K | km[4] 1K | redL 512
// ---------------------------------------------------------------------------
#define OFF_KS 8192
#define OFF_VS 40960
#define OFF_EX 73728
#define EX_PITCH 66
#define OFF_KM 90624
#define OFF_RL 91648
#define ATT_SMEM 92160

__device__ __forceinline__ int kb_of(bool mid, int qb, int chunk, int itk,
                                     const int* __restrict__ rand_blocks)
{
    if (!mid) return chunk * 8 + itk;
    if (itk < 3) return qb - 1 + itk;
    if (itk == 3) return 0;
    if (itk == 4) return 63;
    return rand_blocks[(qb - 2) * 3 + (itk - 5)];
}

__device__ __forceinline__ void attn_prefetch_kv(int bh, int kb, uint32_t KSb,
                                                 uint32_t VSb, int t)
{
    size_t koff = ((size_t)bh * 4096 + kb * 64) * 64;
#pragma unroll
    for (int it = 0; it < 2; it++) {
        int idx = it * 256 + t;
        int r = idx >> 3, c = idx & 7;
        CPASYNC16(KSb + r * 128 + ((c ^ (r & 7)) << 4), &g_kc[koff + r * 64 + c * 8]);
    }
#pragma unroll
    for (int it = 0; it < 2; it++) {
        int idx = it * 256 + t;
        int r = idx >> 3, c = idx & 7;
        CPASYNC16(VSb + r * 128 + ((c ^ (r & 7)) << 4), &g_vc[koff + r * 64 + c * 8]);
    }
    CPCOMMIT();
}

__global__ __launch_bounds__(256, 2)
void attn_hmma(const float* __restrict__ mask, const int* __restrict__ rand_blocks)
{
    extern __shared__ __align__(128) char sm[];
    uint32_t sb = smem_u32(sm);
    const uint32_t QS = sb;
    float* km   = (float*)(sm + OFF_KM);    // [4][64]
    float* redL = (float*)(sm + OFF_RL);
    float* ex   = (float*)(sm + OFF_EX);    // [64][EX_PITCH]

    int t = threadIdx.x, w = t >> 5, lane = t & 31;
    int wm = (w & 3) * 16;
    int wni = w >> 2;
    int wn  = wni * 32;

    int u  = blockIdx.x % 92;
    int bh = blockIdx.x / 92;
    int b  = bh >> 3, h = bh & 7;

    bool mid = (u < 60);
    int qb, chunk = 0, di = 0;
    if (mid) { qb = u + 2; }
    else {
        int d = u - 60;
        di = d >> 3; chunk = d & 7;
        qb = (di < 2) ? di : (60 + di);
    }

    // ---- prologue: group0 = Q+K0+V0, group1 = K1+V1; km[0], km[1] ----
    {
        size_t qoff = ((size_t)bh * 4096 + qb * 64) * 64;
#pragma unroll
        for (int it = 0; it < 2; it++) {
            int idx = it * 256 + t;
            int r = idx >> 3, c = idx & 7;
            CPASYNC16(QS + r * 128 + ((c ^ (r & 7)) << 4), &g_qc[qoff + r * 64 + c * 8]);
        }
        int kb0 = kb_of(mid, qb, chunk, 0, rand_blocks);
        attn_prefetch_kv(bh, kb0, sb + OFF_KS, sb + OFF_VS, t);          // G0
        int kb1 = kb_of(mid, qb, chunk, 1, rand_blocks);
        attn_prefetch_kv(bh, kb1, sb + OFF_KS + 8192, sb + OFF_VS + 8192, t);  // G1
        if (t < 64) {
            km[t]      = mask[b * 4096 + kb0 * 64 + t];
            km[64 + t] = mask[b * 4096 + kb1 * 64 + t];
        }
    }

    int r1 = wm + (lane >> 2), r2 = r1 + 8;
    float mq1 = mask[b * 4096 + qb * 64 + r1];
    float mq2 = mask[b * 4096 + qb * 64 + r2];

    float acc[8][4];
#pragma unroll
    for (int nn = 0; nn < 8; nn++)
#pragma unroll
        for (int e = 0; e < 4; e++) acc[nn][e] = 0.f;
    float ls1 = 0.f, ls2 = 0.f;

    int laneA_row = (((lane >> 3) & 1) << 3) + (lane & 7);
    int laneA_ch  = lane >> 4;
    int laneB_row = ((lane >> 4) << 3) + (lane & 7);
    int laneB_ch  = (lane >> 3) & 1;
    int laneV_row = lane & 15;
    int laneV_g   = lane >> 4;

    uint32_t qh[4][4];

    for (int itk = 0; itk < 8; itk++) {
        int stg = itk & 3;

        // prefetch stage itk+2, then wait for stage itk, single barrier
        if (itk < 6) {
            int s2 = (itk + 2) & 3;
            int kbn = kb_of(mid, qb, chunk, itk + 2, rand_blocks);
            attn_prefetch_kv(bh, kbn, sb + OFF_KS + s2 * 8192,
                             sb + OFF_VS + s2 * 8192, t);
            if (t < 64) km[s2 * 64 + t] = mask[b * 4096 + kbn * 64 + t];
            CPWAIT(2);
        } else if (itk == 6) {
            CPWAIT(1);
        } else {
            CPWAIT(0);
        }
        __syncthreads();

        if (itk == 0) {
            int row = wm + laneA_row;
#pragma unroll
            for (int ks = 0; ks < 4; ks++) {
                int ch = ks * 2 + laneA_ch;
                LDSM_X4(qh[ks][0], qh[ks][1], qh[ks][2], qh[ks][3],
                        QS + row * 128 + ((ch ^ (row & 7)) << 4));
            }
        }

        bool band = mid && (itk < 3);
        uint32_t KSb = sb + OFF_KS + stg * 8192;
        uint32_t VSb = sb + OFF_VS + stg * 8192;
        const float* kmask_s = km + stg * 64;

        // ---- QK ----
        float sc[4][4];
#pragma unroll
        for (int nt = 0; nt < 4; nt++)
#pragma unroll
            for (int e = 0; e < 4; e++) sc[nt][e] = 0.f;

#pragma unroll
        for (int ks = 0; ks < 4; ks++) {
            int kc2 = ks * 2;
#pragma unroll
            for (int g = 0; g < 2; g++) {
                uint32_t kh[4];
                int row = wn + g * 16 + laneB_row;
                int ch = kc2 + laneB_ch;
                LDSM_X4(kh[0], kh[1], kh[2], kh[3],
                        KSb + row * 128 + ((ch ^ (row & 7)) << 4));
                MMA16816(sc[g*2],   qh[ks], kh[0], kh[1]);
                MMA16816(sc[g*2+1], qh[ks], kh[2], kh[3]);
            }
        }

        // ---- mask ----
#pragma unroll
        for (int nt = 0; nt < 4; nt++) {
            int col = wn + nt * 8 + (lane & 3) * 2;
            float mk0 = kmask_s[col], mk1 = kmask_s[col + 1];
            float m00 = band ? mk0 * mq1 : mk0;
            float m01 = band ? mk1 * mq1 : mk1;
            float m10 = band ? mk0 * mq2 : mk0;
            float m11 = band ? mk1 * mq2 : mk1;
            sc[nt][0] += (1.0f - m00) * NEGF;
            sc[nt][1] += (1.0f - m01) * NEGF;
            sc[nt][2] += (1.0f - m10) * NEGF;
            sc[nt][3] += (1.0f - m11) * NEGF;
        }

        // ---- exp + bf16 pack ----
        uint32_t aph[2][4];
#pragma unroll
        for (int nt = 0; nt < 4; nt++) {
            float p00 = __expf(sc[nt][0]), p01 = __expf(sc[nt][1]);
            float p10 = __expf(sc[nt][2]), p11 = __expf(sc[nt][3]);
            ls1 += p00 + p01; ls2 += p10 + p11;
            int j = nt >> 1, hf = (nt & 1) * 2;
            aph[j][hf]     = pack_hi(p00, p01);
            aph[j][hf + 1] = pack_hi(p10, p11);
        }

        // ---- PV ----
#pragma unroll
        for (int j = 0; j < 2; j++) {
            int vrow = wn + j * 16 + laneV_row;
            uint32_t vbase = VSb + vrow * 128;
            int sw = (vrow & 7) << 4;
#pragma unroll
            for (int np = 0; np < 4; np++) {
                uint32_t vh4[4];
                int ch = np * 2 + laneV_g;
                LDSM_X4T(vh4[0], vh4[1], vh4[2], vh4[3], vbase + ((ch << 4) ^ sw));
                MMA16816(acc[np*2],   aph[j], vh4[0], vh4[1]);
                MMA16816(acc[np*2+1], aph[j], vh4[2], vh4[3]);
            }
        }
    }

    // ---- final ls combine ----
    ls1 += __shfl_xor_sync(0xffffffffu, ls1, 1);
    ls1 += __shfl_xor_sync(0xffffffffu, ls1, 2);
    ls2 += __shfl_xor_sync(0xffffffffu, ls2, 1);
    ls2 += __shfl_xor_sync(0xffffffffu, ls2, 2);
    if ((lane & 3) == 0) {
        redL[wni * 64 + r1] = ls1;
        redL[wni * 64 + r2] = ls2;
    }
    __syncthreads();
    ls1 = redL[r1] + redL[64 + r1];
    ls2 = redL[r2] + redL[64 + r2];

    // ---- cross-half acc reduction ----
    if (wni == 1) {
#pragma unroll
        for (int nn = 0; nn < 8; nn++) {
            int col = nn * 8 + (lane & 3) * 2;
            *(float2*)&ex[r1 * EX_PITCH + col] = make_float2(acc[nn][0], acc[nn][1]);
            *(float2*)&ex[r2 * EX_PITCH + col] = make_float2(acc[nn][2], acc[nn][3]);
        }
    }
    __syncthreads();
    if (wni == 0) {
#pragma unroll
        for (int nn = 0; nn < 8; nn++) {
            int col = nn * 8 + (lane & 3) * 2;
            float2 v1 = *(float2*)&ex[r1 * EX_PITCH + col];
            float2 v2 = *(float2*)&ex[r2 * EX_PITCH + col];
            acc[nn][0] += v1.x; acc[nn][1] += v1.y;
            acc[nn][2] += v2.x; acc[nn][3] += v2.y;
        }

        if (mid) {
            float inv1 = 1.0f / ls1, inv2 = 1.0f / ls2;
#pragma unroll
            for (int nn = 0; nn < 8; nn++) {
                int col = nn * 8 + (lane & 3) * 2;
                size_t o1 = ((size_t)(b * 4096 + qb * 64 + r1)) * 512 + h * 64 + col;
                size_t o2 = ((size_t)(b * 4096 + qb * 64 + r2)) * 512 + h * 64 + col;
                *(uint32_t*)&g_xb[o1] = pack_hi(acc[nn][0] * inv1, acc[nn][1] * inv1);
                *(uint32_t*)&g_xb[o2] = pack_hi(acc[nn][2] * inv2, acc[nn][3] * inv2);
            }
        } else {
            int slot = (bh * 4 + di) * 8 + chunk;
            float* p = g_part + (size_t)slot * SLOT_F;
#pragma unroll
            for (int nn = 0; nn < 8; nn++) {
                int col = nn * 8 + (lane & 3) * 2;
                *(float2*)&p[r1 * 64 + col] = make_float2(acc[nn][0], acc[nn][1]);
                *(float2*)&p[r2 * 64 + col] = make_float2(acc[nn][2], acc[nn][3]);
            }
            if ((lane & 3) == 0) {
                p[4096 + r1] = ls1;
                p[4096 + r2] = ls2;
            }
        }
    }
}

// ---------------------------------------------------------------------------
// Combine 8 dense split-K partials -> bf16 ctx
// ---------------------------------------------------------------------------
__global__ __launch_bounds__(256) void combine_kernel()
{
    int g  = blockIdx.x;
    int bh = g >> 2, di = g & 3;
    int qb = (di < 2) ? di : (60 + di);
    int b  = bh >> 3, h = bh & 7;
    int t   = threadIdx.x;
    int row = t & 63;
    int c0  = (t >> 6) * 16;

    const float* base = g_part + (size_t)(g * 8) * SLOT_F;
    float L = 0.f;
#pragma unroll
    for (int s = 0; s < 8; s++) L += base[s*SLOT_F + 4096 + row];
    float inv = 1.0f / L;

    float o[16];
#pragma unroll
    for (int c = 0; c < 16; c++) o[c] = 0.f;
#pragma unroll
    for (int s = 0; s < 8; s++) {
        const float* pa = base + s*SLOT_F + row*64 + c0;
#pragma unroll
        for (int c4 = 0; c4 < 4; c4++) {
            float4 v4 = *(const float4*)&pa[c4*4];
            o[c4*4+0] += v4.x; o[c4*4+1] += v4.y;
            o[c4*4+2] += v4.z; o[c4*4+3] += v4.w;
        }
    }
    size_t dst = ((size_t)(b * 4096 + qb * 64 + row)) * 512 + h * 64 + c0;
#pragma unroll
    for (int cp = 0; cp < 8; cp++)
        *(uint32_t*)&g_xb[dst + cp*2] = pack_hi(o[cp*2] * inv, o[cp*2+1] * inv);
}

// ---------------------------------------------------------------------------
__global__ __launch_bounds__(256) void ln_kernel(const float* __restrict__ x,
                                                 const float* __restrict__ bo,
                                                 const float* __restrict__ gamma,
                                                 const float* __restrict__ beta,
                                                 float* __restrict__ out)
{
    int row = blockIdx.x;
    int t = threadIdx.x;
    size_t base = (size_t)row * 512;
    float h0 = g_h[base + t]       + bo[t]       + x[base + t];
    float h1 = g_h[base + t + 256] + bo[t + 256] + x[base + t + 256];
    float s = h0 + h1;
    float q = h0*h0 + h1*h1;
#pragma unroll
    for (int m = 16; m >= 1; m >>= 1) {
        s += __shfl_xor_sync(0xffffffffu, s, m);
        q += __shfl_xor_sync(0xffffffffu, q, m);
    }
    __shared__ float ss[8], qq[8];
    int w = t >> 5;
    if ((t & 31) == 0) { ss[w] = s; qq[w] = q; }
    __syncthreads();
    float S2 = 0.f, Q2 = 0.f;
#pragma unroll
    for (int i = 0; i < 8; i++) { S2 += ss[i]; Q2 += qq[i]; }
    float mu  = S2 * (1.0f / 512.0f);
    float var = Q2 * (1.0f / 512.0f) - mu * mu;
    float inv = rsqrtf(var + 1e-12f);
    out[base + t]       = (h0 - mu) * inv * gamma[t]       + beta[t];
    out[base + t + 256] = (h1 - mu) * inv * gamma[t + 256] + beta[t + 256];
}

// ---------------------------------------------------------------------------
extern "C" void kernel_launch(void* const* d_in, const int* in_sizes, int n_in,
                              void* d_out, int out_size)
{
    const float* x     = (const float*)d_in[0];
    const float* mask  = (const float*)d_in[1];
    const int*   rb    = (const int*)  d_in[2];
    const float* Wq    = (const float*)d_in[3];
    const float* Wk    = (const float*)d_in[4];
    const float* Wv    = (const float*)d_in[5];
    const float* Wo    = (const float*)d_in[6];
    const float* bo    = (const float*)d_in[7];
    const float* gamma = (const float*)d_in[8];
    const float* beta  = (const float*)d_in[9];
    float* out = (float*)d_out;

    float* hp;
    __nv_bfloat16 *xb, *wtb;
    cudaGetSymbolAddress((void**)&hp, g_h);
    cudaGetSymbolAddress((void**)&xb, g_xb);
    cudaGetSymbolAddress((void**)&wtb, g_wtb);

    cudaFuncSetAttribute(gemm_wo,  cudaFuncAttributeMaxDynamicSharedMemorySize, GEMM_SMEM);
    cudaFuncSetAttribute(gemm_qkv, cudaFuncAttributeMaxDynamicSharedMemorySize, GEMM_SMEM);
    cudaFuncSetAttribute(attn_hmma, cudaFuncAttributeMaxDynamicSharedMemorySize, ATT_SMEM);

    prep_kernel<<<4096 + 1024, 256>>>(x, xb, Wq, Wk, Wv, Wo, wtb);

    dim3 gq(12, 64);                         // 1536/128 x 8192/128
    gemm_qkv<<<gq, 256, GEMM_SMEM>>>(xb, wtb);

    attn_hmma<<<16 * 92, 256, ATT_SMEM>>>(mask, rb);
    combine_kernel<<<64, 256>>>();

    dim3 go(4, 64);
    gemm_wo<<<go, 256, GEMM_SMEM>>>(xb, wtb + 3*262144, hp);

    ln_kernel<<<Bb * Ss, 256>>>(x, bo, gamma, beta, out);
}